// round 1
// baseline (speedup 1.0000x reference)
#include <cuda_runtime.h>
#include <math.h>

#define HEADS   16
#define DHEAD   64
#define BATCH   4
#define SEQ     2048
#define DIM     1024
#define INNER   1024
#define TOKENS  (BATCH*SEQ)       /* 8192 */
#define KVLEN   (SEQ+1)           /* 2049 */
#define SCALE_F 8.0f
#define LN_EPS  1e-5f
#define L2_EPS  1e-12f

#define BQ 64
#define BK 32
#define NTILES ((KVLEN + BK - 1) / BK)   /* 65 */

// ---------------- scratch (global device arrays; no allocations) -------------
__device__ float g_xn   [TOKENS * DIM];          // layernorm output
__device__ float g_qlin [TOKENS * INNER];        // xn @ Wq
__device__ float g_kvlin[TOKENS * 2 * INNER];    // xn @ Wkv
__device__ float g_Q    [BATCH * HEADS * SEQ   * DHEAD];   // l2norm'd * q_scale * SCALE
__device__ float g_K    [BATCH * HEADS * KVLEN * DHEAD];   // null at j=0
__device__ float g_V    [BATCH * HEADS * KVLEN * DHEAD];
__device__ float g_aout [TOKENS * INNER];        // attention out, [token][h*64+d]

// ---------------- LayerNorm ---------------------------------------------------
__global__ void __launch_bounds__(256) ln_kernel(const float* __restrict__ x,
                                                 const float* __restrict__ gamma,
                                                 const float* __restrict__ beta) {
    __shared__ float red[8][2];
    const int t = blockIdx.x;
    const int i = threadIdx.x;
    const float4 v = ((const float4*)(x + (size_t)t * DIM))[i];
    float s  = v.x + v.y + v.z + v.w;
    float ss = v.x*v.x + v.y*v.y + v.z*v.z + v.w*v.w;
    #pragma unroll
    for (int o = 16; o > 0; o >>= 1) {
        s  += __shfl_xor_sync(0xFFFFFFFFu, s,  o);
        ss += __shfl_xor_sync(0xFFFFFFFFu, ss, o);
    }
    const int w = i >> 5, l = i & 31;
    if (l == 0) { red[w][0] = s; red[w][1] = ss; }
    __syncthreads();
    if (w == 0) {
        s  = (l < 8) ? red[l][0] : 0.f;
        ss = (l < 8) ? red[l][1] : 0.f;
        #pragma unroll
        for (int o = 4; o > 0; o >>= 1) {
            s  += __shfl_xor_sync(0xFFFFFFFFu, s,  o);
            ss += __shfl_xor_sync(0xFFFFFFFFu, ss, o);
        }
        if (l == 0) { red[0][0] = s; red[0][1] = ss; }
    }
    __syncthreads();
    const float mu   = red[0][0] * (1.f / DIM);
    const float var  = red[0][1] * (1.f / DIM) - mu * mu;
    const float rstd = rsqrtf(var + LN_EPS);
    const float4 g  = ((const float4*)gamma)[i];
    const float4 be = ((const float4*)beta)[i];
    float4 o4;
    o4.x = (v.x - mu) * rstd * g.x + be.x;
    o4.y = (v.y - mu) * rstd * g.y + be.y;
    o4.z = (v.z - mu) * rstd * g.z + be.z;
    o4.w = (v.w - mu) * rstd * g.w + be.w;
    ((float4*)(g_xn + (size_t)t * DIM))[i] = o4;
}

// ---------------- SGEMM 128x128x8, 8x8/thread, reg prefetch -------------------
template <int N, int K>
__device__ __forceinline__ void sgemm_body(const float* __restrict__ A,
                                           const float* __restrict__ B,
                                           float* __restrict__ C) {
    __shared__ float As[8][128];
    __shared__ float Bs[8][128];
    const int tid = threadIdx.x;
    const int tx = tid & 15;
    const int ty = tid >> 4;
    const int rowBase = blockIdx.y * 128;
    const int colBase = blockIdx.x * 128;
    const int arow = tid >> 1;
    const int acol = (tid & 1) << 2;
    const int brow = tid >> 5;
    const int bcol = (tid & 31) << 2;
    const float* Ap = A + (size_t)(rowBase + arow) * K + acol;
    const float* Bp = B + (size_t)brow * N + colBase + bcol;

    float acc[8][8];
    #pragma unroll
    for (int i = 0; i < 8; i++)
        #pragma unroll
        for (int j = 0; j < 8; j++) acc[i][j] = 0.f;

    float4 aReg = *(const float4*)Ap;
    float4 bReg = *(const float4*)Bp;

    for (int k0 = 0; k0 < K; k0 += 8) {
        As[acol + 0][arow] = aReg.x;
        As[acol + 1][arow] = aReg.y;
        As[acol + 2][arow] = aReg.z;
        As[acol + 3][arow] = aReg.w;
        *(float4*)&Bs[brow][bcol] = bReg;
        __syncthreads();
        if (k0 + 8 < K) {
            aReg = *(const float4*)(Ap + k0 + 8);
            bReg = *(const float4*)(Bp + (size_t)(k0 + 8) * N);
        }
        #pragma unroll
        for (int kk = 0; kk < 8; kk++) {
            float ar[8], br[8];
            *(float4*)&ar[0] = *(const float4*)&As[kk][ty * 8];
            *(float4*)&ar[4] = *(const float4*)&As[kk][ty * 8 + 4];
            *(float4*)&br[0] = *(const float4*)&Bs[kk][tx * 8];
            *(float4*)&br[4] = *(const float4*)&Bs[kk][tx * 8 + 4];
            #pragma unroll
            for (int i = 0; i < 8; i++)
                #pragma unroll
                for (int j = 0; j < 8; j++)
                    acc[i][j] = fmaf(ar[i], br[j], acc[i][j]);
        }
        __syncthreads();
    }
    #pragma unroll
    for (int i = 0; i < 8; i++) {
        float* Cp = C + (size_t)(rowBase + ty * 8 + i) * N + colBase + tx * 8;
        *(float4*)Cp       = make_float4(acc[i][0], acc[i][1], acc[i][2], acc[i][3]);
        *(float4*)(Cp + 4) = make_float4(acc[i][4], acc[i][5], acc[i][6], acc[i][7]);
    }
}

__global__ void __launch_bounds__(256) gemm_q_kernel(const float* __restrict__ Wq) {
    sgemm_body<INNER, DIM>(g_xn, Wq, g_qlin);
}
__global__ void __launch_bounds__(256) gemm_kv_kernel(const float* __restrict__ Wkv) {
    sgemm_body<2 * INNER, DIM>(g_xn, Wkv, g_kvlin);
}
__global__ void __launch_bounds__(256) gemm_o_kernel(const float* __restrict__ Wo,
                                                     float* __restrict__ out) {
    sgemm_body<DIM, INNER>(g_aout, Wo, out);
}

// ---------------- head split + l2norm + scales (SCALE folded into Q) ----------
__global__ void __launch_bounds__(256) qkv_prep(const float* __restrict__ q_scale,
                                                const float* __restrict__ k_scale) {
    const int gw   = (blockIdx.x * 256 + threadIdx.x) >> 5;
    const int lane = threadIdx.x & 31;
    if (gw >= TOKENS * HEADS) return;
    const int t = gw >> 4;         // token 0..8191
    const int h = gw & 15;
    const int b = t >> 11;         // /2048
    const int i = t & 2047;

    // ---- q ----
    const float* qr = g_qlin + (size_t)t * INNER + h * DHEAD;
    float q0 = qr[lane], q1 = qr[lane + 32];
    float ss = q0 * q0 + q1 * q1;
    #pragma unroll
    for (int o = 16; o > 0; o >>= 1) ss += __shfl_xor_sync(0xFFFFFFFFu, ss, o);
    float inv = 1.f / fmaxf(sqrtf(ss), L2_EPS);
    float* qo = g_Q + ((size_t)(b * HEADS + h) * SEQ + i) * DHEAD;
    qo[lane]      = q0 * inv * q_scale[lane]      * SCALE_F;
    qo[lane + 32] = q1 * inv * q_scale[lane + 32] * SCALE_F;

    // ---- k ----
    const float* kr = g_kvlin + (size_t)t * (2 * INNER) + h * DHEAD;
    float k0 = kr[lane], k1 = kr[lane + 32];
    ss = k0 * k0 + k1 * k1;
    #pragma unroll
    for (int o = 16; o > 0; o >>= 1) ss += __shfl_xor_sync(0xFFFFFFFFu, ss, o);
    inv = 1.f / fmaxf(sqrtf(ss), L2_EPS);
    float* ko = g_K + ((size_t)(b * HEADS + h) * KVLEN + i + 1) * DHEAD;
    ko[lane]      = k0 * inv * k_scale[lane];
    ko[lane + 32] = k1 * inv * k_scale[lane + 32];

    // ---- v (copy) ----
    const float* vr = g_kvlin + (size_t)t * (2 * INNER) + INNER + h * DHEAD;
    float* vo = g_V + ((size_t)(b * HEADS + h) * KVLEN + i + 1) * DHEAD;
    vo[lane]      = vr[lane];
    vo[lane + 32] = vr[lane + 32];
}

__global__ void null_prep(const float* __restrict__ null_kv,
                          const float* __restrict__ k_scale) {
    const int bh = blockIdx.x;       // b*16+h
    const int h = bh & 15;
    const int lane = threadIdx.x;    // 32 threads
    const float* nk = null_kv + h * DHEAD;
    const float* nv = null_kv + HEADS * DHEAD + h * DHEAD;
    float k0 = nk[lane], k1 = nk[lane + 32];
    float ss = k0 * k0 + k1 * k1;
    #pragma unroll
    for (int o = 16; o > 0; o >>= 1) ss += __shfl_xor_sync(0xFFFFFFFFu, ss, o);
    const float inv = 1.f / fmaxf(sqrtf(ss), L2_EPS);
    float* ko = g_K + (size_t)bh * KVLEN * DHEAD;
    ko[lane]      = k0 * inv * k_scale[lane];
    ko[lane + 32] = k1 * inv * k_scale[lane + 32];
    float* vo = g_V + (size_t)bh * KVLEN * DHEAD;
    vo[lane]      = nv[lane];
    vo[lane + 32] = nv[lane + 32];
}

// ---------------- flash attention (fp32, online softmax) ----------------------
__global__ void __launch_bounds__(256) attn_kernel() {
    __shared__ float Qs [BQ][65];
    __shared__ float Ks [BK][65];
    __shared__ float Vs [BK][DHEAD];
    __shared__ float Ssm[BQ][33];
    __shared__ float mrow[BQ], lrow[BQ], crow[BQ];

    const int tid = threadIdx.x;
    const int bh  = blockIdx.y;   // 0..63
    const int qt  = blockIdx.x;   // 0..31

    const float* Qg = g_Q + ((size_t)bh * SEQ + qt * BQ) * DHEAD;
    const float* Kg = g_K + (size_t)bh * KVLEN * DHEAD;
    const float* Vg = g_V + (size_t)bh * KVLEN * DHEAD;

    // load Q tile (SCALE already folded in)
    #pragma unroll
    for (int it = 0; it < 4; it++) {
        int e = tid + it * 256;
        int r = e >> 4;
        int c = (e & 15) << 2;
        float4 v = *(const float4*)(Qg + (size_t)r * DHEAD + c);
        Qs[r][c] = v.x; Qs[r][c + 1] = v.y; Qs[r][c + 2] = v.z; Qs[r][c + 3] = v.w;
    }
    if (tid < BQ) { mrow[tid] = -1e30f; lrow[tid] = 0.f; }

    float oacc[16];
    #pragma unroll
    for (int i = 0; i < 16; i++) oacc[i] = 0.f;

    const int trow = (tid >> 4) << 2;   // S-compute: 4 q-rows
    const int tcol = (tid & 15) << 1;   // S-compute: 2 k-cols
    const int orow = tid >> 2;          // O / softmax row
    const int ocol = (tid & 3) << 4;    // O: 16 d-cols
    const int scol = (tid & 3) << 3;    // softmax: 8 cols

    for (int kt = 0; kt < NTILES; kt++) {
        const int kvbase = kt * BK;
        __syncthreads();   // protect Ks/Vs/Ssm vs previous O-update readers
        // load K,V tile (zero / -inf fill past KVLEN)
        #pragma unroll
        for (int it = 0; it < 2; it++) {
            int e = tid + it * 256;
            int r = e >> 4;
            int c = (e & 15) << 2;
            int kv = kvbase + r;
            float4 kvec = make_float4(0.f, 0.f, 0.f, 0.f);
            float4 vvec = make_float4(0.f, 0.f, 0.f, 0.f);
            if (kv < KVLEN) {
                kvec = *(const float4*)(Kg + (size_t)kv * DHEAD + c);
                vvec = *(const float4*)(Vg + (size_t)kv * DHEAD + c);
            }
            Ks[r][c] = kvec.x; Ks[r][c + 1] = kvec.y; Ks[r][c + 2] = kvec.z; Ks[r][c + 3] = kvec.w;
            *(float4*)&Vs[r][c] = vvec;
        }
        __syncthreads();

        // S = Q K^T  (4x2 per thread)
        float s[4][2];
        #pragma unroll
        for (int i = 0; i < 4; i++) { s[i][0] = 0.f; s[i][1] = 0.f; }
        #pragma unroll 8
        for (int d = 0; d < DHEAD; d++) {
            const float k0v = Ks[tcol][d];
            const float k1v = Ks[tcol + 1][d];
            #pragma unroll
            for (int i = 0; i < 4; i++) {
                const float qv = Qs[trow + i][d];
                s[i][0] = fmaf(qv, k0v, s[i][0]);
                s[i][1] = fmaf(qv, k1v, s[i][1]);
            }
        }
        #pragma unroll
        for (int i = 0; i < 4; i++) {
            #pragma unroll
            for (int j = 0; j < 2; j++) {
                const int kv = kvbase + tcol + j;
                Ssm[trow + i][tcol + j] = (kv < KVLEN) ? s[i][j] : -1e30f;
            }
        }
        __syncthreads();

        // online softmax (4 threads per row, 8 cols each)
        {
            float pv[8];
            float tmax = -1e30f;
            #pragma unroll
            for (int i = 0; i < 8; i++) {
                pv[i] = Ssm[orow][scol + i];
                tmax = fmaxf(tmax, pv[i]);
            }
            tmax = fmaxf(tmax, __shfl_xor_sync(0xFFFFFFFFu, tmax, 1));
            tmax = fmaxf(tmax, __shfl_xor_sync(0xFFFFFFFFu, tmax, 2));
            const float mold = mrow[orow];
            const float mnew = fmaxf(mold, tmax);
            float psum = 0.f;
            #pragma unroll
            for (int i = 0; i < 8; i++) {
                const float p = __expf(pv[i] - mnew);
                Ssm[orow][scol + i] = p;
                psum += p;
            }
            psum += __shfl_xor_sync(0xFFFFFFFFu, psum, 1);
            psum += __shfl_xor_sync(0xFFFFFFFFu, psum, 2);
            if ((tid & 3) == 0) {
                const float cf = __expf(mold - mnew);
                crow[orow] = cf;
                mrow[orow] = mnew;
                lrow[orow] = lrow[orow] * cf + psum;
            }
        }
        __syncthreads();

        // O update
        {
            const float cf = crow[orow];
            #pragma unroll
            for (int i = 0; i < 16; i++) oacc[i] *= cf;
            #pragma unroll 4
            for (int k2 = 0; k2 < BK; k2++) {
                const float p = Ssm[orow][k2];
                const float4 v0 = *(const float4*)&Vs[k2][ocol];
                const float4 v1 = *(const float4*)&Vs[k2][ocol + 4];
                const float4 v2 = *(const float4*)&Vs[k2][ocol + 8];
                const float4 v3 = *(const float4*)&Vs[k2][ocol + 12];
                oacc[0]  = fmaf(p, v0.x, oacc[0]);
                oacc[1]  = fmaf(p, v0.y, oacc[1]);
                oacc[2]  = fmaf(p, v0.z, oacc[2]);
                oacc[3]  = fmaf(p, v0.w, oacc[3]);
                oacc[4]  = fmaf(p, v1.x, oacc[4]);
                oacc[5]  = fmaf(p, v1.y, oacc[5]);
                oacc[6]  = fmaf(p, v1.z, oacc[6]);
                oacc[7]  = fmaf(p, v1.w, oacc[7]);
                oacc[8]  = fmaf(p, v2.x, oacc[8]);
                oacc[9]  = fmaf(p, v2.y, oacc[9]);
                oacc[10] = fmaf(p, v2.z, oacc[10]);
                oacc[11] = fmaf(p, v2.w, oacc[11]);
                oacc[12] = fmaf(p, v3.x, oacc[12]);
                oacc[13] = fmaf(p, v3.y, oacc[13]);
                oacc[14] = fmaf(p, v3.z, oacc[14]);
                oacc[15] = fmaf(p, v3.w, oacc[15]);
            }
        }
    }

    // epilogue: divide by l, write to [token][h*64+d] layout
    const float linv = 1.f / lrow[orow];
    const int b = bh >> 4, h = bh & 15;
    float* op = g_aout + ((size_t)(b * SEQ + qt * BQ + orow)) * INNER + h * DHEAD + ocol;
    float4 r0 = make_float4(oacc[0] * linv,  oacc[1] * linv,  oacc[2] * linv,  oacc[3] * linv);
    float4 r1 = make_float4(oacc[4] * linv,  oacc[5] * linv,  oacc[6] * linv,  oacc[7] * linv);
    float4 r2 = make_float4(oacc[8] * linv,  oacc[9] * linv,  oacc[10] * linv, oacc[11] * linv);
    float4 r3 = make_float4(oacc[12] * linv, oacc[13] * linv, oacc[14] * linv, oacc[15] * linv);
    *(float4*)(op)      = r0;
    *(float4*)(op + 4)  = r1;
    *(float4*)(op + 8)  = r2;
    *(float4*)(op + 12) = r3;
}

// ---------------- launch ------------------------------------------------------
extern "C" void kernel_launch(void* const* d_in, const int* in_sizes, int n_in,
                              void* d_out, int out_size) {
    const float* x       = (const float*)d_in[0];
    const float* gamma   = (const float*)d_in[1];
    const float* beta    = (const float*)d_in[2];
    const float* null_kv = (const float*)d_in[3];
    const float* Wq      = (const float*)d_in[4];
    const float* Wkv     = (const float*)d_in[5];
    const float* q_scale = (const float*)d_in[6];
    const float* k_scale = (const float*)d_in[7];
    const float* Wo      = (const float*)d_in[8];
    float* out = (float*)d_out;

    ln_kernel<<<TOKENS, 256>>>(x, gamma, beta);
    gemm_q_kernel <<<dim3(INNER / 128,     TOKENS / 128), 256>>>(Wq);
    gemm_kv_kernel<<<dim3(2 * INNER / 128, TOKENS / 128), 256>>>(Wkv);
    qkv_prep<<<(TOKENS * HEADS) / 8, 256>>>(q_scale, k_scale);
    null_prep<<<BATCH * HEADS, 32>>>(null_kv, k_scale);
    attn_kernel<<<dim3(SEQ / BQ, BATCH * HEADS), 256>>>();
    gemm_o_kernel<<<dim3(DIM / 128, TOKENS / 128), 256>>>(Wo, out);
}

// round 2
// speedup vs baseline: 1.1583x; 1.1583x over previous
#include <cuda_runtime.h>
#include <math.h>

#define HEADS   16
#define DHEAD   64
#define BATCH   4
#define SEQ     2048
#define DIM     1024
#define INNER   1024
#define TOKENS  (BATCH*SEQ)       /* 8192 */
#define KVLEN   (SEQ+1)           /* 2049 */
#define SCALE_F 8.0f
#define LN_EPS  1e-5f
#define L2_EPS  1e-12f

#define BQ 64
#define BK 32
#define NTILES ((KVLEN + BK - 1) / BK)   /* 65 */

// ---------------- scratch (global device arrays; no allocations) -------------
__device__ float g_xn   [TOKENS * DIM];          // layernorm output
__device__ float g_qlin [TOKENS * INNER];        // xn @ Wq
__device__ float g_kvlin[TOKENS * 2 * INNER];    // xn @ Wkv
__device__ float g_Q    [BATCH * HEADS * SEQ   * DHEAD];   // l2norm'd * q_scale * SCALE
__device__ float g_K    [BATCH * HEADS * KVLEN * DHEAD];   // null at j=0
__device__ float g_V    [BATCH * HEADS * KVLEN * DHEAD];
__device__ float g_aout [TOKENS * INNER];        // attention out, [token][h*64+d]

// ---------------- LayerNorm ---------------------------------------------------
__global__ void __launch_bounds__(256) ln_kernel(const float* __restrict__ x,
                                                 const float* __restrict__ gamma,
                                                 const float* __restrict__ beta) {
    __shared__ float red[8][2];
    const int t = blockIdx.x;
    const int i = threadIdx.x;
    const float4 v = ((const float4*)(x + (size_t)t * DIM))[i];
    float s  = v.x + v.y + v.z + v.w;
    float ss = v.x*v.x + v.y*v.y + v.z*v.z + v.w*v.w;
    #pragma unroll
    for (int o = 16; o > 0; o >>= 1) {
        s  += __shfl_xor_sync(0xFFFFFFFFu, s,  o);
        ss += __shfl_xor_sync(0xFFFFFFFFu, ss, o);
    }
    const int w = i >> 5, l = i & 31;
    if (l == 0) { red[w][0] = s; red[w][1] = ss; }
    __syncthreads();
    if (w == 0) {
        s  = (l < 8) ? red[l][0] : 0.f;
        ss = (l < 8) ? red[l][1] : 0.f;
        #pragma unroll
        for (int o = 4; o > 0; o >>= 1) {
            s  += __shfl_xor_sync(0xFFFFFFFFu, s,  o);
            ss += __shfl_xor_sync(0xFFFFFFFFu, ss, o);
        }
        if (l == 0) { red[0][0] = s; red[0][1] = ss; }
    }
    __syncthreads();
    const float mu   = red[0][0] * (1.f / DIM);
    const float var  = red[0][1] * (1.f / DIM) - mu * mu;
    const float rstd = rsqrtf(var + LN_EPS);
    const float4 g  = ((const float4*)gamma)[i];
    const float4 be = ((const float4*)beta)[i];
    float4 o4;
    o4.x = (v.x - mu) * rstd * g.x + be.x;
    o4.y = (v.y - mu) * rstd * g.y + be.y;
    o4.z = (v.z - mu) * rstd * g.z + be.z;
    o4.w = (v.w - mu) * rstd * g.w + be.w;
    ((float4*)(g_xn + (size_t)t * DIM))[i] = o4;
}

// ---------------- TF32 tensor-core GEMM ---------------------------------------
// C[M,N] = A[M,K] @ B[K,N], fp32 in/out, tf32 mma with fp32 accumulate.
// Block tile 256x128 (256 threads, 8 warps of 64x64), K-step 16, double buffer.

__device__ __forceinline__ unsigned f2tf(float f) {
    unsigned u;
    asm("cvt.rna.tf32.f32 %0, %1;" : "=r"(u) : "f"(f));
    return u;
}

__device__ __forceinline__ void mma_tf32(float* c, const unsigned* a, const unsigned* b) {
    asm volatile(
        "mma.sync.aligned.m16n8k8.row.col.f32.tf32.tf32.f32 "
        "{%0,%1,%2,%3}, {%4,%5,%6,%7}, {%8,%9}, {%0,%1,%2,%3};"
        : "+f"(c[0]), "+f"(c[1]), "+f"(c[2]), "+f"(c[3])
        : "r"(a[0]), "r"(a[1]), "r"(a[2]), "r"(a[3]), "r"(b[0]), "r"(b[1]));
}

#define GBM 256
#define GBN 128
#define GBK 16
#define ASTR 20      /* As row stride (floats): conflict-free frag loads */
#define BSTR 132     /* Bs row stride */
#define ASTAGE (GBM * ASTR)          /* 5120 words */
#define BSTAGE (GBK * BSTR)          /* 2112 words */
#define GEMM_SMEM ((2 * ASTAGE + 2 * BSTAGE) * 4)   /* 57856 bytes */

template <int N, int K>
__device__ __forceinline__ void gemm_tf32_body(const float* __restrict__ A,
                                               const float* __restrict__ B,
                                               float* __restrict__ C) {
    extern __shared__ unsigned smem[];
    unsigned* As = smem;                 // [2][GBM][ASTR]
    unsigned* Bs = smem + 2 * ASTAGE;    // [2][GBK][BSTR]

    const int tid  = threadIdx.x;
    const int warp = tid >> 5;
    const int lane = tid & 31;
    const int r = lane >> 2;       // 0..7
    const int c = lane & 3;        // 0..3
    const int wm = (warp & 3) * 64;
    const int wn = (warp >> 2) * 64;
    const int rowBase = blockIdx.y * GBM;
    const int colBase = blockIdx.x * GBN;

    // A staging: rows am+64p (p=0..3), cols ak..ak+3
    const int am = tid >> 2;           // 0..63
    const int ak = (tid & 3) << 2;     // 0,4,8,12
    // B staging: rows bk+8p (p=0..1), cols bn..bn+3
    const int bk = tid >> 5;           // 0..7
    const int bn = lane << 2;          // 0..124

    const float* Ap = A + (size_t)(rowBase + am) * K + ak;
    const float* Bp = B + colBase + bn;

    float acc[4][8][4];
    #pragma unroll
    for (int mi = 0; mi < 4; mi++)
        #pragma unroll
        for (int ni = 0; ni < 8; ni++)
            #pragma unroll
            for (int j = 0; j < 4; j++) acc[mi][ni][j] = 0.f;

    float4 aR[4], bR[2];
    #pragma unroll
    for (int p = 0; p < 4; p++) aR[p] = *(const float4*)(Ap + (size_t)(p * 64) * K);
    #pragma unroll
    for (int p = 0; p < 2; p++) bR[p] = *(const float4*)(Bp + (size_t)(bk + 8 * p) * N);

    const int NIT = K / GBK;
    #pragma unroll 1
    for (int kt = 0; kt < NIT; kt++) {
        const int cur = kt & 1;
        // store staged regs -> smem (cvt to tf32, round-to-nearest)
        {
            unsigned* as = As + cur * ASTAGE;
            unsigned* bs = Bs + cur * BSTAGE;
            #pragma unroll
            for (int p = 0; p < 4; p++) {
                uint4 u;
                u.x = f2tf(aR[p].x); u.y = f2tf(aR[p].y);
                u.z = f2tf(aR[p].z); u.w = f2tf(aR[p].w);
                *(uint4*)&as[(am + 64 * p) * ASTR + ak] = u;
            }
            #pragma unroll
            for (int p = 0; p < 2; p++) {
                uint4 u;
                u.x = f2tf(bR[p].x); u.y = f2tf(bR[p].y);
                u.z = f2tf(bR[p].z); u.w = f2tf(bR[p].w);
                *(uint4*)&bs[(bk + 8 * p) * BSTR + bn] = u;
            }
        }
        __syncthreads();

        // prefetch next K16 tile
        if (kt + 1 < NIT) {
            const int k0 = (kt + 1) * GBK;
            #pragma unroll
            for (int p = 0; p < 4; p++) aR[p] = *(const float4*)(Ap + (size_t)(p * 64) * K + k0);
            #pragma unroll
            for (int p = 0; p < 2; p++) bR[p] = *(const float4*)(Bp + (size_t)(k0 + bk + 8 * p) * N);
        }

        // compute 2 x k8 from current buffer
        {
            const unsigned* as = As + cur * ASTAGE;
            const unsigned* bs = Bs + cur * BSTAGE;
            #pragma unroll
            for (int kk = 0; kk < 2; kk++) {
                const int k8 = kk * 8;
                unsigned af[4][4];
                #pragma unroll
                for (int mi = 0; mi < 4; mi++) {
                    const int m0 = wm + mi * 16 + r;
                    af[mi][0] = as[m0 * ASTR + k8 + c];
                    af[mi][1] = as[(m0 + 8) * ASTR + k8 + c];
                    af[mi][2] = as[m0 * ASTR + k8 + c + 4];
                    af[mi][3] = as[(m0 + 8) * ASTR + k8 + c + 4];
                }
                unsigned bf[8][2];
                #pragma unroll
                for (int ni = 0; ni < 8; ni++) {
                    const int n0 = wn + ni * 8 + r;
                    bf[ni][0] = bs[(k8 + c) * BSTR + n0];
                    bf[ni][1] = bs[(k8 + c + 4) * BSTR + n0];
                }
                #pragma unroll
                for (int mi = 0; mi < 4; mi++)
                    #pragma unroll
                    for (int ni = 0; ni < 8; ni++)
                        mma_tf32(acc[mi][ni], af[mi], bf[ni]);
            }
        }
        __syncthreads();
    }

    // epilogue
    #pragma unroll
    for (int mi = 0; mi < 4; mi++) {
        const int row = rowBase + wm + mi * 16 + r;
        #pragma unroll
        for (int ni = 0; ni < 8; ni++) {
            const int col = colBase + wn + ni * 8 + 2 * c;
            *(float2*)&C[(size_t)row * N + col]       = make_float2(acc[mi][ni][0], acc[mi][ni][1]);
            *(float2*)&C[(size_t)(row + 8) * N + col] = make_float2(acc[mi][ni][2], acc[mi][ni][3]);
        }
    }
}

__global__ void __launch_bounds__(256, 1) gemm_q_kernel(const float* __restrict__ Wq) {
    gemm_tf32_body<INNER, DIM>(g_xn, Wq, g_qlin);
}
__global__ void __launch_bounds__(256, 1) gemm_kv_kernel(const float* __restrict__ Wkv) {
    gemm_tf32_body<2 * INNER, DIM>(g_xn, Wkv, g_kvlin);
}
__global__ void __launch_bounds__(256, 1) gemm_o_kernel(const float* __restrict__ Wo,
                                                        float* __restrict__ out) {
    gemm_tf32_body<DIM, INNER>(g_aout, Wo, out);
}

// ---------------- head split + l2norm + scales (SCALE folded into Q) ----------
__global__ void __launch_bounds__(256) qkv_prep(const float* __restrict__ q_scale,
                                                const float* __restrict__ k_scale) {
    const int gw   = (blockIdx.x * 256 + threadIdx.x) >> 5;
    const int lane = threadIdx.x & 31;
    if (gw >= TOKENS * HEADS) return;
    const int t = gw >> 4;         // token 0..8191
    const int h = gw & 15;
    const int b = t >> 11;         // /2048
    const int i = t & 2047;

    // ---- q ----
    const float* qr = g_qlin + (size_t)t * INNER + h * DHEAD;
    float q0 = qr[lane], q1 = qr[lane + 32];
    float ss = q0 * q0 + q1 * q1;
    #pragma unroll
    for (int o = 16; o > 0; o >>= 1) ss += __shfl_xor_sync(0xFFFFFFFFu, ss, o);
    float inv = 1.f / fmaxf(sqrtf(ss), L2_EPS);
    float* qo = g_Q + ((size_t)(b * HEADS + h) * SEQ + i) * DHEAD;
    qo[lane]      = q0 * inv * q_scale[lane]      * SCALE_F;
    qo[lane + 32] = q1 * inv * q_scale[lane + 32] * SCALE_F;

    // ---- k ----
    const float* kr = g_kvlin + (size_t)t * (2 * INNER) + h * DHEAD;
    float k0 = kr[lane], k1 = kr[lane + 32];
    ss = k0 * k0 + k1 * k1;
    #pragma unroll
    for (int o = 16; o > 0; o >>= 1) ss += __shfl_xor_sync(0xFFFFFFFFu, ss, o);
    inv = 1.f / fmaxf(sqrtf(ss), L2_EPS);
    float* ko = g_K + ((size_t)(b * HEADS + h) * KVLEN + i + 1) * DHEAD;
    ko[lane]      = k0 * inv * k_scale[lane];
    ko[lane + 32] = k1 * inv * k_scale[lane + 32];

    // ---- v (copy) ----
    const float* vr = g_kvlin + (size_t)t * (2 * INNER) + INNER + h * DHEAD;
    float* vo = g_V + ((size_t)(b * HEADS + h) * KVLEN + i + 1) * DHEAD;
    vo[lane]      = vr[lane];
    vo[lane + 32] = vr[lane + 32];
}

__global__ void null_prep(const float* __restrict__ null_kv,
                          const float* __restrict__ k_scale) {
    const int bh = blockIdx.x;       // b*16+h
    const int h = bh & 15;
    const int lane = threadIdx.x;    // 32 threads
    const float* nk = null_kv + h * DHEAD;
    const float* nv = null_kv + HEADS * DHEAD + h * DHEAD;
    float k0 = nk[lane], k1 = nk[lane + 32];
    float ss = k0 * k0 + k1 * k1;
    #pragma unroll
    for (int o = 16; o > 0; o >>= 1) ss += __shfl_xor_sync(0xFFFFFFFFu, ss, o);
    const float inv = 1.f / fmaxf(sqrtf(ss), L2_EPS);
    float* ko = g_K + (size_t)bh * KVLEN * DHEAD;
    ko[lane]      = k0 * inv * k_scale[lane];
    ko[lane + 32] = k1 * inv * k_scale[lane + 32];
    float* vo = g_V + (size_t)bh * KVLEN * DHEAD;
    vo[lane]      = nv[lane];
    vo[lane + 32] = nv[lane + 32];
}

// ---------------- flash attention (fp32, online softmax) ----------------------
__global__ void __launch_bounds__(256) attn_kernel() {
    __shared__ float Qs [BQ][65];
    __shared__ float Ks [BK][65];
    __shared__ float Vs [BK][DHEAD];
    __shared__ float Ssm[BQ][33];
    __shared__ float mrow[BQ], lrow[BQ], crow[BQ];

    const int tid = threadIdx.x;
    const int bh  = blockIdx.y;   // 0..63
    const int qt  = blockIdx.x;   // 0..31

    const float* Qg = g_Q + ((size_t)bh * SEQ + qt * BQ) * DHEAD;
    const float* Kg = g_K + (size_t)bh * KVLEN * DHEAD;
    const float* Vg = g_V + (size_t)bh * KVLEN * DHEAD;

    // load Q tile (SCALE already folded in)
    #pragma unroll
    for (int it = 0; it < 4; it++) {
        int e = tid + it * 256;
        int r = e >> 4;
        int c = (e & 15) << 2;
        float4 v = *(const float4*)(Qg + (size_t)r * DHEAD + c);
        Qs[r][c] = v.x; Qs[r][c + 1] = v.y; Qs[r][c + 2] = v.z; Qs[r][c + 3] = v.w;
    }
    if (tid < BQ) { mrow[tid] = -1e30f; lrow[tid] = 0.f; }

    float oacc[16];
    #pragma unroll
    for (int i = 0; i < 16; i++) oacc[i] = 0.f;

    const int trow = (tid >> 4) << 2;   // S-compute: 4 q-rows
    const int tcol = (tid & 15) << 1;   // S-compute: 2 k-cols
    const int orow = tid >> 2;          // O / softmax row
    const int ocol = (tid & 3) << 4;    // O: 16 d-cols
    const int scol = (tid & 3) << 3;    // softmax: 8 cols

    for (int kt = 0; kt < NTILES; kt++) {
        const int kvbase = kt * BK;
        __syncthreads();   // protect Ks/Vs/Ssm vs previous O-update readers
        // load K,V tile (zero / -inf fill past KVLEN)
        #pragma unroll
        for (int it = 0; it < 2; it++) {
            int e = tid + it * 256;
            int r = e >> 4;
            int c = (e & 15) << 2;
            int kv = kvbase + r;
            float4 kvec = make_float4(0.f, 0.f, 0.f, 0.f);
            float4 vvec = make_float4(0.f, 0.f, 0.f, 0.f);
            if (kv < KVLEN) {
                kvec = *(const float4*)(Kg + (size_t)kv * DHEAD + c);
                vvec = *(const float4*)(Vg + (size_t)kv * DHEAD + c);
            }
            Ks[r][c] = kvec.x; Ks[r][c + 1] = kvec.y; Ks[r][c + 2] = kvec.z; Ks[r][c + 3] = kvec.w;
            *(float4*)&Vs[r][c] = vvec;
        }
        __syncthreads();

        // S = Q K^T  (4x2 per thread)
        float s[4][2];
        #pragma unroll
        for (int i = 0; i < 4; i++) { s[i][0] = 0.f; s[i][1] = 0.f; }
        #pragma unroll 8
        for (int d = 0; d < DHEAD; d++) {
            const float k0v = Ks[tcol][d];
            const float k1v = Ks[tcol + 1][d];
            #pragma unroll
            for (int i = 0; i < 4; i++) {
                const float qv = Qs[trow + i][d];
                s[i][0] = fmaf(qv, k0v, s[i][0]);
                s[i][1] = fmaf(qv, k1v, s[i][1]);
            }
        }
        #pragma unroll
        for (int i = 0; i < 4; i++) {
            #pragma unroll
            for (int j = 0; j < 2; j++) {
                const int kv = kvbase + tcol + j;
                Ssm[trow + i][tcol + j] = (kv < KVLEN) ? s[i][j] : -1e30f;
            }
        }
        __syncthreads();

        // online softmax (4 threads per row, 8 cols each)
        {
            float pv[8];
            float tmax = -1e30f;
            #pragma unroll
            for (int i = 0; i < 8; i++) {
                pv[i] = Ssm[orow][scol + i];
                tmax = fmaxf(tmax, pv[i]);
            }
            tmax = fmaxf(tmax, __shfl_xor_sync(0xFFFFFFFFu, tmax, 1));
            tmax = fmaxf(tmax, __shfl_xor_sync(0xFFFFFFFFu, tmax, 2));
            const float mold = mrow[orow];
            const float mnew = fmaxf(mold, tmax);
            float psum = 0.f;
            #pragma unroll
            for (int i = 0; i < 8; i++) {
                const float p = __expf(pv[i] - mnew);
                Ssm[orow][scol + i] = p;
                psum += p;
            }
            psum += __shfl_xor_sync(0xFFFFFFFFu, psum, 1);
            psum += __shfl_xor_sync(0xFFFFFFFFu, psum, 2);
            if ((tid & 3) == 0) {
                const float cf = __expf(mold - mnew);
                crow[orow] = cf;
                mrow[orow] = mnew;
                lrow[orow] = lrow[orow] * cf + psum;
            }
        }
        __syncthreads();

        // O update
        {
            const float cf = crow[orow];
            #pragma unroll
            for (int i = 0; i < 16; i++) oacc[i] *= cf;
            #pragma unroll 4
            for (int k2 = 0; k2 < BK; k2++) {
                const float p = Ssm[orow][k2];
                const float4 v0 = *(const float4*)&Vs[k2][ocol];
                const float4 v1 = *(const float4*)&Vs[k2][ocol + 4];
                const float4 v2 = *(const float4*)&Vs[k2][ocol + 8];
                const float4 v3 = *(const float4*)&Vs[k2][ocol + 12];
                oacc[0]  = fmaf(p, v0.x, oacc[0]);
                oacc[1]  = fmaf(p, v0.y, oacc[1]);
                oacc[2]  = fmaf(p, v0.z, oacc[2]);
                oacc[3]  = fmaf(p, v0.w, oacc[3]);
                oacc[4]  = fmaf(p, v1.x, oacc[4]);
                oacc[5]  = fmaf(p, v1.y, oacc[5]);
                oacc[6]  = fmaf(p, v1.z, oacc[6]);
                oacc[7]  = fmaf(p, v1.w, oacc[7]);
                oacc[8]  = fmaf(p, v2.x, oacc[8]);
                oacc[9]  = fmaf(p, v2.y, oacc[9]);
                oacc[10] = fmaf(p, v2.z, oacc[10]);
                oacc[11] = fmaf(p, v2.w, oacc[11]);
                oacc[12] = fmaf(p, v3.x, oacc[12]);
                oacc[13] = fmaf(p, v3.y, oacc[13]);
                oacc[14] = fmaf(p, v3.z, oacc[14]);
                oacc[15] = fmaf(p, v3.w, oacc[15]);
            }
        }
    }

    // epilogue: divide by l, write to [token][h*64+d] layout
    const float linv = 1.f / lrow[orow];
    const int b = bh >> 4, h = bh & 15;
    float* op = g_aout + ((size_t)(b * SEQ + qt * BQ + orow)) * INNER + h * DHEAD + ocol;
    float4 r0 = make_float4(oacc[0] * linv,  oacc[1] * linv,  oacc[2] * linv,  oacc[3] * linv);
    float4 r1 = make_float4(oacc[4] * linv,  oacc[5] * linv,  oacc[6] * linv,  oacc[7] * linv);
    float4 r2 = make_float4(oacc[8] * linv,  oacc[9] * linv,  oacc[10] * linv, oacc[11] * linv);
    float4 r3 = make_float4(oacc[12] * linv, oacc[13] * linv, oacc[14] * linv, oacc[15] * linv);
    *(float4*)(op)      = r0;
    *(float4*)(op + 4)  = r1;
    *(float4*)(op + 8)  = r2;
    *(float4*)(op + 12) = r3;
}

// ---------------- launch ------------------------------------------------------
extern "C" void kernel_launch(void* const* d_in, const int* in_sizes, int n_in,
                              void* d_out, int out_size) {
    const float* x       = (const float*)d_in[0];
    const float* gamma   = (const float*)d_in[1];
    const float* beta    = (const float*)d_in[2];
    const float* null_kv = (const float*)d_in[3];
    const float* Wq      = (const float*)d_in[4];
    const float* Wkv     = (const float*)d_in[5];
    const float* q_scale = (const float*)d_in[6];
    const float* k_scale = (const float*)d_in[7];
    const float* Wo      = (const float*)d_in[8];
    float* out = (float*)d_out;

    cudaFuncSetAttribute(gemm_q_kernel,  cudaFuncAttributeMaxDynamicSharedMemorySize, GEMM_SMEM);
    cudaFuncSetAttribute(gemm_kv_kernel, cudaFuncAttributeMaxDynamicSharedMemorySize, GEMM_SMEM);
    cudaFuncSetAttribute(gemm_o_kernel,  cudaFuncAttributeMaxDynamicSharedMemorySize, GEMM_SMEM);

    ln_kernel<<<TOKENS, 256>>>(x, gamma, beta);
    gemm_q_kernel <<<dim3(INNER / GBN,     TOKENS / GBM), 256, GEMM_SMEM>>>(Wq);
    gemm_kv_kernel<<<dim3(2 * INNER / GBN, TOKENS / GBM), 256, GEMM_SMEM>>>(Wkv);
    qkv_prep<<<(TOKENS * HEADS) / 8, 256>>>(q_scale, k_scale);
    null_prep<<<BATCH * HEADS, 32>>>(null_kv, k_scale);
    attn_kernel<<<dim3(SEQ / BQ, BATCH * HEADS), 256>>>();
    gemm_o_kernel<<<dim3(DIM / GBN, TOKENS / GBM), 256, GEMM_SMEM>>>(Wo, out);
}

// round 3
// speedup vs baseline: 3.1352x; 2.7068x over previous
#include <cuda_runtime.h>
#include <math.h>

#define HEADS   16
#define DHEAD   64
#define BATCH   4
#define SEQ     2048
#define DIM     1024
#define INNER   1024
#define TOKENS  (BATCH*SEQ)       /* 8192 */
#define KVLEN   (SEQ+1)           /* 2049 */
#define SCALE_F 8.0f
#define LN_EPS  1e-5f
#define L2_EPS  1e-12f

// ---------------- scratch (global device arrays; no allocations) -------------
__device__ float g_xn   [TOKENS * DIM];          // layernorm output
__device__ float g_qlin [TOKENS * INNER];        // xn @ Wq
__device__ float g_kvlin[TOKENS * 2 * INNER];    // xn @ Wkv
__device__ float g_Q    [BATCH * HEADS * SEQ   * DHEAD];   // l2norm'd * q_scale * SCALE
__device__ float g_K    [BATCH * HEADS * KVLEN * DHEAD];   // null at j=0
__device__ float g_V    [BATCH * HEADS * KVLEN * DHEAD];
__device__ float g_aout [TOKENS * INNER];        // attention out, [token][h*64+d]

// ---------------- LayerNorm ---------------------------------------------------
__global__ void __launch_bounds__(256) ln_kernel(const float* __restrict__ x,
                                                 const float* __restrict__ gamma,
                                                 const float* __restrict__ beta) {
    __shared__ float red[8][2];
    const int t = blockIdx.x;
    const int i = threadIdx.x;
    const float4 v = ((const float4*)(x + (size_t)t * DIM))[i];
    float s  = v.x + v.y + v.z + v.w;
    float ss = v.x*v.x + v.y*v.y + v.z*v.z + v.w*v.w;
    #pragma unroll
    for (int o = 16; o > 0; o >>= 1) {
        s  += __shfl_xor_sync(0xFFFFFFFFu, s,  o);
        ss += __shfl_xor_sync(0xFFFFFFFFu, ss, o);
    }
    const int w = i >> 5, l = i & 31;
    if (l == 0) { red[w][0] = s; red[w][1] = ss; }
    __syncthreads();
    if (w == 0) {
        s  = (l < 8) ? red[l][0] : 0.f;
        ss = (l < 8) ? red[l][1] : 0.f;
        #pragma unroll
        for (int o = 4; o > 0; o >>= 1) {
            s  += __shfl_xor_sync(0xFFFFFFFFu, s,  o);
            ss += __shfl_xor_sync(0xFFFFFFFFu, ss, o);
        }
        if (l == 0) { red[0][0] = s; red[0][1] = ss; }
    }
    __syncthreads();
    const float mu   = red[0][0] * (1.f / DIM);
    const float var  = red[0][1] * (1.f / DIM) - mu * mu;
    const float rstd = rsqrtf(var + LN_EPS);
    const float4 g  = ((const float4*)gamma)[i];
    const float4 be = ((const float4*)beta)[i];
    float4 o4;
    o4.x = (v.x - mu) * rstd * g.x + be.x;
    o4.y = (v.y - mu) * rstd * g.y + be.y;
    o4.z = (v.z - mu) * rstd * g.z + be.z;
    o4.w = (v.w - mu) * rstd * g.w + be.w;
    ((float4*)(g_xn + (size_t)t * DIM))[i] = o4;
}

// ---------------- TF32 helpers -------------------------------------------------
__device__ __forceinline__ unsigned f2tf(float f) {
    unsigned u;
    asm("cvt.rna.tf32.f32 %0, %1;" : "=r"(u) : "f"(f));
    return u;
}
__device__ __forceinline__ float uif(unsigned u) { return __uint_as_float(u); }

__device__ __forceinline__ void mma_tf32(float* c, const unsigned* a, const unsigned* b) {
    asm volatile(
        "mma.sync.aligned.m16n8k8.row.col.f32.tf32.tf32.f32 "
        "{%0,%1,%2,%3}, {%4,%5,%6,%7}, {%8,%9}, {%0,%1,%2,%3};"
        : "+f"(c[0]), "+f"(c[1]), "+f"(c[2]), "+f"(c[3])
        : "r"(a[0]), "r"(a[1]), "r"(a[2]), "r"(a[3]), "r"(b[0]), "r"(b[1]));
}

// ---------------- TF32 tensor-core GEMM (projections) --------------------------
#define GBM 256
#define GBN 128
#define GBK 16
#define ASTR 20
#define BSTR 132
#define ASTAGE (GBM * ASTR)
#define BSTAGE (GBK * BSTR)
#define GEMM_SMEM ((2 * ASTAGE + 2 * BSTAGE) * 4)

template <int N, int K>
__device__ __forceinline__ void gemm_tf32_body(const float* __restrict__ A,
                                               const float* __restrict__ B,
                                               float* __restrict__ C) {
    extern __shared__ unsigned smem[];
    unsigned* As = smem;
    unsigned* Bs = smem + 2 * ASTAGE;

    const int tid  = threadIdx.x;
    const int warp = tid >> 5;
    const int lane = tid & 31;
    const int r = lane >> 2;
    const int c = lane & 3;
    const int wm = (warp & 3) * 64;
    const int wn = (warp >> 2) * 64;
    const int rowBase = blockIdx.y * GBM;
    const int colBase = blockIdx.x * GBN;

    const int am = tid >> 2;
    const int ak = (tid & 3) << 2;
    const int bk = tid >> 5;
    const int bn = lane << 2;

    const float* Ap = A + (size_t)(rowBase + am) * K + ak;
    const float* Bp = B + colBase + bn;

    float acc[4][8][4];
    #pragma unroll
    for (int mi = 0; mi < 4; mi++)
        #pragma unroll
        for (int ni = 0; ni < 8; ni++)
            #pragma unroll
            for (int j = 0; j < 4; j++) acc[mi][ni][j] = 0.f;

    float4 aR[4], bR[2];
    #pragma unroll
    for (int p = 0; p < 4; p++) aR[p] = *(const float4*)(Ap + (size_t)(p * 64) * K);
    #pragma unroll
    for (int p = 0; p < 2; p++) bR[p] = *(const float4*)(Bp + (size_t)(bk + 8 * p) * N);

    const int NIT = K / GBK;
    #pragma unroll 1
    for (int kt = 0; kt < NIT; kt++) {
        const int cur = kt & 1;
        {
            unsigned* as = As + cur * ASTAGE;
            unsigned* bs = Bs + cur * BSTAGE;
            #pragma unroll
            for (int p = 0; p < 4; p++) {
                uint4 u;
                u.x = f2tf(aR[p].x); u.y = f2tf(aR[p].y);
                u.z = f2tf(aR[p].z); u.w = f2tf(aR[p].w);
                *(uint4*)&as[(am + 64 * p) * ASTR + ak] = u;
            }
            #pragma unroll
            for (int p = 0; p < 2; p++) {
                uint4 u;
                u.x = f2tf(bR[p].x); u.y = f2tf(bR[p].y);
                u.z = f2tf(bR[p].z); u.w = f2tf(bR[p].w);
                *(uint4*)&bs[(bk + 8 * p) * BSTR + bn] = u;
            }
        }
        __syncthreads();

        if (kt + 1 < NIT) {
            const int k0 = (kt + 1) * GBK;
            #pragma unroll
            for (int p = 0; p < 4; p++) aR[p] = *(const float4*)(Ap + (size_t)(p * 64) * K + k0);
            #pragma unroll
            for (int p = 0; p < 2; p++) bR[p] = *(const float4*)(Bp + (size_t)(k0 + bk + 8 * p) * N);
        }

        {
            const unsigned* as = As + cur * ASTAGE;
            const unsigned* bs = Bs + cur * BSTAGE;
            #pragma unroll
            for (int kk = 0; kk < 2; kk++) {
                const int k8 = kk * 8;
                unsigned af[4][4];
                #pragma unroll
                for (int mi = 0; mi < 4; mi++) {
                    const int m0 = wm + mi * 16 + r;
                    af[mi][0] = as[m0 * ASTR + k8 + c];
                    af[mi][1] = as[(m0 + 8) * ASTR + k8 + c];
                    af[mi][2] = as[m0 * ASTR + k8 + c + 4];
                    af[mi][3] = as[(m0 + 8) * ASTR + k8 + c + 4];
                }
                unsigned bf[8][2];
                #pragma unroll
                for (int ni = 0; ni < 8; ni++) {
                    const int n0 = wn + ni * 8 + r;
                    bf[ni][0] = bs[(k8 + c) * BSTR + n0];
                    bf[ni][1] = bs[(k8 + c + 4) * BSTR + n0];
                }
                #pragma unroll
                for (int mi = 0; mi < 4; mi++)
                    #pragma unroll
                    for (int ni = 0; ni < 8; ni++)
                        mma_tf32(acc[mi][ni], af[mi], bf[ni]);
            }
        }
        __syncthreads();
    }

    #pragma unroll
    for (int mi = 0; mi < 4; mi++) {
        const int row = rowBase + wm + mi * 16 + r;
        #pragma unroll
        for (int ni = 0; ni < 8; ni++) {
            const int col = colBase + wn + ni * 8 + 2 * c;
            *(float2*)&C[(size_t)row * N + col]       = make_float2(acc[mi][ni][0], acc[mi][ni][1]);
            *(float2*)&C[(size_t)(row + 8) * N + col] = make_float2(acc[mi][ni][2], acc[mi][ni][3]);
        }
    }
}

__global__ void __launch_bounds__(256, 1) gemm_q_kernel(const float* __restrict__ Wq) {
    gemm_tf32_body<INNER, DIM>(g_xn, Wq, g_qlin);
}
__global__ void __launch_bounds__(256, 1) gemm_kv_kernel(const float* __restrict__ Wkv) {
    gemm_tf32_body<2 * INNER, DIM>(g_xn, Wkv, g_kvlin);
}
__global__ void __launch_bounds__(256, 1) gemm_o_kernel(const float* __restrict__ Wo,
                                                        float* __restrict__ out) {
    gemm_tf32_body<DIM, INNER>(g_aout, Wo, out);
}

// ---------------- head split + l2norm + scales (SCALE folded into Q) ----------
__global__ void __launch_bounds__(256) qkv_prep(const float* __restrict__ q_scale,
                                                const float* __restrict__ k_scale) {
    const int gw   = (blockIdx.x * 256 + threadIdx.x) >> 5;
    const int lane = threadIdx.x & 31;
    if (gw >= TOKENS * HEADS) return;
    const int t = gw >> 4;
    const int h = gw & 15;
    const int b = t >> 11;
    const int i = t & 2047;

    const float* qr = g_qlin + (size_t)t * INNER + h * DHEAD;
    float q0 = qr[lane], q1 = qr[lane + 32];
    float ss = q0 * q0 + q1 * q1;
    #pragma unroll
    for (int o = 16; o > 0; o >>= 1) ss += __shfl_xor_sync(0xFFFFFFFFu, ss, o);
    float inv = 1.f / fmaxf(sqrtf(ss), L2_EPS);
    float* qo = g_Q + ((size_t)(b * HEADS + h) * SEQ + i) * DHEAD;
    qo[lane]      = q0 * inv * q_scale[lane]      * SCALE_F;
    qo[lane + 32] = q1 * inv * q_scale[lane + 32] * SCALE_F;

    const float* kr = g_kvlin + (size_t)t * (2 * INNER) + h * DHEAD;
    float k0 = kr[lane], k1 = kr[lane + 32];
    ss = k0 * k0 + k1 * k1;
    #pragma unroll
    for (int o = 16; o > 0; o >>= 1) ss += __shfl_xor_sync(0xFFFFFFFFu, ss, o);
    inv = 1.f / fmaxf(sqrtf(ss), L2_EPS);
    float* ko = g_K + ((size_t)(b * HEADS + h) * KVLEN + i + 1) * DHEAD;
    ko[lane]      = k0 * inv * k_scale[lane];
    ko[lane + 32] = k1 * inv * k_scale[lane + 32];

    const float* vr = g_kvlin + (size_t)t * (2 * INNER) + INNER + h * DHEAD;
    float* vo = g_V + ((size_t)(b * HEADS + h) * KVLEN + i + 1) * DHEAD;
    vo[lane]      = vr[lane];
    vo[lane + 32] = vr[lane + 32];
}

__global__ void null_prep(const float* __restrict__ null_kv,
                          const float* __restrict__ k_scale) {
    const int bh = blockIdx.x;
    const int h = bh & 15;
    const int lane = threadIdx.x;
    const float* nk = null_kv + h * DHEAD;
    const float* nv = null_kv + HEADS * DHEAD + h * DHEAD;
    float k0 = nk[lane], k1 = nk[lane + 32];
    float ss = k0 * k0 + k1 * k1;
    #pragma unroll
    for (int o = 16; o > 0; o >>= 1) ss += __shfl_xor_sync(0xFFFFFFFFu, ss, o);
    const float inv = 1.f / fmaxf(sqrtf(ss), L2_EPS);
    float* ko = g_K + (size_t)bh * KVLEN * DHEAD;
    ko[lane]      = k0 * inv * k_scale[lane];
    ko[lane + 32] = k1 * inv * k_scale[lane + 32];
    float* vo = g_V + (size_t)bh * KVLEN * DHEAD;
    vo[lane]      = nv[lane];
    vo[lane + 32] = nv[lane + 32];
}

// ---------------- flash attention on tensor cores (split-TF32, 3-pass) --------
#define ABQ 128
#define ABK 64
#define ANT ((KVLEN + ABK - 1) / ABK)   /* 33 */
#define KTLD 72   /* Kt row pad (words): conflict-free b-frag loads */
#define VLD  72   /* Vs row pad */
#define PLD  68   /* P  row pad: conflict-free a-frag loads */

#define ATT_SMEM ((2*64*KTLD + 2*64*VLD + 2*ABQ*PLD) * 4)   /* 143360 B */

__global__ void __launch_bounds__(256, 1) attn_mma_kernel() {
    extern __shared__ unsigned ash[];
    unsigned* KtHi = ash;                      // [d][j]  64 x KTLD
    unsigned* KtLo = KtHi + 64 * KTLD;
    unsigned* Vhi  = KtLo + 64 * KTLD;         // [j][d]  64 x VLD
    unsigned* Vlo  = Vhi  + 64 * VLD;
    unsigned* Phi  = Vlo  + 64 * VLD;          // [row][j] ABQ x PLD
    unsigned* Plo  = Phi  + ABQ * PLD;

    const int tid  = threadIdx.x;
    const int warp = tid >> 5;
    const int lane = tid & 31;
    const int r = lane >> 2;
    const int c = lane & 3;
    const int bh = blockIdx.y;
    const int qt = blockIdx.x;
    const int m0 = warp * 16;

    // ---- Q fragments (register resident, hi/lo split) ----
    const float* Qg = g_Q + ((size_t)bh * SEQ + (size_t)qt * ABQ + m0) * DHEAD;
    unsigned qhi[8][4], qlo[8][4];
    #pragma unroll
    for (int k = 0; k < 8; k++) {
        float a0 = Qg[(size_t)r * DHEAD + k * 8 + c];
        float a1 = Qg[(size_t)(r + 8) * DHEAD + k * 8 + c];
        float a2 = Qg[(size_t)r * DHEAD + k * 8 + c + 4];
        float a3 = Qg[(size_t)(r + 8) * DHEAD + k * 8 + c + 4];
        qhi[k][0] = f2tf(a0); qlo[k][0] = f2tf(a0 - uif(qhi[k][0]));
        qhi[k][1] = f2tf(a1); qlo[k][1] = f2tf(a1 - uif(qhi[k][1]));
        qhi[k][2] = f2tf(a2); qlo[k][2] = f2tf(a2 - uif(qhi[k][2]));
        qhi[k][3] = f2tf(a3); qlo[k][3] = f2tf(a3 - uif(qhi[k][3]));
    }

    float oacc[8][4];
    #pragma unroll
    for (int nt = 0; nt < 8; nt++)
        #pragma unroll
        for (int j = 0; j < 4; j++) oacc[nt][j] = 0.f;
    float mrow0 = -1e30f, mrow1 = -1e30f, lrow0 = 0.f, lrow1 = 0.f;

    const float* Kg = g_K + (size_t)bh * KVLEN * DHEAD;
    const float* Vg = g_V + (size_t)bh * KVLEN * DHEAD;

    for (int kt = 0; kt < ANT; kt++) {
        const int kvbase = kt * ABK;
        __syncthreads();   // previous tile's smem readers done

        // ---- fill Kt (transposed, hi/lo) ----
        {
            const int j  = tid & 63;
            const int d0 = (tid >> 6) << 4;
            const bool ok = (kvbase + j) < KVLEN;
            const float* kp = Kg + (size_t)(kvbase + j) * DHEAD + d0;
            #pragma unroll
            for (int u = 0; u < 4; u++) {
                float4 v = ok ? *(const float4*)(kp + u * 4) : make_float4(0.f, 0.f, 0.f, 0.f);
                const float f[4] = {v.x, v.y, v.z, v.w};
                #pragma unroll
                for (int i = 0; i < 4; i++) {
                    unsigned h = f2tf(f[i]);
                    KtHi[(d0 + u * 4 + i) * KTLD + j] = h;
                    KtLo[(d0 + u * 4 + i) * KTLD + j] = f2tf(f[i] - uif(h));
                }
            }
        }
        // ---- fill V (natural, hi/lo) ----
        {
            const int j  = tid >> 2;
            const int d0 = (tid & 3) << 4;
            const bool ok = (kvbase + j) < KVLEN;
            const float* vp = Vg + (size_t)(kvbase + j) * DHEAD + d0;
            #pragma unroll
            for (int u = 0; u < 4; u++) {
                float4 v = ok ? *(const float4*)(vp + u * 4) : make_float4(0.f, 0.f, 0.f, 0.f);
                const float f[4] = {v.x, v.y, v.z, v.w};
                #pragma unroll
                for (int i = 0; i < 4; i++) {
                    unsigned h = f2tf(f[i]);
                    Vhi[j * VLD + d0 + u * 4 + i] = h;
                    Vlo[j * VLD + d0 + u * 4 + i] = f2tf(f[i] - uif(h));
                }
            }
        }
        __syncthreads();

        // ---- S = Q K^T (3-pass split tf32) ----
        float sa[8][4];
        #pragma unroll
        for (int nt = 0; nt < 8; nt++)
            #pragma unroll
            for (int j = 0; j < 4; j++) sa[nt][j] = 0.f;

        #pragma unroll
        for (int k = 0; k < 8; k++) {
            #pragma unroll
            for (int nt = 0; nt < 8; nt++) {
                unsigned bfh[2], bfl[2];
                bfh[0] = KtHi[(k * 8 + c) * KTLD + nt * 8 + r];
                bfh[1] = KtHi[(k * 8 + c + 4) * KTLD + nt * 8 + r];
                bfl[0] = KtLo[(k * 8 + c) * KTLD + nt * 8 + r];
                bfl[1] = KtLo[(k * 8 + c + 4) * KTLD + nt * 8 + r];
                mma_tf32(sa[nt], qhi[k], bfh);
                mma_tf32(sa[nt], qhi[k], bfl);
                mma_tf32(sa[nt], qlo[k], bfh);
            }
        }

        // ---- mask + online softmax ----
        float tmax0 = -1e30f, tmax1 = -1e30f;
        #pragma unroll
        for (int nt = 0; nt < 8; nt++) {
            const int j0 = kvbase + nt * 8 + 2 * c;
            if (j0 >= KVLEN)     { sa[nt][0] = -1e30f; sa[nt][2] = -1e30f; }
            if (j0 + 1 >= KVLEN) { sa[nt][1] = -1e30f; sa[nt][3] = -1e30f; }
            tmax0 = fmaxf(tmax0, fmaxf(sa[nt][0], sa[nt][1]));
            tmax1 = fmaxf(tmax1, fmaxf(sa[nt][2], sa[nt][3]));
        }
        tmax0 = fmaxf(tmax0, __shfl_xor_sync(0xFFFFFFFFu, tmax0, 1));
        tmax0 = fmaxf(tmax0, __shfl_xor_sync(0xFFFFFFFFu, tmax0, 2));
        tmax1 = fmaxf(tmax1, __shfl_xor_sync(0xFFFFFFFFu, tmax1, 1));
        tmax1 = fmaxf(tmax1, __shfl_xor_sync(0xFFFFFFFFu, tmax1, 2));

        const float mnew0 = fmaxf(mrow0, tmax0);
        const float mnew1 = fmaxf(mrow1, tmax1);
        const float cf0 = __expf(mrow0 - mnew0);
        const float cf1 = __expf(mrow1 - mnew1);
        mrow0 = mnew0; mrow1 = mnew1;

        float psum0 = 0.f, psum1 = 0.f;
        #pragma unroll
        for (int nt = 0; nt < 8; nt++) {
            const float p0 = __expf(sa[nt][0] - mnew0);
            const float p1 = __expf(sa[nt][1] - mnew0);
            const float p2 = __expf(sa[nt][2] - mnew1);
            const float p3 = __expf(sa[nt][3] - mnew1);
            psum0 += p0 + p1;
            psum1 += p2 + p3;
            const unsigned h0 = f2tf(p0), h1 = f2tf(p1), h2 = f2tf(p2), h3 = f2tf(p3);
            uint2 hv0 = make_uint2(h0, h1);
            uint2 lv0 = make_uint2(f2tf(p0 - uif(h0)), f2tf(p1 - uif(h1)));
            uint2 hv1 = make_uint2(h2, h3);
            uint2 lv1 = make_uint2(f2tf(p2 - uif(h2)), f2tf(p3 - uif(h3)));
            const int base0 = (m0 + r) * PLD + nt * 8 + 2 * c;
            const int base1 = (m0 + r + 8) * PLD + nt * 8 + 2 * c;
            *(uint2*)&Phi[base0] = hv0;
            *(uint2*)&Plo[base0] = lv0;
            *(uint2*)&Phi[base1] = hv1;
            *(uint2*)&Plo[base1] = lv1;
        }
        psum0 += __shfl_xor_sync(0xFFFFFFFFu, psum0, 1);
        psum0 += __shfl_xor_sync(0xFFFFFFFFu, psum0, 2);
        psum1 += __shfl_xor_sync(0xFFFFFFFFu, psum1, 1);
        psum1 += __shfl_xor_sync(0xFFFFFFFFu, psum1, 2);
        lrow0 = lrow0 * cf0 + psum0;
        lrow1 = lrow1 * cf1 + psum1;

        // rescale O accumulators
        #pragma unroll
        for (int nt = 0; nt < 8; nt++) {
            oacc[nt][0] *= cf0; oacc[nt][1] *= cf0;
            oacc[nt][2] *= cf1; oacc[nt][3] *= cf1;
        }
        __syncwarp();   // P rows are warp-private: warp-level visibility is enough

        // ---- O += P V (3-pass split tf32) ----
        #pragma unroll
        for (int k = 0; k < 8; k++) {
            unsigned pah[4], pal[4];
            pah[0] = Phi[(m0 + r) * PLD + k * 8 + c];
            pah[1] = Phi[(m0 + r + 8) * PLD + k * 8 + c];
            pah[2] = Phi[(m0 + r) * PLD + k * 8 + c + 4];
            pah[3] = Phi[(m0 + r + 8) * PLD + k * 8 + c + 4];
            pal[0] = Plo[(m0 + r) * PLD + k * 8 + c];
            pal[1] = Plo[(m0 + r + 8) * PLD + k * 8 + c];
            pal[2] = Plo[(m0 + r) * PLD + k * 8 + c + 4];
            pal[3] = Plo[(m0 + r + 8) * PLD + k * 8 + c + 4];
            #pragma unroll
            for (int nt = 0; nt < 8; nt++) {
                unsigned vfh[2], vfl[2];
                vfh[0] = Vhi[(k * 8 + c) * VLD + nt * 8 + r];
                vfh[1] = Vhi[(k * 8 + c + 4) * VLD + nt * 8 + r];
                vfl[0] = Vlo[(k * 8 + c) * VLD + nt * 8 + r];
                vfl[1] = Vlo[(k * 8 + c + 4) * VLD + nt * 8 + r];
                mma_tf32(oacc[nt], pah, vfh);
                mma_tf32(oacc[nt], pah, vfl);
                mma_tf32(oacc[nt], pal, vfh);
            }
        }
    }

    // ---- epilogue ----
    const float li0 = 1.f / lrow0;
    const float li1 = 1.f / lrow1;
    const int b = bh >> 4, h = bh & 15;
    const int row0 = qt * ABQ + m0 + r;
    #pragma unroll
    for (int nt = 0; nt < 8; nt++) {
        const int col = h * DHEAD + nt * 8 + 2 * c;
        float* o0 = g_aout + (size_t)(b * SEQ + row0) * INNER + col;
        float* o1 = g_aout + (size_t)(b * SEQ + row0 + 8) * INNER + col;
        *(float2*)o0 = make_float2(oacc[nt][0] * li0, oacc[nt][1] * li0);
        *(float2*)o1 = make_float2(oacc[nt][2] * li1, oacc[nt][3] * li1);
    }
}

// ---------------- launch ------------------------------------------------------
extern "C" void kernel_launch(void* const* d_in, const int* in_sizes, int n_in,
                              void* d_out, int out_size) {
    const float* x       = (const float*)d_in[0];
    const float* gamma   = (const float*)d_in[1];
    const float* beta    = (const float*)d_in[2];
    const float* null_kv = (const float*)d_in[3];
    const float* Wq      = (const float*)d_in[4];
    const float* Wkv     = (const float*)d_in[5];
    const float* q_scale = (const float*)d_in[6];
    const float* k_scale = (const float*)d_in[7];
    const float* Wo      = (const float*)d_in[8];
    float* out = (float*)d_out;

    cudaFuncSetAttribute(gemm_q_kernel,  cudaFuncAttributeMaxDynamicSharedMemorySize, GEMM_SMEM);
    cudaFuncSetAttribute(gemm_kv_kernel, cudaFuncAttributeMaxDynamicSharedMemorySize, GEMM_SMEM);
    cudaFuncSetAttribute(gemm_o_kernel,  cudaFuncAttributeMaxDynamicSharedMemorySize, GEMM_SMEM);
    cudaFuncSetAttribute(attn_mma_kernel, cudaFuncAttributeMaxDynamicSharedMemorySize, ATT_SMEM);

    ln_kernel<<<TOKENS, 256>>>(x, gamma, beta);
    gemm_q_kernel <<<dim3(INNER / GBN,     TOKENS / GBM), 256, GEMM_SMEM>>>(Wq);
    gemm_kv_kernel<<<dim3(2 * INNER / GBN, TOKENS / GBM), 256, GEMM_SMEM>>>(Wkv);
    qkv_prep<<<(TOKENS * HEADS) / 8, 256>>>(q_scale, k_scale);
    null_prep<<<BATCH * HEADS, 32>>>(null_kv, k_scale);
    attn_mma_kernel<<<dim3(SEQ / ABQ, BATCH * HEADS), 256, ATT_SMEM>>>();
    gemm_o_kernel<<<dim3(DIM / GBN, TOKENS / GBM), 256, GEMM_SMEM>>>(Wo, out);
}

// round 4
// speedup vs baseline: 4.5478x; 1.4506x over previous
#include <cuda_runtime.h>
#include <cuda_fp16.h>
#include <math.h>

#define HEADS   16
#define DHEAD   64
#define BATCH   4
#define SEQ     2048
#define DIM     1024
#define INNER   1024
#define TOKENS  (BATCH*SEQ)       /* 8192 */
#define KVLEN   (SEQ+1)           /* 2049 */
#define SCALE_F 8.0f
#define LN_EPS  1e-5f
#define L2_EPS  1e-12f

// ---------------- scratch (global device arrays; no allocations) -------------
__device__ float g_xn   [TOKENS * DIM];
__device__ float g_qlin [TOKENS * INNER];
__device__ float g_kvlin[TOKENS * 2 * INNER];
__device__ float g_Q    [BATCH * HEADS * SEQ   * DHEAD];
__device__ float g_K    [BATCH * HEADS * KVLEN * DHEAD];
__device__ float g_V    [BATCH * HEADS * KVLEN * DHEAD];
__device__ float g_aout [TOKENS * INNER];

// ---------------- LayerNorm ---------------------------------------------------
__global__ void __launch_bounds__(256) ln_kernel(const float* __restrict__ x,
                                                 const float* __restrict__ gamma,
                                                 const float* __restrict__ beta) {
    __shared__ float red[8][2];
    const int t = blockIdx.x;
    const int i = threadIdx.x;
    const float4 v = ((const float4*)(x + (size_t)t * DIM))[i];
    float s  = v.x + v.y + v.z + v.w;
    float ss = v.x*v.x + v.y*v.y + v.z*v.z + v.w*v.w;
    #pragma unroll
    for (int o = 16; o > 0; o >>= 1) {
        s  += __shfl_xor_sync(0xFFFFFFFFu, s,  o);
        ss += __shfl_xor_sync(0xFFFFFFFFu, ss, o);
    }
    const int w = i >> 5, l = i & 31;
    if (l == 0) { red[w][0] = s; red[w][1] = ss; }
    __syncthreads();
    if (w == 0) {
        s  = (l < 8) ? red[l][0] : 0.f;
        ss = (l < 8) ? red[l][1] : 0.f;
        #pragma unroll
        for (int o = 4; o > 0; o >>= 1) {
            s  += __shfl_xor_sync(0xFFFFFFFFu, s,  o);
            ss += __shfl_xor_sync(0xFFFFFFFFu, ss, o);
        }
        if (l == 0) { red[0][0] = s; red[0][1] = ss; }
    }
    __syncthreads();
    const float mu   = red[0][0] * (1.f / DIM);
    const float var  = red[0][1] * (1.f / DIM) - mu * mu;
    const float rstd = rsqrtf(var + LN_EPS);
    const float4 g  = ((const float4*)gamma)[i];
    const float4 be = ((const float4*)beta)[i];
    float4 o4;
    o4.x = (v.x - mu) * rstd * g.x + be.x;
    o4.y = (v.y - mu) * rstd * g.y + be.y;
    o4.z = (v.z - mu) * rstd * g.z + be.z;
    o4.w = (v.w - mu) * rstd * g.w + be.w;
    ((float4*)(g_xn + (size_t)t * DIM))[i] = o4;
}

// ---------------- TF32 helpers -------------------------------------------------
__device__ __forceinline__ unsigned f2tf(float f) {
    unsigned u;
    asm("cvt.rna.tf32.f32 %0, %1;" : "=r"(u) : "f"(f));
    return u;
}
__device__ __forceinline__ float uif(unsigned u) { return __uint_as_float(u); }

__device__ __forceinline__ void mma_tf32(float* c, const unsigned* a, const unsigned* b) {
    asm volatile(
        "mma.sync.aligned.m16n8k8.row.col.f32.tf32.tf32.f32 "
        "{%0,%1,%2,%3}, {%4,%5,%6,%7}, {%8,%9}, {%0,%1,%2,%3};"
        : "+f"(c[0]), "+f"(c[1]), "+f"(c[2]), "+f"(c[3])
        : "r"(a[0]), "r"(a[1]), "r"(a[2]), "r"(a[3]), "r"(b[0]), "r"(b[1]));
}

// ---------------- fp16 helpers --------------------------------------------------
__device__ __forceinline__ void mma_f16(float* c, const unsigned* a, const unsigned* b) {
    asm volatile(
        "mma.sync.aligned.m16n8k16.row.col.f32.f16.f16.f32 "
        "{%0,%1,%2,%3}, {%4,%5,%6,%7}, {%8,%9}, {%0,%1,%2,%3};"
        : "+f"(c[0]), "+f"(c[1]), "+f"(c[2]), "+f"(c[3])
        : "r"(a[0]), "r"(a[1]), "r"(a[2]), "r"(a[3]), "r"(b[0]), "r"(b[1]));
}

// split a pair of floats into packed-f16 hi and packed-f16 lo (residual)
__device__ __forceinline__ void split2(float a, float b, unsigned& hi, unsigned& lo) {
    __half ha = __float2half_rn(a);
    __half hb = __float2half_rn(b);
    float la = a - __half2float(ha);
    float lb = b - __half2float(hb);
    __half2 h2 = __halves2half2(ha, hb);
    __half2 l2 = __floats2half2_rn(la, lb);
    hi = *(unsigned*)&h2;
    lo = *(unsigned*)&l2;
}

// ---------------- TF32 tensor-core GEMM (projections) --------------------------
#define GBM 256
#define GBN 128
#define GBK 16
#define ASTR 20
#define BSTR 132
#define ASTAGE (GBM * ASTR)
#define BSTAGE (GBK * BSTR)
#define GEMM_SMEM ((2 * ASTAGE + 2 * BSTAGE) * 4)

template <int N, int K>
__device__ __forceinline__ void gemm_tf32_body(const float* __restrict__ A,
                                               const float* __restrict__ B,
                                               float* __restrict__ C) {
    extern __shared__ unsigned smem[];
    unsigned* As = smem;
    unsigned* Bs = smem + 2 * ASTAGE;

    const int tid  = threadIdx.x;
    const int warp = tid >> 5;
    const int lane = tid & 31;
    const int r = lane >> 2;
    const int c = lane & 3;
    const int wm = (warp & 3) * 64;
    const int wn = (warp >> 2) * 64;
    const int rowBase = blockIdx.y * GBM;
    const int colBase = blockIdx.x * GBN;

    const int am = tid >> 2;
    const int ak = (tid & 3) << 2;
    const int bk = tid >> 5;
    const int bn = lane << 2;

    const float* Ap = A + (size_t)(rowBase + am) * K + ak;
    const float* Bp = B + colBase + bn;

    float acc[4][8][4];
    #pragma unroll
    for (int mi = 0; mi < 4; mi++)
        #pragma unroll
        for (int ni = 0; ni < 8; ni++)
            #pragma unroll
            for (int j = 0; j < 4; j++) acc[mi][ni][j] = 0.f;

    float4 aR[4], bR[2];
    #pragma unroll
    for (int p = 0; p < 4; p++) aR[p] = *(const float4*)(Ap + (size_t)(p * 64) * K);
    #pragma unroll
    for (int p = 0; p < 2; p++) bR[p] = *(const float4*)(Bp + (size_t)(bk + 8 * p) * N);

    const int NIT = K / GBK;
    #pragma unroll 1
    for (int kt = 0; kt < NIT; kt++) {
        const int cur = kt & 1;
        {
            unsigned* as = As + cur * ASTAGE;
            unsigned* bs = Bs + cur * BSTAGE;
            #pragma unroll
            for (int p = 0; p < 4; p++) {
                uint4 u;
                u.x = f2tf(aR[p].x); u.y = f2tf(aR[p].y);
                u.z = f2tf(aR[p].z); u.w = f2tf(aR[p].w);
                *(uint4*)&as[(am + 64 * p) * ASTR + ak] = u;
            }
            #pragma unroll
            for (int p = 0; p < 2; p++) {
                uint4 u;
                u.x = f2tf(bR[p].x); u.y = f2tf(bR[p].y);
                u.z = f2tf(bR[p].z); u.w = f2tf(bR[p].w);
                *(uint4*)&bs[(bk + 8 * p) * BSTR + bn] = u;
            }
        }
        __syncthreads();

        if (kt + 1 < NIT) {
            const int k0 = (kt + 1) * GBK;
            #pragma unroll
            for (int p = 0; p < 4; p++) aR[p] = *(const float4*)(Ap + (size_t)(p * 64) * K + k0);
            #pragma unroll
            for (int p = 0; p < 2; p++) bR[p] = *(const float4*)(Bp + (size_t)(k0 + bk + 8 * p) * N);
        }

        {
            const unsigned* as = As + cur * ASTAGE;
            const unsigned* bs = Bs + cur * BSTAGE;
            #pragma unroll
            for (int kk = 0; kk < 2; kk++) {
                const int k8 = kk * 8;
                unsigned af[4][4];
                #pragma unroll
                for (int mi = 0; mi < 4; mi++) {
                    const int m0 = wm + mi * 16 + r;
                    af[mi][0] = as[m0 * ASTR + k8 + c];
                    af[mi][1] = as[(m0 + 8) * ASTR + k8 + c];
                    af[mi][2] = as[m0 * ASTR + k8 + c + 4];
                    af[mi][3] = as[(m0 + 8) * ASTR + k8 + c + 4];
                }
                unsigned bf[8][2];
                #pragma unroll
                for (int ni = 0; ni < 8; ni++) {
                    const int n0 = wn + ni * 8 + r;
                    bf[ni][0] = bs[(k8 + c) * BSTR + n0];
                    bf[ni][1] = bs[(k8 + c + 4) * BSTR + n0];
                }
                #pragma unroll
                for (int mi = 0; mi < 4; mi++)
                    #pragma unroll
                    for (int ni = 0; ni < 8; ni++)
                        mma_tf32(acc[mi][ni], af[mi], bf[ni]);
            }
        }
        __syncthreads();
    }

    #pragma unroll
    for (int mi = 0; mi < 4; mi++) {
        const int row = rowBase + wm + mi * 16 + r;
        #pragma unroll
        for (int ni = 0; ni < 8; ni++) {
            const int col = colBase + wn + ni * 8 + 2 * c;
            *(float2*)&C[(size_t)row * N + col]       = make_float2(acc[mi][ni][0], acc[mi][ni][1]);
            *(float2*)&C[(size_t)(row + 8) * N + col] = make_float2(acc[mi][ni][2], acc[mi][ni][3]);
        }
    }
}

__global__ void __launch_bounds__(256, 1) gemm_q_kernel(const float* __restrict__ Wq) {
    gemm_tf32_body<INNER, DIM>(g_xn, Wq, g_qlin);
}
__global__ void __launch_bounds__(256, 1) gemm_kv_kernel(const float* __restrict__ Wkv) {
    gemm_tf32_body<2 * INNER, DIM>(g_xn, Wkv, g_kvlin);
}
__global__ void __launch_bounds__(256, 1) gemm_o_kernel(const float* __restrict__ Wo,
                                                        float* __restrict__ out) {
    gemm_tf32_body<DIM, INNER>(g_aout, Wo, out);
}

// ---------------- head split + l2norm + scales (SCALE folded into Q) ----------
__global__ void __launch_bounds__(256) qkv_prep(const float* __restrict__ q_scale,
                                                const float* __restrict__ k_scale) {
    const int gw   = (blockIdx.x * 256 + threadIdx.x) >> 5;
    const int lane = threadIdx.x & 31;
    if (gw >= TOKENS * HEADS) return;
    const int t = gw >> 4;
    const int h = gw & 15;
    const int b = t >> 11;
    const int i = t & 2047;

    const float* qr = g_qlin + (size_t)t * INNER + h * DHEAD;
    float q0 = qr[lane], q1 = qr[lane + 32];
    float ss = q0 * q0 + q1 * q1;
    #pragma unroll
    for (int o = 16; o > 0; o >>= 1) ss += __shfl_xor_sync(0xFFFFFFFFu, ss, o);
    float inv = 1.f / fmaxf(sqrtf(ss), L2_EPS);
    float* qo = g_Q + ((size_t)(b * HEADS + h) * SEQ + i) * DHEAD;
    qo[lane]      = q0 * inv * q_scale[lane]      * SCALE_F;
    qo[lane + 32] = q1 * inv * q_scale[lane + 32] * SCALE_F;

    const float* kr = g_kvlin + (size_t)t * (2 * INNER) + h * DHEAD;
    float k0 = kr[lane], k1 = kr[lane + 32];
    ss = k0 * k0 + k1 * k1;
    #pragma unroll
    for (int o = 16; o > 0; o >>= 1) ss += __shfl_xor_sync(0xFFFFFFFFu, ss, o);
    inv = 1.f / fmaxf(sqrtf(ss), L2_EPS);
    float* ko = g_K + ((size_t)(b * HEADS + h) * KVLEN + i + 1) * DHEAD;
    ko[lane]      = k0 * inv * k_scale[lane];
    ko[lane + 32] = k1 * inv * k_scale[lane + 32];

    const float* vr = g_kvlin + (size_t)t * (2 * INNER) + INNER + h * DHEAD;
    float* vo = g_V + ((size_t)(b * HEADS + h) * KVLEN + i + 1) * DHEAD;
    vo[lane]      = vr[lane];
    vo[lane + 32] = vr[lane + 32];
}

__global__ void null_prep(const float* __restrict__ null_kv,
                          const float* __restrict__ k_scale) {
    const int bh = blockIdx.x;
    const int h = bh & 15;
    const int lane = threadIdx.x;
    const float* nk = null_kv + h * DHEAD;
    const float* nv = null_kv + HEADS * DHEAD + h * DHEAD;
    float k0 = nk[lane], k1 = nk[lane + 32];
    float ss = k0 * k0 + k1 * k1;
    #pragma unroll
    for (int o = 16; o > 0; o >>= 1) ss += __shfl_xor_sync(0xFFFFFFFFu, ss, o);
    const float inv = 1.f / fmaxf(sqrtf(ss), L2_EPS);
    float* ko = g_K + (size_t)bh * KVLEN * DHEAD;
    ko[lane]      = k0 * inv * k_scale[lane];
    ko[lane + 32] = k1 * inv * k_scale[lane + 32];
    float* vo = g_V + (size_t)bh * KVLEN * DHEAD;
    vo[lane]      = nv[lane];
    vo[lane + 32] = nv[lane + 32];
}

// ---------------- flash attention, fp16 hi/lo split on tensor cores -----------
// S = qh*kh + qh*kl + ql*kh   (residual ql*kl ~ 2^-22: negligible)
// O += ph*vh + ph*vl + pl*vh
#define ABQ 128
#define ABK 64
#define ANT ((KVLEN + ABK - 1) / ABK)   /* 33 */
#define KTLD 72   /* KtP row length (words of f16x2 pairs over j) */
#define VLD  72   /* VP  row length */
#define PLD2 36   /* PP  row length (words, 32 used) */

#define ATT_SMEM ((2*32*KTLD + 2*32*VLD + 2*ABQ*PLD2) * 4)   /* 73728 B */

__global__ void __launch_bounds__(256, 2) attn_mma_kernel() {
    extern __shared__ unsigned ash[];
    unsigned* KtHi = ash;                      // [dd=32][KTLD]  pairs over d
    unsigned* KtLo = KtHi + 32 * KTLD;
    unsigned* VHi  = KtLo + 32 * KTLD;         // [jj=32][VLD]   pairs over j
    unsigned* VLo  = VHi  + 32 * VLD;
    unsigned* PHi  = VLo  + 32 * VLD;          // [row=128][PLD2] pairs over j
    unsigned* PLo  = PHi  + ABQ * PLD2;

    const int tid  = threadIdx.x;
    const int warp = tid >> 5;
    const int lane = tid & 31;
    const int r = lane >> 2;
    const int c = lane & 3;
    const int bh = blockIdx.y;
    const int qt = blockIdx.x;
    const int m0 = warp * 16;

    // ---- Q fragments (register resident, fp16 hi/lo split) ----
    const float* Qg = g_Q + ((size_t)bh * SEQ + (size_t)qt * ABQ + m0) * DHEAD;
    unsigned qhi[4][4], qlo[4][4];
    #pragma unroll
    for (int s = 0; s < 4; s++) {
        float2 x0 = *(const float2*)(Qg + (size_t)r * DHEAD + s * 16 + 2 * c);
        float2 x1 = *(const float2*)(Qg + (size_t)(r + 8) * DHEAD + s * 16 + 2 * c);
        float2 x2 = *(const float2*)(Qg + (size_t)r * DHEAD + s * 16 + 2 * c + 8);
        float2 x3 = *(const float2*)(Qg + (size_t)(r + 8) * DHEAD + s * 16 + 2 * c + 8);
        split2(x0.x, x0.y, qhi[s][0], qlo[s][0]);
        split2(x1.x, x1.y, qhi[s][1], qlo[s][1]);
        split2(x2.x, x2.y, qhi[s][2], qlo[s][2]);
        split2(x3.x, x3.y, qhi[s][3], qlo[s][3]);
    }

    float oacc[8][4];
    #pragma unroll
    for (int nt = 0; nt < 8; nt++)
        #pragma unroll
        for (int j = 0; j < 4; j++) oacc[nt][j] = 0.f;
    float mrow0 = -1e30f, mrow1 = -1e30f, lrow0 = 0.f, lrow1 = 0.f;

    const float* Kg = g_K + (size_t)bh * KVLEN * DHEAD;
    const float* Vg = g_V + (size_t)bh * KVLEN * DHEAD;

    for (int kt = 0; kt < ANT; kt++) {
        const int kvbase = kt * ABK;
        __syncthreads();

        // ---- fill KtP: packed d-pairs, transposed [dd][j] ----
        {
            const int j  = tid & 63;
            const int d0 = (tid >> 6) << 4;          // 0,16,32,48
            const bool ok = (kvbase + j) < KVLEN;
            const float* kp = Kg + (size_t)(kvbase + j) * DHEAD + d0;
            #pragma unroll
            for (int u = 0; u < 4; u++) {
                float4 v = ok ? *(const float4*)(kp + u * 4) : make_float4(0.f, 0.f, 0.f, 0.f);
                unsigned h0, l0, h1, l1;
                split2(v.x, v.y, h0, l0);
                split2(v.z, v.w, h1, l1);
                const int dd = (d0 >> 1) + u * 2;
                KtHi[dd * KTLD + j]       = h0;
                KtHi[(dd + 1) * KTLD + j] = h1;
                KtLo[dd * KTLD + j]       = l0;
                KtLo[(dd + 1) * KTLD + j] = l1;
            }
        }
        // ---- fill VP: packed j-pairs [jj][d] ----
        {
            const int jj = tid >> 3;                 // 0..31
            const int d0 = (tid & 7) << 3;           // 0..56
            const int j0 = kvbase + 2 * jj;
            const bool ok0 = j0 < KVLEN;
            const bool ok1 = (j0 + 1) < KVLEN;
            const float* v0p = Vg + (size_t)j0 * DHEAD + d0;
            const float* v1p = Vg + (size_t)(j0 + 1) * DHEAD + d0;
            float4 a0 = ok0 ? *(const float4*)v0p       : make_float4(0.f, 0.f, 0.f, 0.f);
            float4 a1 = ok0 ? *(const float4*)(v0p + 4) : make_float4(0.f, 0.f, 0.f, 0.f);
            float4 b0 = ok1 ? *(const float4*)v1p       : make_float4(0.f, 0.f, 0.f, 0.f);
            float4 b1 = ok1 ? *(const float4*)(v1p + 4) : make_float4(0.f, 0.f, 0.f, 0.f);
            const float fa[8] = {a0.x, a0.y, a0.z, a0.w, a1.x, a1.y, a1.z, a1.w};
            const float fb[8] = {b0.x, b0.y, b0.z, b0.w, b1.x, b1.y, b1.z, b1.w};
            #pragma unroll
            for (int i = 0; i < 8; i++) {
                unsigned h, l;
                split2(fa[i], fb[i], h, l);
                VHi[jj * VLD + d0 + i] = h;
                VLo[jj * VLD + d0 + i] = l;
            }
        }
        __syncthreads();

        // ---- S = Q K^T (fp16 3-pass split, m16n8k16) ----
        float sa[8][4];
        #pragma unroll
        for (int nt = 0; nt < 8; nt++)
            #pragma unroll
            for (int j = 0; j < 4; j++) sa[nt][j] = 0.f;

        #pragma unroll
        for (int s = 0; s < 4; s++) {
            #pragma unroll
            for (int nt = 0; nt < 8; nt++) {
                unsigned bfh[2], bfl[2];
                bfh[0] = KtHi[(8 * s + c) * KTLD + nt * 8 + r];
                bfh[1] = KtHi[(8 * s + c + 4) * KTLD + nt * 8 + r];
                bfl[0] = KtLo[(8 * s + c) * KTLD + nt * 8 + r];
                bfl[1] = KtLo[(8 * s + c + 4) * KTLD + nt * 8 + r];
                mma_f16(sa[nt], qhi[s], bfh);
                mma_f16(sa[nt], qhi[s], bfl);
                mma_f16(sa[nt], qlo[s], bfh);
            }
        }

        // ---- mask + online softmax ----
        float tmax0 = -1e30f, tmax1 = -1e30f;
        #pragma unroll
        for (int nt = 0; nt < 8; nt++) {
            const int j0 = kvbase + nt * 8 + 2 * c;
            if (j0 >= KVLEN)     { sa[nt][0] = -1e30f; sa[nt][2] = -1e30f; }
            if (j0 + 1 >= KVLEN) { sa[nt][1] = -1e30f; sa[nt][3] = -1e30f; }
            tmax0 = fmaxf(tmax0, fmaxf(sa[nt][0], sa[nt][1]));
            tmax1 = fmaxf(tmax1, fmaxf(sa[nt][2], sa[nt][3]));
        }
        tmax0 = fmaxf(tmax0, __shfl_xor_sync(0xFFFFFFFFu, tmax0, 1));
        tmax0 = fmaxf(tmax0, __shfl_xor_sync(0xFFFFFFFFu, tmax0, 2));
        tmax1 = fmaxf(tmax1, __shfl_xor_sync(0xFFFFFFFFu, tmax1, 1));
        tmax1 = fmaxf(tmax1, __shfl_xor_sync(0xFFFFFFFFu, tmax1, 2));

        const float mnew0 = fmaxf(mrow0, tmax0);
        const float mnew1 = fmaxf(mrow1, tmax1);
        const float cf0 = __expf(mrow0 - mnew0);
        const float cf1 = __expf(mrow1 - mnew1);
        mrow0 = mnew0; mrow1 = mnew1;

        float psum0 = 0.f, psum1 = 0.f;
        #pragma unroll
        for (int nt = 0; nt < 8; nt++) {
            const float p0 = __expf(sa[nt][0] - mnew0);
            const float p1 = __expf(sa[nt][1] - mnew0);
            const float p2 = __expf(sa[nt][2] - mnew1);
            const float p3 = __expf(sa[nt][3] - mnew1);
            psum0 += p0 + p1;
            psum1 += p2 + p3;
            unsigned h0, l0, h1, l1;
            split2(p0, p1, h0, l0);
            split2(p2, p3, h1, l1);
            PHi[(m0 + r) * PLD2 + nt * 4 + c]     = h0;
            PLo[(m0 + r) * PLD2 + nt * 4 + c]     = l0;
            PHi[(m0 + r + 8) * PLD2 + nt * 4 + c] = h1;
            PLo[(m0 + r + 8) * PLD2 + nt * 4 + c] = l1;
        }
        psum0 += __shfl_xor_sync(0xFFFFFFFFu, psum0, 1);
        psum0 += __shfl_xor_sync(0xFFFFFFFFu, psum0, 2);
        psum1 += __shfl_xor_sync(0xFFFFFFFFu, psum1, 1);
        psum1 += __shfl_xor_sync(0xFFFFFFFFu, psum1, 2);
        lrow0 = lrow0 * cf0 + psum0;
        lrow1 = lrow1 * cf1 + psum1;

        #pragma unroll
        for (int nt = 0; nt < 8; nt++) {
            oacc[nt][0] *= cf0; oacc[nt][1] *= cf0;
            oacc[nt][2] *= cf1; oacc[nt][3] *= cf1;
        }
        __syncwarp();   // P rows are warp-private

        // ---- O += P V (fp16 3-pass split) ----
        #pragma unroll
        for (int s = 0; s < 4; s++) {
            unsigned pah[4], pal[4];
            pah[0] = PHi[(m0 + r) * PLD2 + 8 * s + c];
            pah[1] = PHi[(m0 + r + 8) * PLD2 + 8 * s + c];
            pah[2] = PHi[(m0 + r) * PLD2 + 8 * s + c + 4];
            pah[3] = PHi[(m0 + r + 8) * PLD2 + 8 * s + c + 4];
            pal[0] = PLo[(m0 + r) * PLD2 + 8 * s + c];
            pal[1] = PLo[(m0 + r + 8) * PLD2 + 8 * s + c];
            pal[2] = PLo[(m0 + r) * PLD2 + 8 * s + c + 4];
            pal[3] = PLo[(m0 + r + 8) * PLD2 + 8 * s + c + 4];
            #pragma unroll
            for (int nt = 0; nt < 8; nt++) {
                unsigned vfh[2], vfl[2];
                vfh[0] = VHi[(8 * s + c) * VLD + nt * 8 + r];
                vfh[1] = VHi[(8 * s + c + 4) * VLD + nt * 8 + r];
                vfl[0] = VLo[(8 * s + c) * VLD + nt * 8 + r];
                vfl[1] = VLo[(8 * s + c + 4) * VLD + nt * 8 + r];
                mma_f16(oacc[nt], pah, vfh);
                mma_f16(oacc[nt], pah, vfl);
                mma_f16(oacc[nt], pal, vfh);
            }
        }
    }

    // ---- epilogue ----
    const float li0 = 1.f / lrow0;
    const float li1 = 1.f / lrow1;
    const int b = bh >> 4, h = bh & 15;
    const int row0 = qt * ABQ + m0 + r;
    #pragma unroll
    for (int nt = 0; nt < 8; nt++) {
        const int col = h * DHEAD + nt * 8 + 2 * c;
        float* o0 = g_aout + (size_t)(b * SEQ + row0) * INNER + col;
        float* o1 = g_aout + (size_t)(b * SEQ + row0 + 8) * INNER + col;
        *(float2*)o0 = make_float2(oacc[nt][0] * li0, oacc[nt][1] * li0);
        *(float2*)o1 = make_float2(oacc[nt][2] * li1, oacc[nt][3] * li1);
    }
}

// ---------------- launch ------------------------------------------------------
extern "C" void kernel_launch(void* const* d_in, const int* in_sizes, int n_in,
                              void* d_out, int out_size) {
    const float* x       = (const float*)d_in[0];
    const float* gamma   = (const float*)d_in[1];
    const float* beta    = (const float*)d_in[2];
    const float* null_kv = (const float*)d_in[3];
    const float* Wq      = (const float*)d_in[4];
    const float* Wkv     = (const float*)d_in[5];
    const float* q_scale = (const float*)d_in[6];
    const float* k_scale = (const float*)d_in[7];
    const float* Wo      = (const float*)d_in[8];
    float* out = (float*)d_out;

    cudaFuncSetAttribute(gemm_q_kernel,  cudaFuncAttributeMaxDynamicSharedMemorySize, GEMM_SMEM);
    cudaFuncSetAttribute(gemm_kv_kernel, cudaFuncAttributeMaxDynamicSharedMemorySize, GEMM_SMEM);
    cudaFuncSetAttribute(gemm_o_kernel,  cudaFuncAttributeMaxDynamicSharedMemorySize, GEMM_SMEM);
    cudaFuncSetAttribute(attn_mma_kernel, cudaFuncAttributeMaxDynamicSharedMemorySize, ATT_SMEM);

    ln_kernel<<<TOKENS, 256>>>(x, gamma, beta);
    gemm_q_kernel <<<dim3(INNER / GBN,     TOKENS / GBM), 256, GEMM_SMEM>>>(Wq);
    gemm_kv_kernel<<<dim3(2 * INNER / GBN, TOKENS / GBM), 256, GEMM_SMEM>>>(Wkv);
    qkv_prep<<<(TOKENS * HEADS) / 8, 256>>>(q_scale, k_scale);
    null_prep<<<BATCH * HEADS, 32>>>(null_kv, k_scale);
    attn_mma_kernel<<<dim3(SEQ / ABQ, BATCH * HEADS), 256, ATT_SMEM>>>();
    gemm_o_kernel<<<dim3(DIM / GBN, TOKENS / GBM), 256, GEMM_SMEM>>>(Wo, out);
}

// round 5
// speedup vs baseline: 5.1425x; 1.1308x over previous
#include <cuda_runtime.h>
#include <cuda_fp16.h>
#include <math.h>

#define HEADS   16
#define DHEAD   64
#define BATCH   4
#define SEQ     2048
#define DIM     1024
#define INNER   1024
#define TOKENS  (BATCH*SEQ)       /* 8192 */
#define KVLEN   (SEQ+1)           /* 2049 */
#define SCALE_F 8.0f
#define LN_EPS  1e-5f
#define L2_EPS  1e-12f

// ---------------- scratch (global device arrays; no allocations) -------------
__device__ float g_xn   [TOKENS * DIM];
__device__ float g_qlin [TOKENS * INNER];
__device__ float g_kvlin[TOKENS * 2 * INNER];
__device__ float g_Q    [BATCH * HEADS * SEQ   * DHEAD];
__device__ float g_K    [BATCH * HEADS * KVLEN * DHEAD];
__device__ float g_V    [BATCH * HEADS * KVLEN * DHEAD];
__device__ float g_aout [TOKENS * INNER];

// ---------------- LayerNorm ---------------------------------------------------
__global__ void __launch_bounds__(256) ln_kernel(const float* __restrict__ x,
                                                 const float* __restrict__ gamma,
                                                 const float* __restrict__ beta) {
    __shared__ float red[8][2];
    const int t = blockIdx.x;
    const int i = threadIdx.x;
    const float4 v = ((const float4*)(x + (size_t)t * DIM))[i];
    float s  = v.x + v.y + v.z + v.w;
    float ss = v.x*v.x + v.y*v.y + v.z*v.z + v.w*v.w;
    #pragma unroll
    for (int o = 16; o > 0; o >>= 1) {
        s  += __shfl_xor_sync(0xFFFFFFFFu, s,  o);
        ss += __shfl_xor_sync(0xFFFFFFFFu, ss, o);
    }
    const int w = i >> 5, l = i & 31;
    if (l == 0) { red[w][0] = s; red[w][1] = ss; }
    __syncthreads();
    if (w == 0) {
        s  = (l < 8) ? red[l][0] : 0.f;
        ss = (l < 8) ? red[l][1] : 0.f;
        #pragma unroll
        for (int o = 4; o > 0; o >>= 1) {
            s  += __shfl_xor_sync(0xFFFFFFFFu, s,  o);
            ss += __shfl_xor_sync(0xFFFFFFFFu, ss, o);
        }
        if (l == 0) { red[0][0] = s; red[0][1] = ss; }
    }
    __syncthreads();
    const float mu   = red[0][0] * (1.f / DIM);
    const float var  = red[0][1] * (1.f / DIM) - mu * mu;
    const float rstd = rsqrtf(var + LN_EPS);
    const float4 g  = ((const float4*)gamma)[i];
    const float4 be = ((const float4*)beta)[i];
    float4 o4;
    o4.x = (v.x - mu) * rstd * g.x + be.x;
    o4.y = (v.y - mu) * rstd * g.y + be.y;
    o4.z = (v.z - mu) * rstd * g.z + be.z;
    o4.w = (v.w - mu) * rstd * g.w + be.w;
    ((float4*)(g_xn + (size_t)t * DIM))[i] = o4;
}

// ---------------- TF32 helpers -------------------------------------------------
__device__ __forceinline__ unsigned f2tf(float f) {
    unsigned u;
    asm("cvt.rna.tf32.f32 %0, %1;" : "=r"(u) : "f"(f));
    return u;
}
__device__ __forceinline__ float uif(unsigned u) { return __uint_as_float(u); }

__device__ __forceinline__ void mma_tf32(float* c, const unsigned* a, const unsigned* b) {
    asm volatile(
        "mma.sync.aligned.m16n8k8.row.col.f32.tf32.tf32.f32 "
        "{%0,%1,%2,%3}, {%4,%5,%6,%7}, {%8,%9}, {%0,%1,%2,%3};"
        : "+f"(c[0]), "+f"(c[1]), "+f"(c[2]), "+f"(c[3])
        : "r"(a[0]), "r"(a[1]), "r"(a[2]), "r"(a[3]), "r"(b[0]), "r"(b[1]));
}

// ---------------- fp16 helpers --------------------------------------------------
__device__ __forceinline__ void mma_f16(float* c, const unsigned* a, const unsigned* b) {
    asm volatile(
        "mma.sync.aligned.m16n8k16.row.col.f32.f16.f16.f32 "
        "{%0,%1,%2,%3}, {%4,%5,%6,%7}, {%8,%9}, {%0,%1,%2,%3};"
        : "+f"(c[0]), "+f"(c[1]), "+f"(c[2]), "+f"(c[3])
        : "r"(a[0]), "r"(a[1]), "r"(a[2]), "r"(a[3]), "r"(b[0]), "r"(b[1]));
}

// split a pair of floats into packed-f16 hi and packed-f16 lo (residual)
__device__ __forceinline__ void split2(float a, float b, unsigned& hi, unsigned& lo) {
    __half ha = __float2half_rn(a);
    __half hb = __float2half_rn(b);
    float la = a - __half2float(ha);
    float lb = b - __half2float(hb);
    __half2 h2 = __halves2half2(ha, hb);
    __half2 l2 = __floats2half2_rn(la, lb);
    hi = *(unsigned*)&h2;
    lo = *(unsigned*)&l2;
}
__device__ __forceinline__ unsigned pack2(float a, float b) {
    __half2 h2 = __floats2half2_rn(a, b);
    return *(unsigned*)&h2;
}

// ---------------- TF32 tensor-core GEMM (projections) --------------------------
#define GBM 256
#define GBN 128
#define GBK 16
#define ASTR 20
#define BSTR 132
#define ASTAGE (GBM * ASTR)
#define BSTAGE (GBK * BSTR)
#define GEMM_SMEM ((2 * ASTAGE + 2 * BSTAGE) * 4)

template <int N, int K>
__device__ __forceinline__ void gemm_tf32_body(const float* __restrict__ A,
                                               const float* __restrict__ B,
                                               float* __restrict__ C) {
    extern __shared__ unsigned smem[];
    unsigned* As = smem;
    unsigned* Bs = smem + 2 * ASTAGE;

    const int tid  = threadIdx.x;
    const int warp = tid >> 5;
    const int lane = tid & 31;
    const int r = lane >> 2;
    const int c = lane & 3;
    const int wm = (warp & 3) * 64;
    const int wn = (warp >> 2) * 64;
    const int rowBase = blockIdx.y * GBM;
    const int colBase = blockIdx.x * GBN;

    const int am = tid >> 2;
    const int ak = (tid & 3) << 2;
    const int bk = tid >> 5;
    const int bn = lane << 2;

    const float* Ap = A + (size_t)(rowBase + am) * K + ak;
    const float* Bp = B + colBase + bn;

    float acc[4][8][4];
    #pragma unroll
    for (int mi = 0; mi < 4; mi++)
        #pragma unroll
        for (int ni = 0; ni < 8; ni++)
            #pragma unroll
            for (int j = 0; j < 4; j++) acc[mi][ni][j] = 0.f;

    float4 aR[4], bR[2];
    #pragma unroll
    for (int p = 0; p < 4; p++) aR[p] = *(const float4*)(Ap + (size_t)(p * 64) * K);
    #pragma unroll
    for (int p = 0; p < 2; p++) bR[p] = *(const float4*)(Bp + (size_t)(bk + 8 * p) * N);

    const int NIT = K / GBK;
    #pragma unroll 1
    for (int kt = 0; kt < NIT; kt++) {
        const int cur = kt & 1;
        {
            unsigned* as = As + cur * ASTAGE;
            unsigned* bs = Bs + cur * BSTAGE;
            #pragma unroll
            for (int p = 0; p < 4; p++) {
                uint4 u;
                u.x = f2tf(aR[p].x); u.y = f2tf(aR[p].y);
                u.z = f2tf(aR[p].z); u.w = f2tf(aR[p].w);
                *(uint4*)&as[(am + 64 * p) * ASTR + ak] = u;
            }
            #pragma unroll
            for (int p = 0; p < 2; p++) {
                uint4 u;
                u.x = f2tf(bR[p].x); u.y = f2tf(bR[p].y);
                u.z = f2tf(bR[p].z); u.w = f2tf(bR[p].w);
                *(uint4*)&bs[(bk + 8 * p) * BSTR + bn] = u;
            }
        }
        __syncthreads();

        if (kt + 1 < NIT) {
            const int k0 = (kt + 1) * GBK;
            #pragma unroll
            for (int p = 0; p < 4; p++) aR[p] = *(const float4*)(Ap + (size_t)(p * 64) * K + k0);
            #pragma unroll
            for (int p = 0; p < 2; p++) bR[p] = *(const float4*)(Bp + (size_t)(k0 + bk + 8 * p) * N);
        }

        {
            const unsigned* as = As + cur * ASTAGE;
            const unsigned* bs = Bs + cur * BSTAGE;
            #pragma unroll
            for (int kk = 0; kk < 2; kk++) {
                const int k8 = kk * 8;
                unsigned af[4][4];
                #pragma unroll
                for (int mi = 0; mi < 4; mi++) {
                    const int m0 = wm + mi * 16 + r;
                    af[mi][0] = as[m0 * ASTR + k8 + c];
                    af[mi][1] = as[(m0 + 8) * ASTR + k8 + c];
                    af[mi][2] = as[m0 * ASTR + k8 + c + 4];
                    af[mi][3] = as[(m0 + 8) * ASTR + k8 + c + 4];
                }
                unsigned bf[8][2];
                #pragma unroll
                for (int ni = 0; ni < 8; ni++) {
                    const int n0 = wn + ni * 8 + r;
                    bf[ni][0] = bs[(k8 + c) * BSTR + n0];
                    bf[ni][1] = bs[(k8 + c + 4) * BSTR + n0];
                }
                #pragma unroll
                for (int mi = 0; mi < 4; mi++)
                    #pragma unroll
                    for (int ni = 0; ni < 8; ni++)
                        mma_tf32(acc[mi][ni], af[mi], bf[ni]);
            }
        }
        __syncthreads();
    }

    #pragma unroll
    for (int mi = 0; mi < 4; mi++) {
        const int row = rowBase + wm + mi * 16 + r;
        #pragma unroll
        for (int ni = 0; ni < 8; ni++) {
            const int col = colBase + wn + ni * 8 + 2 * c;
            *(float2*)&C[(size_t)row * N + col]       = make_float2(acc[mi][ni][0], acc[mi][ni][1]);
            *(float2*)&C[(size_t)(row + 8) * N + col] = make_float2(acc[mi][ni][2], acc[mi][ni][3]);
        }
    }
}

__global__ void __launch_bounds__(256, 1) gemm_q_kernel(const float* __restrict__ Wq) {
    gemm_tf32_body<INNER, DIM>(g_xn, Wq, g_qlin);
}
__global__ void __launch_bounds__(256, 1) gemm_kv_kernel(const float* __restrict__ Wkv) {
    gemm_tf32_body<2 * INNER, DIM>(g_xn, Wkv, g_kvlin);
}
__global__ void __launch_bounds__(256, 1) gemm_o_kernel(const float* __restrict__ Wo,
                                                        float* __restrict__ out) {
    gemm_tf32_body<DIM, INNER>(g_aout, Wo, out);
}

// ---------------- head split + l2norm + scales (SCALE folded into Q) ----------
__global__ void __launch_bounds__(256) qkv_prep(const float* __restrict__ q_scale,
                                                const float* __restrict__ k_scale) {
    const int gw   = (blockIdx.x * 256 + threadIdx.x) >> 5;
    const int lane = threadIdx.x & 31;
    if (gw >= TOKENS * HEADS) return;
    const int t = gw >> 4;
    const int h = gw & 15;
    const int b = t >> 11;
    const int i = t & 2047;

    const float* qr = g_qlin + (size_t)t * INNER + h * DHEAD;
    float q0 = qr[lane], q1 = qr[lane + 32];
    float ss = q0 * q0 + q1 * q1;
    #pragma unroll
    for (int o = 16; o > 0; o >>= 1) ss += __shfl_xor_sync(0xFFFFFFFFu, ss, o);
    float inv = 1.f / fmaxf(sqrtf(ss), L2_EPS);
    float* qo = g_Q + ((size_t)(b * HEADS + h) * SEQ + i) * DHEAD;
    qo[lane]      = q0 * inv * q_scale[lane]      * SCALE_F;
    qo[lane + 32] = q1 * inv * q_scale[lane + 32] * SCALE_F;

    const float* kr = g_kvlin + (size_t)t * (2 * INNER) + h * DHEAD;
    float k0 = kr[lane], k1 = kr[lane + 32];
    ss = k0 * k0 + k1 * k1;
    #pragma unroll
    for (int o = 16; o > 0; o >>= 1) ss += __shfl_xor_sync(0xFFFFFFFFu, ss, o);
    inv = 1.f / fmaxf(sqrtf(ss), L2_EPS);
    float* ko = g_K + ((size_t)(b * HEADS + h) * KVLEN + i + 1) * DHEAD;
    ko[lane]      = k0 * inv * k_scale[lane];
    ko[lane + 32] = k1 * inv * k_scale[lane + 32];

    const float* vr = g_kvlin + (size_t)t * (2 * INNER) + INNER + h * DHEAD;
    float* vo = g_V + ((size_t)(b * HEADS + h) * KVLEN + i + 1) * DHEAD;
    vo[lane]      = vr[lane];
    vo[lane + 32] = vr[lane + 32];
}

__global__ void null_prep(const float* __restrict__ null_kv,
                          const float* __restrict__ k_scale) {
    const int bh = blockIdx.x;
    const int h = bh & 15;
    const int lane = threadIdx.x;
    const float* nk = null_kv + h * DHEAD;
    const float* nv = null_kv + HEADS * DHEAD + h * DHEAD;
    float k0 = nk[lane], k1 = nk[lane + 32];
    float ss = k0 * k0 + k1 * k1;
    #pragma unroll
    for (int o = 16; o > 0; o >>= 1) ss += __shfl_xor_sync(0xFFFFFFFFu, ss, o);
    const float inv = 1.f / fmaxf(sqrtf(ss), L2_EPS);
    float* ko = g_K + (size_t)bh * KVLEN * DHEAD;
    ko[lane]      = k0 * inv * k_scale[lane];
    ko[lane + 32] = k1 * inv * k_scale[lane + 32];
    float* vo = g_V + (size_t)bh * KVLEN * DHEAD;
    vo[lane]      = nv[lane];
    vo[lane + 32] = nv[lane + 32];
}

// ---------------- flash attention, fp16 2-pass split on tensor cores ----------
// S  = qh*kh + ql*kh    (K rounded to fp16; dropped term ~2^-12 of logit)
// O += ph*vh + pl*vh    (V rounded to fp16; dropped term ~2^-12 relative)
#define ABQ 128
#define ABK 64
#define ANT ((KVLEN + ABK - 1) / ABK)   /* 33 */
#define KTLD 72   /* KtH row length */
#define VLD  72   /* VH  row length */
#define PLD2 36   /* P   row length (words, 32 used) */

#define ATT_SMEM ((32*KTLD + 32*VLD + 2*ABQ*PLD2) * 4)   /* 55296 B */

__global__ void __launch_bounds__(256, 2) attn_mma_kernel() {
    extern __shared__ unsigned ash[];
    unsigned* KtH = ash;                      // [dd=32][KTLD]  d-pairs, transposed
    unsigned* VH  = KtH + 32 * KTLD;          // [jj=32][VLD]   j-pairs
    unsigned* PHi = VH  + 32 * VLD;           // [row=128][PLD2]
    unsigned* PLo = PHi + ABQ * PLD2;

    const int tid  = threadIdx.x;
    const int warp = tid >> 5;
    const int lane = tid & 31;
    const int r = lane >> 2;
    const int c = lane & 3;
    const int bh = blockIdx.y;
    const int qt = blockIdx.x;
    const int m0 = warp * 16;

    // ---- Q fragments (register resident, fp16 hi/lo split) ----
    const float* Qg = g_Q + ((size_t)bh * SEQ + (size_t)qt * ABQ + m0) * DHEAD;
    unsigned qhi[4][4], qlo[4][4];
    #pragma unroll
    for (int s = 0; s < 4; s++) {
        float2 x0 = *(const float2*)(Qg + (size_t)r * DHEAD + s * 16 + 2 * c);
        float2 x1 = *(const float2*)(Qg + (size_t)(r + 8) * DHEAD + s * 16 + 2 * c);
        float2 x2 = *(const float2*)(Qg + (size_t)r * DHEAD + s * 16 + 2 * c + 8);
        float2 x3 = *(const float2*)(Qg + (size_t)(r + 8) * DHEAD + s * 16 + 2 * c + 8);
        split2(x0.x, x0.y, qhi[s][0], qlo[s][0]);
        split2(x1.x, x1.y, qhi[s][1], qlo[s][1]);
        split2(x2.x, x2.y, qhi[s][2], qlo[s][2]);
        split2(x3.x, x3.y, qhi[s][3], qlo[s][3]);
    }

    float oacc[8][4];
    #pragma unroll
    for (int nt = 0; nt < 8; nt++)
        #pragma unroll
        for (int j = 0; j < 4; j++) oacc[nt][j] = 0.f;
    float mrow0 = -1e30f, mrow1 = -1e30f, lrow0 = 0.f, lrow1 = 0.f;

    const float* Kg = g_K + (size_t)bh * KVLEN * DHEAD;
    const float* Vg = g_V + (size_t)bh * KVLEN * DHEAD;

    for (int kt = 0; kt < ANT; kt++) {
        const int kvbase = kt * ABK;
        __syncthreads();

        // ---- fill KtH: packed d-pairs, transposed [dd][j] ----
        {
            const int j  = tid & 63;
            const int d0 = (tid >> 6) << 4;          // 0,16,32,48
            const bool ok = (kvbase + j) < KVLEN;
            const float* kp = Kg + (size_t)(kvbase + j) * DHEAD + d0;
            #pragma unroll
            for (int u = 0; u < 4; u++) {
                float4 v = ok ? *(const float4*)(kp + u * 4) : make_float4(0.f, 0.f, 0.f, 0.f);
                const int dd = (d0 >> 1) + u * 2;
                KtH[dd * KTLD + j]       = pack2(v.x, v.y);
                KtH[(dd + 1) * KTLD + j] = pack2(v.z, v.w);
            }
        }
        // ---- fill VH: packed j-pairs [jj][d] ----
        {
            const int jj = tid >> 3;                 // 0..31
            const int d0 = (tid & 7) << 3;           // 0..56
            const int j0 = kvbase + 2 * jj;
            const bool ok0 = j0 < KVLEN;
            const bool ok1 = (j0 + 1) < KVLEN;
            const float* v0p = Vg + (size_t)j0 * DHEAD + d0;
            const float* v1p = Vg + (size_t)(j0 + 1) * DHEAD + d0;
            float4 a0 = ok0 ? *(const float4*)v0p       : make_float4(0.f, 0.f, 0.f, 0.f);
            float4 a1 = ok0 ? *(const float4*)(v0p + 4) : make_float4(0.f, 0.f, 0.f, 0.f);
            float4 b0 = ok1 ? *(const float4*)v1p       : make_float4(0.f, 0.f, 0.f, 0.f);
            float4 b1 = ok1 ? *(const float4*)(v1p + 4) : make_float4(0.f, 0.f, 0.f, 0.f);
            const float fa[8] = {a0.x, a0.y, a0.z, a0.w, a1.x, a1.y, a1.z, a1.w};
            const float fb[8] = {b0.x, b0.y, b0.z, b0.w, b1.x, b1.y, b1.z, b1.w};
            #pragma unroll
            for (int i = 0; i < 8; i++)
                VH[jj * VLD + d0 + i] = pack2(fa[i], fb[i]);
        }
        __syncthreads();

        // ---- S = Q K^T (fp16 2-pass: qh*kh + ql*kh) ----
        float sa[8][4];
        #pragma unroll
        for (int nt = 0; nt < 8; nt++)
            #pragma unroll
            for (int j = 0; j < 4; j++) sa[nt][j] = 0.f;

        #pragma unroll
        for (int s = 0; s < 4; s++) {
            #pragma unroll
            for (int nt = 0; nt < 8; nt++) {
                unsigned bfh[2];
                bfh[0] = KtH[(8 * s + c) * KTLD + nt * 8 + r];
                bfh[1] = KtH[(8 * s + c + 4) * KTLD + nt * 8 + r];
                mma_f16(sa[nt], qhi[s], bfh);
                mma_f16(sa[nt], qlo[s], bfh);
            }
        }

        // ---- mask + online softmax ----
        float tmax0 = -1e30f, tmax1 = -1e30f;
        #pragma unroll
        for (int nt = 0; nt < 8; nt++) {
            const int j0 = kvbase + nt * 8 + 2 * c;
            if (j0 >= KVLEN)     { sa[nt][0] = -1e30f; sa[nt][2] = -1e30f; }
            if (j0 + 1 >= KVLEN) { sa[nt][1] = -1e30f; sa[nt][3] = -1e30f; }
            tmax0 = fmaxf(tmax0, fmaxf(sa[nt][0], sa[nt][1]));
            tmax1 = fmaxf(tmax1, fmaxf(sa[nt][2], sa[nt][3]));
        }
        tmax0 = fmaxf(tmax0, __shfl_xor_sync(0xFFFFFFFFu, tmax0, 1));
        tmax0 = fmaxf(tmax0, __shfl_xor_sync(0xFFFFFFFFu, tmax0, 2));
        tmax1 = fmaxf(tmax1, __shfl_xor_sync(0xFFFFFFFFu, tmax1, 1));
        tmax1 = fmaxf(tmax1, __shfl_xor_sync(0xFFFFFFFFu, tmax1, 2));

        const float mnew0 = fmaxf(mrow0, tmax0);
        const float mnew1 = fmaxf(mrow1, tmax1);
        const float cf0 = __expf(mrow0 - mnew0);
        const float cf1 = __expf(mrow1 - mnew1);
        mrow0 = mnew0; mrow1 = mnew1;

        float psum0 = 0.f, psum1 = 0.f;
        #pragma unroll
        for (int nt = 0; nt < 8; nt++) {
            const float p0 = __expf(sa[nt][0] - mnew0);
            const float p1 = __expf(sa[nt][1] - mnew0);
            const float p2 = __expf(sa[nt][2] - mnew1);
            const float p3 = __expf(sa[nt][3] - mnew1);
            psum0 += p0 + p1;
            psum1 += p2 + p3;
            unsigned h0, l0, h1, l1;
            split2(p0, p1, h0, l0);
            split2(p2, p3, h1, l1);
            PHi[(m0 + r) * PLD2 + nt * 4 + c]     = h0;
            PLo[(m0 + r) * PLD2 + nt * 4 + c]     = l0;
            PHi[(m0 + r + 8) * PLD2 + nt * 4 + c] = h1;
            PLo[(m0 + r + 8) * PLD2 + nt * 4 + c] = l1;
        }
        psum0 += __shfl_xor_sync(0xFFFFFFFFu, psum0, 1);
        psum0 += __shfl_xor_sync(0xFFFFFFFFu, psum0, 2);
        psum1 += __shfl_xor_sync(0xFFFFFFFFu, psum1, 1);
        psum1 += __shfl_xor_sync(0xFFFFFFFFu, psum1, 2);
        lrow0 = lrow0 * cf0 + psum0;
        lrow1 = lrow1 * cf1 + psum1;

        #pragma unroll
        for (int nt = 0; nt < 8; nt++) {
            oacc[nt][0] *= cf0; oacc[nt][1] *= cf0;
            oacc[nt][2] *= cf1; oacc[nt][3] *= cf1;
        }
        __syncwarp();   // P rows are warp-private

        // ---- O += P V (fp16 2-pass: ph*vh + pl*vh) ----
        #pragma unroll
        for (int s = 0; s < 4; s++) {
            unsigned pah[4], pal[4];
            pah[0] = PHi[(m0 + r) * PLD2 + 8 * s + c];
            pah[1] = PHi[(m0 + r + 8) * PLD2 + 8 * s + c];
            pah[2] = PHi[(m0 + r) * PLD2 + 8 * s + c + 4];
            pah[3] = PHi[(m0 + r + 8) * PLD2 + 8 * s + c + 4];
            pal[0] = PLo[(m0 + r) * PLD2 + 8 * s + c];
            pal[1] = PLo[(m0 + r + 8) * PLD2 + 8 * s + c];
            pal[2] = PLo[(m0 + r) * PLD2 + 8 * s + c + 4];
            pal[3] = PLo[(m0 + r + 8) * PLD2 + 8 * s + c + 4];
            #pragma unroll
            for (int nt = 0; nt < 8; nt++) {
                unsigned vfh[2];
                vfh[0] = VH[(8 * s + c) * VLD + nt * 8 + r];
                vfh[1] = VH[(8 * s + c + 4) * VLD + nt * 8 + r];
                mma_f16(oacc[nt], pah, vfh);
                mma_f16(oacc[nt], pal, vfh);
            }
        }
    }

    // ---- epilogue ----
    const float li0 = 1.f / lrow0;
    const float li1 = 1.f / lrow1;
    const int b = bh >> 4, h = bh & 15;
    const int row0 = qt * ABQ + m0 + r;
    #pragma unroll
    for (int nt = 0; nt < 8; nt++) {
        const int col = h * DHEAD + nt * 8 + 2 * c;
        float* o0 = g_aout + (size_t)(b * SEQ + row0) * INNER + col;
        float* o1 = g_aout + (size_t)(b * SEQ + row0 + 8) * INNER + col;
        *(float2*)o0 = make_float2(oacc[nt][0] * li0, oacc[nt][1] * li0);
        *(float2*)o1 = make_float2(oacc[nt][2] * li1, oacc[nt][3] * li1);
    }
}

// ---------------- launch ------------------------------------------------------
extern "C" void kernel_launch(void* const* d_in, const int* in_sizes, int n_in,
                              void* d_out, int out_size) {
    const float* x       = (const float*)d_in[0];
    const float* gamma   = (const float*)d_in[1];
    const float* beta    = (const float*)d_in[2];
    const float* null_kv = (const float*)d_in[3];
    const float* Wq      = (const float*)d_in[4];
    const float* Wkv     = (const float*)d_in[5];
    const float* q_scale = (const float*)d_in[6];
    const float* k_scale = (const float*)d_in[7];
    const float* Wo      = (const float*)d_in[8];
    float* out = (float*)d_out;

    cudaFuncSetAttribute(gemm_q_kernel,  cudaFuncAttributeMaxDynamicSharedMemorySize, GEMM_SMEM);
    cudaFuncSetAttribute(gemm_kv_kernel, cudaFuncAttributeMaxDynamicSharedMemorySize, GEMM_SMEM);
    cudaFuncSetAttribute(gemm_o_kernel,  cudaFuncAttributeMaxDynamicSharedMemorySize, GEMM_SMEM);
    cudaFuncSetAttribute(attn_mma_kernel, cudaFuncAttributeMaxDynamicSharedMemorySize, ATT_SMEM);

    ln_kernel<<<TOKENS, 256>>>(x, gamma, beta);
    gemm_q_kernel <<<dim3(INNER / GBN,     TOKENS / GBM), 256, GEMM_SMEM>>>(Wq);
    gemm_kv_kernel<<<dim3(2 * INNER / GBN, TOKENS / GBM), 256, GEMM_SMEM>>>(Wkv);
    qkv_prep<<<(TOKENS * HEADS) / 8, 256>>>(q_scale, k_scale);
    null_prep<<<BATCH * HEADS, 32>>>(null_kv, k_scale);
    attn_mma_kernel<<<dim3(SEQ / ABQ, BATCH * HEADS), 256, ATT_SMEM>>>();
    gemm_o_kernel<<<dim3(DIM / GBN, TOKENS / GBM), 256, GEMM_SMEM>>>(Wo, out);
}

// round 7
// speedup vs baseline: 5.3389x; 1.0382x over previous
#include <cuda_runtime.h>
#include <cuda_fp16.h>
#include <math.h>

#define HEADS   16
#define DHEAD   64
#define BATCH   4
#define SEQ     2048
#define DIM     1024
#define INNER   1024
#define TOKENS  (BATCH*SEQ)       /* 8192 */
#define KVLEN   (SEQ+1)           /* 2049 */
#define SCALE_F 8.0f
#define LN_EPS  1e-5f
#define L2_EPS  1e-12f

// ---------------- scratch (global device arrays; no allocations) -------------
__device__ float g_xn   [TOKENS * DIM];
__device__ float g_qlin [TOKENS * INNER];
__device__ float g_kvlin[TOKENS * 2 * INNER];
__device__ float g_Q    [BATCH * HEADS * SEQ   * DHEAD];
__device__ float g_K    [BATCH * HEADS * KVLEN * DHEAD];
__device__ float g_V    [BATCH * HEADS * KVLEN * DHEAD];
__device__ float g_aout [TOKENS * INNER];

// ---------------- LayerNorm ---------------------------------------------------
__global__ void __launch_bounds__(256) ln_kernel(const float* __restrict__ x,
                                                 const float* __restrict__ gamma,
                                                 const float* __restrict__ beta) {
    __shared__ float red[8][2];
    const int t = blockIdx.x;
    const int i = threadIdx.x;
    const float4 v = ((const float4*)(x + (size_t)t * DIM))[i];
    float s  = v.x + v.y + v.z + v.w;
    float ss = v.x*v.x + v.y*v.y + v.z*v.z + v.w*v.w;
    #pragma unroll
    for (int o = 16; o > 0; o >>= 1) {
        s  += __shfl_xor_sync(0xFFFFFFFFu, s,  o);
        ss += __shfl_xor_sync(0xFFFFFFFFu, ss, o);
    }
    const int w = i >> 5, l = i & 31;
    if (l == 0) { red[w][0] = s; red[w][1] = ss; }
    __syncthreads();
    if (w == 0) {
        s  = (l < 8) ? red[l][0] : 0.f;
        ss = (l < 8) ? red[l][1] : 0.f;
        #pragma unroll
        for (int o = 4; o > 0; o >>= 1) {
            s  += __shfl_xor_sync(0xFFFFFFFFu, s,  o);
            ss += __shfl_xor_sync(0xFFFFFFFFu, ss, o);
        }
        if (l == 0) { red[0][0] = s; red[0][1] = ss; }
    }
    __syncthreads();
    const float mu   = red[0][0] * (1.f / DIM);
    const float var  = red[0][1] * (1.f / DIM) - mu * mu;
    const float rstd = rsqrtf(var + LN_EPS);
    const float4 g  = ((const float4*)gamma)[i];
    const float4 be = ((const float4*)beta)[i];
    float4 o4;
    o4.x = (v.x - mu) * rstd * g.x + be.x;
    o4.y = (v.y - mu) * rstd * g.y + be.y;
    o4.z = (v.z - mu) * rstd * g.z + be.z;
    o4.w = (v.w - mu) * rstd * g.w + be.w;
    ((float4*)(g_xn + (size_t)t * DIM))[i] = o4;
}

// ---------------- fp16 helpers --------------------------------------------------
__device__ __forceinline__ void mma_f16(float* c, const unsigned* a, const unsigned* b) {
    asm volatile(
        "mma.sync.aligned.m16n8k16.row.col.f32.f16.f16.f32 "
        "{%0,%1,%2,%3}, {%4,%5,%6,%7}, {%8,%9}, {%0,%1,%2,%3};"
        : "+f"(c[0]), "+f"(c[1]), "+f"(c[2]), "+f"(c[3])
        : "r"(a[0]), "r"(a[1]), "r"(a[2]), "r"(a[3]), "r"(b[0]), "r"(b[1]));
}

__device__ __forceinline__ void split2(float a, float b, unsigned& hi, unsigned& lo) {
    __half ha = __float2half_rn(a);
    __half hb = __float2half_rn(b);
    float la = a - __half2float(ha);
    float lb = b - __half2float(hb);
    __half2 h2 = __halves2half2(ha, hb);
    __half2 l2 = __floats2half2_rn(la, lb);
    hi = *(unsigned*)&h2;
    lo = *(unsigned*)&l2;
}
__device__ __forceinline__ unsigned pack2(float a, float b) {
    __half2 h2 = __floats2half2_rn(a, b);
    return *(unsigned*)&h2;
}

// ---------------- fp16 2-pass tensor-core GEMM (projections) -------------------
// C[M,N] = A[M,K] @ B[K,N]. A = hi + lo (exact fp16 split), B rounded fp16.
// C = Ahi*B + Alo*B. Block 128x128, K-chunk 32, 8 warps (4m x 2n), warp 32x64.
#define ASLD 20     /* A row stride (words of f16x2 over k), 16 used */
#define BSLD 136    /* B row stride (words over n), 128 used */
#define GSTAGE_W (2 * 128 * ASLD + 16 * BSLD)          /* words per stage: 7296 */
#define GEMM_SMEM (2 * GSTAGE_W * 4)                   /* 58368 B */

template <int N, int K>
__device__ __forceinline__ void gemm_f16_body(const float* __restrict__ A,
                                              const float* __restrict__ B,
                                              float* __restrict__ C) {
    extern __shared__ unsigned gsm[];

    const int tid  = threadIdx.x;
    const int warp = tid >> 5;
    const int lane = tid & 31;
    const int r = lane >> 2;
    const int c = lane & 3;
    const int wm = (warp & 3) * 32;
    const int wn = (warp >> 2) * 64;
    const int rowBase = blockIdx.y * 128;
    const int colBase = blockIdx.x * 128;

    // fill mappings
    const int arow = tid >> 1;            // 0..127
    const int ah0  = (tid & 1) * 16;      // k offset 0/16
    const int bkp  = tid >> 4;            // 0..15  (k-pair row)
    const int bn0  = (tid & 15) * 8;      // 0..120

    const float* ApG = A + (size_t)(rowBase + arow) * K + ah0;
    const float* BpG = B + colBase + bn0;

    float acc[2][8][4];
    #pragma unroll
    for (int mi = 0; mi < 2; mi++)
        #pragma unroll
        for (int ni = 0; ni < 8; ni++)
            #pragma unroll
            for (int j = 0; j < 4; j++) acc[mi][ni][j] = 0.f;

    const int NC = K / 32;

    auto fill = [&](int ck) {
        unsigned* st  = gsm + (ck & 1) * GSTAGE_W;
        unsigned* AsH = st;
        unsigned* AsL = st + 128 * ASLD;
        unsigned* Bs  = st + 2 * 128 * ASLD;
        const int k0 = ck * 32;
        // A tile: hi + lo, [row][kpair]
        #pragma unroll
        for (int i = 0; i < 4; i++) {
            float4 v = *(const float4*)(ApG + k0 + 4 * i);
            unsigned h0, l0, h1, l1;
            split2(v.x, v.y, h0, l0);
            split2(v.z, v.w, h1, l1);
            const int kp = (ah0 >> 1) + 2 * i;
            *(uint2*)&AsH[arow * ASLD + kp] = make_uint2(h0, h1);
            *(uint2*)&AsL[arow * ASLD + kp] = make_uint2(l0, l1);
        }
        // B tile: [kpair][n], pack over k
        {
            const float* b0 = BpG + (size_t)(k0 + 2 * bkp) * N;
            const float* b1 = b0 + N;
            float4 x0 = *(const float4*)b0;
            float4 x1 = *(const float4*)(b0 + 4);
            float4 y0 = *(const float4*)b1;
            float4 y1 = *(const float4*)(b1 + 4);
            unsigned* bw = &Bs[bkp * BSLD + bn0];
            bw[0] = pack2(x0.x, y0.x); bw[1] = pack2(x0.y, y0.y);
            bw[2] = pack2(x0.z, y0.z); bw[3] = pack2(x0.w, y0.w);
            bw[4] = pack2(x1.x, y1.x); bw[5] = pack2(x1.y, y1.y);
            bw[6] = pack2(x1.z, y1.z); bw[7] = pack2(x1.w, y1.w);
        }
    };

    fill(0);
    __syncthreads();

    #pragma unroll 1
    for (int ck = 0; ck < NC; ck++) {
        if (ck + 1 < NC) fill(ck + 1);   // writes other stage; overlaps compute

        const unsigned* st  = gsm + (ck & 1) * GSTAGE_W;
        const unsigned* AsH = st;
        const unsigned* AsL = st + 128 * ASLD;
        const unsigned* Bs  = st + 2 * 128 * ASLD;

        #pragma unroll
        for (int s = 0; s < 2; s++) {
            unsigned ah[2][4], al[2][4];
            #pragma unroll
            for (int mi = 0; mi < 2; mi++) {
                const int row = wm + mi * 16;
                ah[mi][0] = AsH[(row + r) * ASLD + 8 * s + c];
                ah[mi][1] = AsH[(row + 8 + r) * ASLD + 8 * s + c];
                ah[mi][2] = AsH[(row + r) * ASLD + 8 * s + c + 4];
                ah[mi][3] = AsH[(row + 8 + r) * ASLD + 8 * s + c + 4];
                al[mi][0] = AsL[(row + r) * ASLD + 8 * s + c];
                al[mi][1] = AsL[(row + 8 + r) * ASLD + 8 * s + c];
                al[mi][2] = AsL[(row + r) * ASLD + 8 * s + c + 4];
                al[mi][3] = AsL[(row + 8 + r) * ASLD + 8 * s + c + 4];
            }
            #pragma unroll
            for (int ni = 0; ni < 8; ni++) {
                unsigned bf[2];
                bf[0] = Bs[(8 * s + c) * BSLD + wn + ni * 8 + r];
                bf[1] = Bs[(8 * s + c + 4) * BSLD + wn + ni * 8 + r];
                #pragma unroll
                for (int mi = 0; mi < 2; mi++) {
                    mma_f16(acc[mi][ni], ah[mi], bf);
                    mma_f16(acc[mi][ni], al[mi], bf);
                }
            }
        }
        __syncthreads();
    }

    #pragma unroll
    for (int mi = 0; mi < 2; mi++) {
        const int row = rowBase + wm + mi * 16 + r;
        #pragma unroll
        for (int ni = 0; ni < 8; ni++) {
            const int col = colBase + wn + ni * 8 + 2 * c;
            *(float2*)&C[(size_t)row * N + col]       = make_float2(acc[mi][ni][0], acc[mi][ni][1]);
            *(float2*)&C[(size_t)(row + 8) * N + col] = make_float2(acc[mi][ni][2], acc[mi][ni][3]);
        }
    }
}

__global__ void __launch_bounds__(256, 2) gemm_q_kernel(const float* __restrict__ Wq) {
    gemm_f16_body<INNER, DIM>(g_xn, Wq, g_qlin);
}
__global__ void __launch_bounds__(256, 2) gemm_kv_kernel(const float* __restrict__ Wkv) {
    gemm_f16_body<2 * INNER, DIM>(g_xn, Wkv, g_kvlin);
}
__global__ void __launch_bounds__(256, 2) gemm_o_kernel(const float* __restrict__ Wo,
                                                        float* __restrict__ out) {
    gemm_f16_body<DIM, INNER>(g_aout, Wo, out);
}

// ---------------- head split + l2norm + scales (SCALE folded into Q) ----------
__global__ void __launch_bounds__(256) qkv_prep(const float* __restrict__ q_scale,
                                                const float* __restrict__ k_scale) {
    const int gw   = (blockIdx.x * 256 + threadIdx.x) >> 5;
    const int lane = threadIdx.x & 31;
    if (gw >= TOKENS * HEADS) return;
    const int t = gw >> 4;
    const int h = gw & 15;
    const int b = t >> 11;
    const int i = t & 2047;

    const float* qr = g_qlin + (size_t)t * INNER + h * DHEAD;
    float q0 = qr[lane], q1 = qr[lane + 32];
    float ss = q0 * q0 + q1 * q1;
    #pragma unroll
    for (int o = 16; o > 0; o >>= 1) ss += __shfl_xor_sync(0xFFFFFFFFu, ss, o);
    float inv = 1.f / fmaxf(sqrtf(ss), L2_EPS);
    float* qo = g_Q + ((size_t)(b * HEADS + h) * SEQ + i) * DHEAD;
    qo[lane]      = q0 * inv * q_scale[lane]      * SCALE_F;
    qo[lane + 32] = q1 * inv * q_scale[lane + 32] * SCALE_F;

    const float* kr = g_kvlin + (size_t)t * (2 * INNER) + h * DHEAD;
    float k0 = kr[lane], k1 = kr[lane + 32];
    ss = k0 * k0 + k1 * k1;
    #pragma unroll
    for (int o = 16; o > 0; o >>= 1) ss += __shfl_xor_sync(0xFFFFFFFFu, ss, o);
    inv = 1.f / fmaxf(sqrtf(ss), L2_EPS);
    float* ko = g_K + ((size_t)(b * HEADS + h) * KVLEN + i + 1) * DHEAD;
    ko[lane]      = k0 * inv * k_scale[lane];
    ko[lane + 32] = k1 * inv * k_scale[lane + 32];

    const float* vr = g_kvlin + (size_t)t * (2 * INNER) + INNER + h * DHEAD;
    float* vo = g_V + ((size_t)(b * HEADS + h) * KVLEN + i + 1) * DHEAD;
    vo[lane]      = vr[lane];
    vo[lane + 32] = vr[lane + 32];
}

__global__ void null_prep(const float* __restrict__ null_kv,
                          const float* __restrict__ k_scale) {
    const int bh = blockIdx.x;
    const int h = bh & 15;
    const int lane = threadIdx.x;
    const float* nk = null_kv + h * DHEAD;
    const float* nv = null_kv + HEADS * DHEAD + h * DHEAD;
    float k0 = nk[lane], k1 = nk[lane + 32];
    float ss = k0 * k0 + k1 * k1;
    #pragma unroll
    for (int o = 16; o > 0; o >>= 1) ss += __shfl_xor_sync(0xFFFFFFFFu, ss, o);
    const float inv = 1.f / fmaxf(sqrtf(ss), L2_EPS);
    float* ko = g_K + (size_t)bh * KVLEN * DHEAD;
    ko[lane]      = k0 * inv * k_scale[lane];
    ko[lane + 32] = k1 * inv * k_scale[lane + 32];
    float* vo = g_V + (size_t)bh * KVLEN * DHEAD;
    vo[lane]      = nv[lane];
    vo[lane + 32] = nv[lane + 32];
}

// ---------------- flash attention, fp16 2-pass split on tensor cores ----------
#define ABQ 128
#define ABK 64
#define ANT ((KVLEN + ABK - 1) / ABK)   /* 33 */
#define KTLD 72
#define VLD  72
#define PLD2 36

#define ATT_SMEM ((32*KTLD + 32*VLD + 2*ABQ*PLD2) * 4)   /* 55296 B */

__global__ void __launch_bounds__(256, 2) attn_mma_kernel() {
    extern __shared__ unsigned ash[];
    unsigned* KtH = ash;
    unsigned* VH  = KtH + 32 * KTLD;
    unsigned* PHi = VH  + 32 * VLD;
    unsigned* PLo = PHi + ABQ * PLD2;

    const int tid  = threadIdx.x;
    const int warp = tid >> 5;
    const int lane = tid & 31;
    const int r = lane >> 2;
    const int c = lane & 3;
    const int bh = blockIdx.y;
    const int qt = blockIdx.x;
    const int m0 = warp * 16;

    const float* Qg = g_Q + ((size_t)bh * SEQ + (size_t)qt * ABQ + m0) * DHEAD;
    unsigned qhi[4][4], qlo[4][4];
    #pragma unroll
    for (int s = 0; s < 4; s++) {
        float2 x0 = *(const float2*)(Qg + (size_t)r * DHEAD + s * 16 + 2 * c);
        float2 x1 = *(const float2*)(Qg + (size_t)(r + 8) * DHEAD + s * 16 + 2 * c);
        float2 x2 = *(const float2*)(Qg + (size_t)r * DHEAD + s * 16 + 2 * c + 8);
        float2 x3 = *(const float2*)(Qg + (size_t)(r + 8) * DHEAD + s * 16 + 2 * c + 8);
        split2(x0.x, x0.y, qhi[s][0], qlo[s][0]);
        split2(x1.x, x1.y, qhi[s][1], qlo[s][1]);
        split2(x2.x, x2.y, qhi[s][2], qlo[s][2]);
        split2(x3.x, x3.y, qhi[s][3], qlo[s][3]);
    }

    float oacc[8][4];
    #pragma unroll
    for (int nt = 0; nt < 8; nt++)
        #pragma unroll
        for (int j = 0; j < 4; j++) oacc[nt][j] = 0.f;
    float mrow0 = -1e30f, mrow1 = -1e30f, lrow0 = 0.f, lrow1 = 0.f;

    const float* Kg = g_K + (size_t)bh * KVLEN * DHEAD;
    const float* Vg = g_V + (size_t)bh * KVLEN * DHEAD;

    for (int kt = 0; kt < ANT; kt++) {
        const int kvbase = kt * ABK;
        __syncthreads();

        {
            const int j  = tid & 63;
            const int d0 = (tid >> 6) << 4;
            const bool ok = (kvbase + j) < KVLEN;
            const float* kp = Kg + (size_t)(kvbase + j) * DHEAD + d0;
            #pragma unroll
            for (int u = 0; u < 4; u++) {
                float4 v = ok ? *(const float4*)(kp + u * 4) : make_float4(0.f, 0.f, 0.f, 0.f);
                const int dd = (d0 >> 1) + u * 2;
                KtH[dd * KTLD + j]       = pack2(v.x, v.y);
                KtH[(dd + 1) * KTLD + j] = pack2(v.z, v.w);
            }
        }
        {
            const int jj = tid >> 3;
            const int d0 = (tid & 7) << 3;
            const int j0 = kvbase + 2 * jj;
            const bool ok0 = j0 < KVLEN;
            const bool ok1 = (j0 + 1) < KVLEN;
            const float* v0p = Vg + (size_t)j0 * DHEAD + d0;
            const float* v1p = Vg + (size_t)(j0 + 1) * DHEAD + d0;
            float4 a0 = ok0 ? *(const float4*)v0p       : make_float4(0.f, 0.f, 0.f, 0.f);
            float4 a1 = ok0 ? *(const float4*)(v0p + 4) : make_float4(0.f, 0.f, 0.f, 0.f);
            float4 b0 = ok1 ? *(const float4*)v1p       : make_float4(0.f, 0.f, 0.f, 0.f);
            float4 b1 = ok1 ? *(const float4*)(v1p + 4) : make_float4(0.f, 0.f, 0.f, 0.f);
            const float fa[8] = {a0.x, a0.y, a0.z, a0.w, a1.x, a1.y, a1.z, a1.w};
            const float fb[8] = {b0.x, b0.y, b0.z, b0.w, b1.x, b1.y, b1.z, b1.w};
            #pragma unroll
            for (int i = 0; i < 8; i++)
                VH[jj * VLD + d0 + i] = pack2(fa[i], fb[i]);
        }
        __syncthreads();

        float sa[8][4];
        #pragma unroll
        for (int nt = 0; nt < 8; nt++)
            #pragma unroll
            for (int j = 0; j < 4; j++) sa[nt][j] = 0.f;

        #pragma unroll
        for (int s = 0; s < 4; s++) {
            #pragma unroll
            for (int nt = 0; nt < 8; nt++) {
                unsigned bfh[2];
                bfh[0] = KtH[(8 * s + c) * KTLD + nt * 8 + r];
                bfh[1] = KtH[(8 * s + c + 4) * KTLD + nt * 8 + r];
                mma_f16(sa[nt], qhi[s], bfh);
                mma_f16(sa[nt], qlo[s], bfh);
            }
        }

        float tmax0 = -1e30f, tmax1 = -1e30f;
        #pragma unroll
        for (int nt = 0; nt < 8; nt++) {
            const int j0 = kvbase + nt * 8 + 2 * c;
            if (j0 >= KVLEN)     { sa[nt][0] = -1e30f; sa[nt][2] = -1e30f; }
            if (j0 + 1 >= KVLEN) { sa[nt][1] = -1e30f; sa[nt][3] = -1e30f; }
            tmax0 = fmaxf(tmax0, fmaxf(sa[nt][0], sa[nt][1]));
            tmax1 = fmaxf(tmax1, fmaxf(sa[nt][2], sa[nt][3]));
        }
        tmax0 = fmaxf(tmax0, __shfl_xor_sync(0xFFFFFFFFu, tmax0, 1));
        tmax0 = fmaxf(tmax0, __shfl_xor_sync(0xFFFFFFFFu, tmax0, 2));
        tmax1 = fmaxf(tmax1, __shfl_xor_sync(0xFFFFFFFFu, tmax1, 1));
        tmax1 = fmaxf(tmax1, __shfl_xor_sync(0xFFFFFFFFu, tmax1, 2));

        const float mnew0 = fmaxf(mrow0, tmax0);
        const float mnew1 = fmaxf(mrow1, tmax1);
        const float cf0 = __expf(mrow0 - mnew0);
        const float cf1 = __expf(mrow1 - mnew1);
        mrow0 = mnew0; mrow1 = mnew1;

        float psum0 = 0.f, psum1 = 0.f;
        #pragma unroll
        for (int nt = 0; nt < 8; nt++) {
            const float p0 = __expf(sa[nt][0] - mnew0);
            const float p1 = __expf(sa[nt][1] - mnew0);
            const float p2 = __expf(sa[nt][2] - mnew1);
            const float p3 = __expf(sa[nt][3] - mnew1);
            psum0 += p0 + p1;
            psum1 += p2 + p3;
            unsigned h0, l0, h1, l1;
            split2(p0, p1, h0, l0);
            split2(p2, p3, h1, l1);
            PHi[(m0 + r) * PLD2 + nt * 4 + c]     = h0;
            PLo[(m0 + r) * PLD2 + nt * 4 + c]     = l0;
            PHi[(m0 + r + 8) * PLD2 + nt * 4 + c] = h1;
            PLo[(m0 + r + 8) * PLD2 + nt * 4 + c] = l1;
        }
        psum0 += __shfl_xor_sync(0xFFFFFFFFu, psum0, 1);
        psum0 += __shfl_xor_sync(0xFFFFFFFFu, psum0, 2);
        psum1 += __shfl_xor_sync(0xFFFFFFFFu, psum1, 1);
        psum1 += __shfl_xor_sync(0xFFFFFFFFu, psum1, 2);
        lrow0 = lrow0 * cf0 + psum0;
        lrow1 = lrow1 * cf1 + psum1;

        #pragma unroll
        for (int nt = 0; nt < 8; nt++) {
            oacc[nt][0] *= cf0; oacc[nt][1] *= cf0;
            oacc[nt][2] *= cf1; oacc[nt][3] *= cf1;
        }
        __syncwarp();

        #pragma unroll
        for (int s = 0; s < 4; s++) {
            unsigned pah[4], pal[4];
            pah[0] = PHi[(m0 + r) * PLD2 + 8 * s + c];
            pah[1] = PHi[(m0 + r + 8) * PLD2 + 8 * s + c];
            pah[2] = PHi[(m0 + r) * PLD2 + 8 * s + c + 4];
            pah[3] = PHi[(m0 + r + 8) * PLD2 + 8 * s + c + 4];
            pal[0] = PLo[(m0 + r) * PLD2 + 8 * s + c];
            pal[1] = PLo[(m0 + r + 8) * PLD2 + 8 * s + c];
            pal[2] = PLo[(m0 + r) * PLD2 + 8 * s + c + 4];
            pal[3] = PLo[(m0 + r + 8) * PLD2 + 8 * s + c + 4];
            #pragma unroll
            for (int nt = 0; nt < 8; nt++) {
                unsigned vfh[2];
                vfh[0] = VH[(8 * s + c) * VLD + nt * 8 + r];
                vfh[1] = VH[(8 * s + c + 4) * VLD + nt * 8 + r];
                mma_f16(oacc[nt], pah, vfh);
                mma_f16(oacc[nt], pal, vfh);
            }
        }
    }

    const float li0 = 1.f / lrow0;
    const float li1 = 1.f / lrow1;
    const int b = bh >> 4, h = bh & 15;
    const int row0 = qt * ABQ + m0 + r;
    #pragma unroll
    for (int nt = 0; nt < 8; nt++) {
        const int col = h * DHEAD + nt * 8 + 2 * c;
        float* o0 = g_aout + (size_t)(b * SEQ + row0) * INNER + col;
        float* o1 = g_aout + (size_t)(b * SEQ + row0 + 8) * INNER + col;
        *(float2*)o0 = make_float2(oacc[nt][0] * li0, oacc[nt][1] * li0);
        *(float2*)o1 = make_float2(oacc[nt][2] * li1, oacc[nt][3] * li1);
    }
}

// ---------------- launch ------------------------------------------------------
extern "C" void kernel_launch(void* const* d_in, const int* in_sizes, int n_in,
                              void* d_out, int out_size) {
    const float* x       = (const float*)d_in[0];
    const float* gamma   = (const float*)d_in[1];
    const float* beta    = (const float*)d_in[2];
    const float* null_kv = (const float*)d_in[3];
    const float* Wq      = (const float*)d_in[4];
    const float* Wkv     = (const float*)d_in[5];
    const float* q_scale = (const float*)d_in[6];
    const float* k_scale = (const float*)d_in[7];
    const float* Wo      = (const float*)d_in[8];
    float* out = (float*)d_out;

    cudaFuncSetAttribute(gemm_q_kernel,  cudaFuncAttributeMaxDynamicSharedMemorySize, GEMM_SMEM);
    cudaFuncSetAttribute(gemm_kv_kernel, cudaFuncAttributeMaxDynamicSharedMemorySize, GEMM_SMEM);
    cudaFuncSetAttribute(gemm_o_kernel,  cudaFuncAttributeMaxDynamicSharedMemorySize, GEMM_SMEM);
    cudaFuncSetAttribute(attn_mma_kernel, cudaFuncAttributeMaxDynamicSharedMemorySize, ATT_SMEM);

    ln_kernel<<<TOKENS, 256>>>(x, gamma, beta);
    gemm_q_kernel <<<dim3(INNER / 128,     TOKENS / 128), 256, GEMM_SMEM>>>(Wq);
    gemm_kv_kernel<<<dim3(2 * INNER / 128, TOKENS / 128), 256, GEMM_SMEM>>>(Wkv);
    qkv_prep<<<(TOKENS * HEADS) / 8, 256>>>(q_scale, k_scale);
    null_prep<<<BATCH * HEADS, 32>>>(null_kv, k_scale);
    attn_mma_kernel<<<dim3(SEQ / ABQ, BATCH * HEADS), 256, ATT_SMEM>>>();
    gemm_o_kernel<<<dim3(DIM / 128, TOKENS / 128), 256, GEMM_SMEM>>>(Wo, out);
}

// round 8
// speedup vs baseline: 5.8999x; 1.1051x over previous
#include <cuda_runtime.h>
#include <cuda_fp16.h>
#include <math.h>

#define HEADS   16
#define DHEAD   64
#define BATCH   4
#define SEQ     2048
#define DIM     1024
#define INNER   1024
#define TOKENS  (BATCH*SEQ)       /* 8192 */
#define KVLEN   (SEQ+1)           /* 2049 */
#define SCALE_F 8.0f
#define LN_EPS  1e-5f
#define L2_EPS  1e-12f

#define KTPITCH 2112   /* words per (bh,dd) row of packed-transposed K; zero-init pad */
#define VROWS   2112   /* padded j rows of packed V */

// ---------------- scratch (global device arrays; no allocations) -------------
// packed f16x2 words unless noted. Pads are never written -> stay zero-initialized.
__device__ unsigned g_xnH [TOKENS * DIM / 2];
__device__ unsigned g_xnL [TOKENS * DIM / 2];
__device__ unsigned g_WqP [(DIM / 2) * INNER];
__device__ unsigned g_WkvP[(DIM / 2) * 2 * INNER];
__device__ unsigned g_WoP [(INNER / 2) * DIM];
__device__ float    g_qlin [TOKENS * INNER];
__device__ float    g_kvlin[TOKENS * 2 * INNER];
__device__ float    g_Q    [BATCH * HEADS * SEQ * DHEAD];
__device__ unsigned g_KtP  [64 * 32 * KTPITCH];   // [bh][dd][j]: (K[j][2dd],K[j][2dd+1])
__device__ unsigned g_VP   [64 * VROWS * 32];     // [bh][j][dw]: (V[j][2dw],V[j][2dw+1])
__device__ unsigned g_aoH  [TOKENS * INNER / 2];
__device__ unsigned g_aoL  [TOKENS * INNER / 2];

// ---------------- fp16 helpers --------------------------------------------------
__device__ __forceinline__ void mma_f16(float* c, const unsigned* a, const unsigned* b) {
    asm volatile(
        "mma.sync.aligned.m16n8k16.row.col.f32.f16.f16.f32 "
        "{%0,%1,%2,%3}, {%4,%5,%6,%7}, {%8,%9}, {%0,%1,%2,%3};"
        : "+f"(c[0]), "+f"(c[1]), "+f"(c[2]), "+f"(c[3])
        : "r"(a[0]), "r"(a[1]), "r"(a[2]), "r"(a[3]), "r"(b[0]), "r"(b[1]));
}
__device__ __forceinline__ void split2(float a, float b, unsigned& hi, unsigned& lo) {
    __half ha = __float2half_rn(a);
    __half hb = __float2half_rn(b);
    float la = a - __half2float(ha);
    float lb = b - __half2float(hb);
    __half2 h2 = __halves2half2(ha, hb);
    __half2 l2 = __floats2half2_rn(la, lb);
    hi = *(unsigned*)&h2;
    lo = *(unsigned*)&l2;
}
__device__ __forceinline__ unsigned pack2(float a, float b) {
    __half2 h2 = __floats2half2_rn(a, b);
    return *(unsigned*)&h2;
}
__device__ __forceinline__ unsigned prmt(unsigned a, unsigned b, unsigned sel) {
    unsigned d;
    asm("prmt.b32 %0, %1, %2, %3;" : "=r"(d) : "r"(a), "r"(b), "r"(sel));
    return d;
}

// ---------------- LayerNorm (writes packed f16 hi/lo) --------------------------
__global__ void __launch_bounds__(256) ln_kernel(const float* __restrict__ x,
                                                 const float* __restrict__ gamma,
                                                 const float* __restrict__ beta) {
    __shared__ float red[8][2];
    const int t = blockIdx.x;
    const int i = threadIdx.x;
    const float4 v = ((const float4*)(x + (size_t)t * DIM))[i];
    float s  = v.x + v.y + v.z + v.w;
    float ss = v.x*v.x + v.y*v.y + v.z*v.z + v.w*v.w;
    #pragma unroll
    for (int o = 16; o > 0; o >>= 1) {
        s  += __shfl_xor_sync(0xFFFFFFFFu, s,  o);
        ss += __shfl_xor_sync(0xFFFFFFFFu, ss, o);
    }
    const int w = i >> 5, l = i & 31;
    if (l == 0) { red[w][0] = s; red[w][1] = ss; }
    __syncthreads();
    if (w == 0) {
        s  = (l < 8) ? red[l][0] : 0.f;
        ss = (l < 8) ? red[l][1] : 0.f;
        #pragma unroll
        for (int o = 4; o > 0; o >>= 1) {
            s  += __shfl_xor_sync(0xFFFFFFFFu, s,  o);
            ss += __shfl_xor_sync(0xFFFFFFFFu, ss, o);
        }
        if (l == 0) { red[0][0] = s; red[0][1] = ss; }
    }
    __syncthreads();
    const float mu   = red[0][0] * (1.f / DIM);
    const float var  = red[0][1] * (1.f / DIM) - mu * mu;
    const float rstd = rsqrtf(var + LN_EPS);
    const float4 g  = ((const float4*)gamma)[i];
    const float4 be = ((const float4*)beta)[i];
    float4 o4;
    o4.x = (v.x - mu) * rstd * g.x + be.x;
    o4.y = (v.y - mu) * rstd * g.y + be.y;
    o4.z = (v.z - mu) * rstd * g.z + be.z;
    o4.w = (v.w - mu) * rstd * g.w + be.w;
    unsigned h0, l0, h1, l1;
    split2(o4.x, o4.y, h0, l0);
    split2(o4.z, o4.w, h1, l1);
    const size_t wi = (size_t)t * (DIM / 2) + 2 * i;
    *(uint2*)&g_xnH[wi] = make_uint2(h0, h1);
    *(uint2*)&g_xnL[wi] = make_uint2(l0, l1);
}

// ---------------- weight packing: W[K][N] fp32 -> WP[K/2][N] f16x2 -------------
__global__ void __launch_bounds__(256) pack_w(const float* __restrict__ W,
                                              unsigned* __restrict__ WP,
                                              int K, int N) {
    const int total = (K / 2) * N;
    for (int idx = blockIdx.x * 256 + threadIdx.x; idx < total; idx += gridDim.x * 256) {
        const int kp = idx / N;
        const int n  = idx - kp * N;
        WP[idx] = pack2(W[(size_t)(2 * kp) * N + n], W[(size_t)(2 * kp + 1) * N + n]);
    }
}

// ---------------- fp16 2-pass tensor-core GEMM (pure-copy fills) ---------------
#define ASLD 20
#define BSLD 136
#define GSTAGE_W (2 * 128 * ASLD + 16 * BSLD)
#define GEMM_SMEM (2 * GSTAGE_W * 4)

template <int N, int K>
__device__ __forceinline__ void gemm_f16_body(const unsigned* __restrict__ AH,
                                              const unsigned* __restrict__ AL,
                                              const unsigned* __restrict__ BP,
                                              float* __restrict__ C) {
    extern __shared__ unsigned gsm[];

    const int tid  = threadIdx.x;
    const int warp = tid >> 5;
    const int lane = tid & 31;
    const int r = lane >> 2;
    const int c = lane & 3;
    const int wm = (warp & 3) * 32;
    const int wn = (warp >> 2) * 64;
    const int rowBase = blockIdx.y * 128;
    const int colBase = blockIdx.x * 128;

    const int arow = tid >> 1;
    const int asel = (tid & 1) * 8;       // word offset 0/8 within 16-word row chunk
    const int bkp  = tid >> 4;            // 0..15
    const int bn0  = (tid & 15) * 8;

    const unsigned* ApH = AH + (size_t)(rowBase + arow) * (K / 2) + asel;
    const unsigned* ApL = AL + (size_t)(rowBase + arow) * (K / 2) + asel;
    const unsigned* BpP = BP + colBase + bn0;

    float acc[2][8][4];
    #pragma unroll
    for (int mi = 0; mi < 2; mi++)
        #pragma unroll
        for (int ni = 0; ni < 8; ni++)
            #pragma unroll
            for (int j = 0; j < 4; j++) acc[mi][ni][j] = 0.f;

    const int NC = K / 32;

    auto fill = [&](int ck) {
        unsigned* st  = gsm + (ck & 1) * GSTAGE_W;
        unsigned* AsH = st;
        unsigned* AsL = st + 128 * ASLD;
        unsigned* Bs  = st + 2 * 128 * ASLD;
        const int kw = ck * 16;
        uint4 h0 = *(const uint4*)(ApH + kw);
        uint4 h1 = *(const uint4*)(ApH + kw + 4);
        uint4 l0 = *(const uint4*)(ApL + kw);
        uint4 l1 = *(const uint4*)(ApL + kw + 4);
        unsigned* ad = &AsH[arow * ASLD + asel];
        *(uint4*)ad       = h0;
        *(uint4*)(ad + 4) = h1;
        unsigned* al = &AsL[arow * ASLD + asel];
        *(uint4*)al       = l0;
        *(uint4*)(al + 4) = l1;
        const unsigned* bp = BpP + (size_t)(kw + bkp) * N;
        uint4 b0 = *(const uint4*)bp;
        uint4 b1 = *(const uint4*)(bp + 4);
        unsigned* bd = &Bs[bkp * BSLD + bn0];
        *(uint4*)bd       = b0;
        *(uint4*)(bd + 4) = b1;
    };

    fill(0);
    __syncthreads();

    #pragma unroll 1
    for (int ck = 0; ck < NC; ck++) {
        if (ck + 1 < NC) fill(ck + 1);

        const unsigned* st  = gsm + (ck & 1) * GSTAGE_W;
        const unsigned* AsH = st;
        const unsigned* AsL = st + 128 * ASLD;
        const unsigned* Bs  = st + 2 * 128 * ASLD;

        #pragma unroll
        for (int s = 0; s < 2; s++) {
            unsigned ah[2][4], al[2][4];
            #pragma unroll
            for (int mi = 0; mi < 2; mi++) {
                const int row = wm + mi * 16;
                ah[mi][0] = AsH[(row + r) * ASLD + 8 * s + c];
                ah[mi][1] = AsH[(row + 8 + r) * ASLD + 8 * s + c];
                ah[mi][2] = AsH[(row + r) * ASLD + 8 * s + c + 4];
                ah[mi][3] = AsH[(row + 8 + r) * ASLD + 8 * s + c + 4];
                al[mi][0] = AsL[(row + r) * ASLD + 8 * s + c];
                al[mi][1] = AsL[(row + 8 + r) * ASLD + 8 * s + c];
                al[mi][2] = AsL[(row + r) * ASLD + 8 * s + c + 4];
                al[mi][3] = AsL[(row + 8 + r) * ASLD + 8 * s + c + 4];
            }
            #pragma unroll
            for (int ni = 0; ni < 8; ni++) {
                unsigned bf[2];
                bf[0] = Bs[(8 * s + c) * BSLD + wn + ni * 8 + r];
                bf[1] = Bs[(8 * s + c + 4) * BSLD + wn + ni * 8 + r];
                #pragma unroll
                for (int mi = 0; mi < 2; mi++) {
                    mma_f16(acc[mi][ni], ah[mi], bf);
                    mma_f16(acc[mi][ni], al[mi], bf);
                }
            }
        }
        __syncthreads();
    }

    #pragma unroll
    for (int mi = 0; mi < 2; mi++) {
        const int row = rowBase + wm + mi * 16 + r;
        #pragma unroll
        for (int ni = 0; ni < 8; ni++) {
            const int col = colBase + wn + ni * 8 + 2 * c;
            *(float2*)&C[(size_t)row * N + col]       = make_float2(acc[mi][ni][0], acc[mi][ni][1]);
            *(float2*)&C[(size_t)(row + 8) * N + col] = make_float2(acc[mi][ni][2], acc[mi][ni][3]);
        }
    }
}

__global__ void __launch_bounds__(256, 2) gemm_q_kernel() {
    gemm_f16_body<INNER, DIM>(g_xnH, g_xnL, g_WqP, g_qlin);
}
__global__ void __launch_bounds__(256, 2) gemm_kv_kernel() {
    gemm_f16_body<2 * INNER, DIM>(g_xnH, g_xnL, g_WkvP, g_kvlin);
}
__global__ void __launch_bounds__(256, 2) gemm_o_kernel(float* __restrict__ out) {
    gemm_f16_body<DIM, INNER>(g_aoH, g_aoL, g_WoP, out);
}

// ---------------- head split + l2norm + packed fp16 K/V ------------------------
__global__ void __launch_bounds__(256) qkv_prep(const float* __restrict__ q_scale,
                                                const float* __restrict__ k_scale) {
    const int gw   = (blockIdx.x * 256 + threadIdx.x) >> 5;
    const int lane = threadIdx.x & 31;
    if (gw >= TOKENS * HEADS) return;
    const int t = gw >> 4;
    const int h = gw & 15;
    const int bb = t >> 11;
    const int i = t & 2047;
    const int bh = bb * HEADS + h;
    const int src0 = (2 * lane) & 31;
    const int src1 = (2 * lane + 1) & 31;

    // ---- q (fp32, SCALE folded) ----
    const float* qr = g_qlin + (size_t)t * INNER + h * DHEAD;
    float q0 = qr[lane], q1 = qr[lane + 32];
    float ss = q0 * q0 + q1 * q1;
    #pragma unroll
    for (int o = 16; o > 0; o >>= 1) ss += __shfl_xor_sync(0xFFFFFFFFu, ss, o);
    float inv = 1.f / fmaxf(sqrtf(ss), L2_EPS);
    float* qo = g_Q + ((size_t)bh * SEQ + i) * DHEAD;
    qo[lane]      = q0 * inv * q_scale[lane]      * SCALE_F;
    qo[lane + 32] = q1 * inv * q_scale[lane + 32] * SCALE_F;

    // ---- k: scale, round to fp16, write packed-transposed d-pairs ----
    const float* kr = g_kvlin + (size_t)t * (2 * INNER) + h * DHEAD;
    float k0 = kr[lane], k1 = kr[lane + 32];
    ss = k0 * k0 + k1 * k1;
    #pragma unroll
    for (int o = 16; o > 0; o >>= 1) ss += __shfl_xor_sync(0xFFFFFFFFu, ss, o);
    inv = 1.f / fmaxf(sqrtf(ss), L2_EPS);
    const float kk0 = k0 * inv * k_scale[lane];
    const float kk1 = k1 * inv * k_scale[lane + 32];
    {
        float s0a = __shfl_sync(0xFFFFFFFFu, kk0, src0);
        float s0b = __shfl_sync(0xFFFFFFFFu, kk0, src1);
        float s1a = __shfl_sync(0xFFFFFFFFu, kk1, src0);
        float s1b = __shfl_sync(0xFFFFFFFFu, kk1, src1);
        const float a = (lane < 16) ? s0a : s1a;
        const float b = (lane < 16) ? s0b : s1b;
        g_KtP[((size_t)bh * 32 + lane) * KTPITCH + i + 1] = pack2(a, b);
    }

    // ---- v: round to fp16, write d-pair words ----
    const float* vr = g_kvlin + (size_t)t * (2 * INNER) + INNER + h * DHEAD;
    const float v0 = vr[lane], v1 = vr[lane + 32];
    {
        float s0a = __shfl_sync(0xFFFFFFFFu, v0, src0);
        float s0b = __shfl_sync(0xFFFFFFFFu, v0, src1);
        float s1a = __shfl_sync(0xFFFFFFFFu, v1, src0);
        float s1b = __shfl_sync(0xFFFFFFFFu, v1, src1);
        const float a = (lane < 16) ? s0a : s1a;
        const float b = (lane < 16) ? s0b : s1b;
        g_VP[((size_t)bh * VROWS + i + 1) * 32 + lane] = pack2(a, b);
    }
}

__global__ void null_prep(const float* __restrict__ null_kv,
                          const float* __restrict__ k_scale) {
    const int bh = blockIdx.x;
    const int h = bh & 15;
    const int lane = threadIdx.x;
    const int src0 = (2 * lane) & 31;
    const int src1 = (2 * lane + 1) & 31;
    const float* nk = null_kv + h * DHEAD;
    const float* nv = null_kv + HEADS * DHEAD + h * DHEAD;
    float k0 = nk[lane], k1 = nk[lane + 32];
    float ss = k0 * k0 + k1 * k1;
    #pragma unroll
    for (int o = 16; o > 0; o >>= 1) ss += __shfl_xor_sync(0xFFFFFFFFu, ss, o);
    const float inv = 1.f / fmaxf(sqrtf(ss), L2_EPS);
    const float kk0 = k0 * inv * k_scale[lane];
    const float kk1 = k1 * inv * k_scale[lane + 32];
    {
        float s0a = __shfl_sync(0xFFFFFFFFu, kk0, src0);
        float s0b = __shfl_sync(0xFFFFFFFFu, kk0, src1);
        float s1a = __shfl_sync(0xFFFFFFFFu, kk1, src0);
        float s1b = __shfl_sync(0xFFFFFFFFu, kk1, src1);
        const float a = (lane < 16) ? s0a : s1a;
        const float b = (lane < 16) ? s0b : s1b;
        g_KtP[((size_t)bh * 32 + lane) * KTPITCH] = pack2(a, b);
    }
    const float v0 = nv[lane], v1 = nv[lane + 32];
    {
        float s0a = __shfl_sync(0xFFFFFFFFu, v0, src0);
        float s0b = __shfl_sync(0xFFFFFFFFu, v0, src1);
        float s1a = __shfl_sync(0xFFFFFFFFu, v1, src0);
        float s1b = __shfl_sync(0xFFFFFFFFu, v1, src1);
        const float a = (lane < 16) ? s0a : s1a;
        const float b = (lane < 16) ? s0b : s1b;
        g_VP[(size_t)bh * VROWS * 32 + lane] = pack2(a, b);
    }
}

// ---------------- flash attention, fp16 2-pass split (copy fills) --------------
#define ABQ 128
#define ABK 64
#define ANT ((KVLEN + ABK - 1) / ABK)   /* 33 */
#define KTLD 72
#define VLD  72
#define PLD2 36

#define ATT_SMEM ((32*KTLD + 32*VLD + 2*ABQ*PLD2) * 4)   /* 55296 B */

__global__ void __launch_bounds__(256, 2) attn_mma_kernel() {
    extern __shared__ unsigned ash[];
    unsigned* KtH = ash;
    unsigned* VH  = KtH + 32 * KTLD;
    unsigned* PHi = VH  + 32 * VLD;
    unsigned* PLo = PHi + ABQ * PLD2;

    const int tid  = threadIdx.x;
    const int warp = tid >> 5;
    const int lane = tid & 31;
    const int r = lane >> 2;
    const int c = lane & 3;
    const int bh = blockIdx.y;
    const int qt = blockIdx.x;
    const int m0 = warp * 16;

    const float* Qg = g_Q + ((size_t)bh * SEQ + (size_t)qt * ABQ + m0) * DHEAD;
    unsigned qhi[4][4], qlo[4][4];
    #pragma unroll
    for (int s = 0; s < 4; s++) {
        float2 x0 = *(const float2*)(Qg + (size_t)r * DHEAD + s * 16 + 2 * c);
        float2 x1 = *(const float2*)(Qg + (size_t)(r + 8) * DHEAD + s * 16 + 2 * c);
        float2 x2 = *(const float2*)(Qg + (size_t)r * DHEAD + s * 16 + 2 * c + 8);
        float2 x3 = *(const float2*)(Qg + (size_t)(r + 8) * DHEAD + s * 16 + 2 * c + 8);
        split2(x0.x, x0.y, qhi[s][0], qlo[s][0]);
        split2(x1.x, x1.y, qhi[s][1], qlo[s][1]);
        split2(x2.x, x2.y, qhi[s][2], qlo[s][2]);
        split2(x3.x, x3.y, qhi[s][3], qlo[s][3]);
    }

    float oacc[8][4];
    #pragma unroll
    for (int nt = 0; nt < 8; nt++)
        #pragma unroll
        for (int j = 0; j < 4; j++) oacc[nt][j] = 0.f;
    float mrow0 = -1e30f, mrow1 = -1e30f, lrow0 = 0.f, lrow1 = 0.f;

    // fill pointers (pads are zero-initialized -> unchecked loads safe)
    const unsigned* KtG = g_KtP + ((size_t)bh * 32 + (tid >> 3)) * KTPITCH + (tid & 7) * 8;
    const int vjj = tid >> 3;
    const int vdw = (tid & 7) * 4;
    const unsigned* VgBase = g_VP + (size_t)bh * VROWS * 32;

    for (int kt = 0; kt < ANT; kt++) {
        const int kvbase = kt * ABK;
        __syncthreads();

        // ---- Kt fill: straight copy ----
        {
            uint4 w0 = *(const uint4*)(KtG + kvbase);
            uint4 w1 = *(const uint4*)(KtG + kvbase + 4);
            unsigned* dst = &KtH[(tid >> 3) * KTLD + (tid & 7) * 8];
            *(uint4*)dst       = w0;
            *(uint4*)(dst + 4) = w1;
        }
        // ---- V fill: 2 loads + prmt interleave (j-pair packing) ----
        {
            const unsigned* va = VgBase + (size_t)(kvbase + 2 * vjj) * 32 + vdw;
            uint4 A4 = *(const uint4*)va;
            uint4 B4 = *(const uint4*)(va + 32);
            unsigned* dst = &VH[vjj * VLD + 2 * vdw];
            uint4 o0, o1;
            o0.x = prmt(A4.x, B4.x, 0x5410); o0.y = prmt(A4.x, B4.x, 0x7632);
            o0.z = prmt(A4.y, B4.y, 0x5410); o0.w = prmt(A4.y, B4.y, 0x7632);
            o1.x = prmt(A4.z, B4.z, 0x5410); o1.y = prmt(A4.z, B4.z, 0x7632);
            o1.z = prmt(A4.w, B4.w, 0x5410); o1.w = prmt(A4.w, B4.w, 0x7632);
            *(uint4*)dst       = o0;
            *(uint4*)(dst + 4) = o1;
        }
        __syncthreads();

        float sa[8][4];
        #pragma unroll
        for (int nt = 0; nt < 8; nt++)
            #pragma unroll
            for (int j = 0; j < 4; j++) sa[nt][j] = 0.f;

        #pragma unroll
        for (int s = 0; s < 4; s++) {
            #pragma unroll
            for (int nt = 0; nt < 8; nt++) {
                unsigned bfh[2];
                bfh[0] = KtH[(8 * s + c) * KTLD + nt * 8 + r];
                bfh[1] = KtH[(8 * s + c + 4) * KTLD + nt * 8 + r];
                mma_f16(sa[nt], qhi[s], bfh);
                mma_f16(sa[nt], qlo[s], bfh);
            }
        }

        float tmax0 = -1e30f, tmax1 = -1e30f;
        #pragma unroll
        for (int nt = 0; nt < 8; nt++) {
            const int j0 = kvbase + nt * 8 + 2 * c;
            if (j0 >= KVLEN)     { sa[nt][0] = -1e30f; sa[nt][2] = -1e30f; }
            if (j0 + 1 >= KVLEN) { sa[nt][1] = -1e30f; sa[nt][3] = -1e30f; }
            tmax0 = fmaxf(tmax0, fmaxf(sa[nt][0], sa[nt][1]));
            tmax1 = fmaxf(tmax1, fmaxf(sa[nt][2], sa[nt][3]));
        }
        tmax0 = fmaxf(tmax0, __shfl_xor_sync(0xFFFFFFFFu, tmax0, 1));
        tmax0 = fmaxf(tmax0, __shfl_xor_sync(0xFFFFFFFFu, tmax0, 2));
        tmax1 = fmaxf(tmax1, __shfl_xor_sync(0xFFFFFFFFu, tmax1, 1));
        tmax1 = fmaxf(tmax1, __shfl_xor_sync(0xFFFFFFFFu, tmax1, 2));

        const float mnew0 = fmaxf(mrow0, tmax0);
        const float mnew1 = fmaxf(mrow1, tmax1);
        const float cf0 = __expf(mrow0 - mnew0);
        const float cf1 = __expf(mrow1 - mnew1);
        mrow0 = mnew0; mrow1 = mnew1;

        float psum0 = 0.f, psum1 = 0.f;
        #pragma unroll
        for (int nt = 0; nt < 8; nt++) {
            const float p0 = __expf(sa[nt][0] - mnew0);
            const float p1 = __expf(sa[nt][1] - mnew0);
            const float p2 = __expf(sa[nt][2] - mnew1);
            const float p3 = __expf(sa[nt][3] - mnew1);
            psum0 += p0 + p1;
            psum1 += p2 + p3;
            unsigned h0, l0, h1, l1;
            split2(p0, p1, h0, l0);
            split2(p2, p3, h1, l1);
            PHi[(m0 + r) * PLD2 + nt * 4 + c]     = h0;
            PLo[(m0 + r) * PLD2 + nt * 4 + c]     = l0;
            PHi[(m0 + r + 8) * PLD2 + nt * 4 + c] = h1;
            PLo[(m0 + r + 8) * PLD2 + nt * 4 + c] = l1;
        }
        psum0 += __shfl_xor_sync(0xFFFFFFFFu, psum0, 1);
        psum0 += __shfl_xor_sync(0xFFFFFFFFu, psum0, 2);
        psum1 += __shfl_xor_sync(0xFFFFFFFFu, psum1, 1);
        psum1 += __shfl_xor_sync(0xFFFFFFFFu, psum1, 2);
        lrow0 = lrow0 * cf0 + psum0;
        lrow1 = lrow1 * cf1 + psum1;

        #pragma unroll
        for (int nt = 0; nt < 8; nt++) {
            oacc[nt][0] *= cf0; oacc[nt][1] *= cf0;
            oacc[nt][2] *= cf1; oacc[nt][3] *= cf1;
        }
        __syncwarp();

        #pragma unroll
        for (int s = 0; s < 4; s++) {
            unsigned pah[4], pal[4];
            pah[0] = PHi[(m0 + r) * PLD2 + 8 * s + c];
            pah[1] = PHi[(m0 + r + 8) * PLD2 + 8 * s + c];
            pah[2] = PHi[(m0 + r) * PLD2 + 8 * s + c + 4];
            pah[3] = PHi[(m0 + r + 8) * PLD2 + 8 * s + c + 4];
            pal[0] = PLo[(m0 + r) * PLD2 + 8 * s + c];
            pal[1] = PLo[(m0 + r + 8) * PLD2 + 8 * s + c];
            pal[2] = PLo[(m0 + r) * PLD2 + 8 * s + c + 4];
            pal[3] = PLo[(m0 + r + 8) * PLD2 + 8 * s + c + 4];
            #pragma unroll
            for (int nt = 0; nt < 8; nt++) {
                unsigned vfh[2];
                vfh[0] = VH[(8 * s + c) * VLD + nt * 8 + r];
                vfh[1] = VH[(8 * s + c + 4) * VLD + nt * 8 + r];
                mma_f16(oacc[nt], pah, vfh);
                mma_f16(oacc[nt], pal, vfh);
            }
        }
    }

    // ---- epilogue: write packed fp16 hi/lo for gemm_o ----
    const float li0 = 1.f / lrow0;
    const float li1 = 1.f / lrow1;
    const int bb = bh >> 4, h = bh & 15;
    const int row0 = qt * ABQ + m0 + r;
    #pragma unroll
    for (int nt = 0; nt < 8; nt++) {
        const size_t wi0 = (size_t)(bb * SEQ + row0) * (INNER / 2) + h * 32 + nt * 4 + c;
        const size_t wi1 = (size_t)(bb * SEQ + row0 + 8) * (INNER / 2) + h * 32 + nt * 4 + c;
        unsigned hw, lw;
        split2(oacc[nt][0] * li0, oacc[nt][1] * li0, hw, lw);
        g_aoH[wi0] = hw; g_aoL[wi0] = lw;
        split2(oacc[nt][2] * li1, oacc[nt][3] * li1, hw, lw);
        g_aoH[wi1] = hw; g_aoL[wi1] = lw;
    }
}

// ---------------- launch ------------------------------------------------------
extern "C" void kernel_launch(void* const* d_in, const int* in_sizes, int n_in,
                              void* d_out, int out_size) {
    const float* x       = (const float*)d_in[0];
    const float* gamma   = (const float*)d_in[1];
    const float* beta    = (const float*)d_in[2];
    const float* null_kv = (const float*)d_in[3];
    const float* Wq      = (const float*)d_in[4];
    const float* Wkv     = (const float*)d_in[5];
    const float* q_scale = (const float*)d_in[6];
    const float* k_scale = (const float*)d_in[7];
    const float* Wo      = (const float*)d_in[8];
    float* out = (float*)d_out;

    unsigned* wqp, *wkvp, *wop;
    cudaGetSymbolAddress((void**)&wqp,  g_WqP);
    cudaGetSymbolAddress((void**)&wkvp, g_WkvP);
    cudaGetSymbolAddress((void**)&wop,  g_WoP);

    cudaFuncSetAttribute(gemm_q_kernel,  cudaFuncAttributeMaxDynamicSharedMemorySize, GEMM_SMEM);
    cudaFuncSetAttribute(gemm_kv_kernel, cudaFuncAttributeMaxDynamicSharedMemorySize, GEMM_SMEM);
    cudaFuncSetAttribute(gemm_o_kernel,  cudaFuncAttributeMaxDynamicSharedMemorySize, GEMM_SMEM);
    cudaFuncSetAttribute(attn_mma_kernel, cudaFuncAttributeMaxDynamicSharedMemorySize, ATT_SMEM);

    pack_w<<<512, 256>>>(Wq,  wqp,  DIM,   INNER);
    pack_w<<<512, 256>>>(Wkv, wkvp, DIM,   2 * INNER);
    pack_w<<<512, 256>>>(Wo,  wop,  INNER, DIM);
    ln_kernel<<<TOKENS, 256>>>(x, gamma, beta);
    gemm_q_kernel <<<dim3(INNER / 128,     TOKENS / 128), 256, GEMM_SMEM>>>();
    gemm_kv_kernel<<<dim3(2 * INNER / 128, TOKENS / 128), 256, GEMM_SMEM>>>();
    qkv_prep<<<(TOKENS * HEADS) / 8, 256>>>(q_scale, k_scale);
    null_prep<<<BATCH * HEADS, 32>>>(null_kv, k_scale);
    attn_mma_kernel<<<dim3(SEQ / ABQ, BATCH * HEADS), 256, ATT_SMEM>>>();
    gemm_o_kernel<<<dim3(DIM / 128, TOKENS / 128), 256, GEMM_SMEM>>>(out);
}

// round 9
// speedup vs baseline: 8.5366x; 1.4469x over previous
#include <cuda_runtime.h>
#include <cuda_fp16.h>
#include <math.h>

#define HEADS   16
#define DHEAD   64
#define BATCH   4
#define SEQ     2048
#define DIM     1024
#define INNER   1024
#define TOKENS  (BATCH*SEQ)       /* 8192 */
#define KVLEN   (SEQ+1)           /* 2049 */
#define SCALE_F 8.0f
#define LN_EPS  1e-5f
#define L2_EPS  1e-12f

#define KTPITCH 2112   /* words per (bh,dd) row of packed-transposed K; zero-init pad */
#define VROWS   2112   /* padded j rows of packed V */

// ---------------- scratch (global device arrays; no allocations) -------------
__device__ unsigned g_xnH [TOKENS * DIM / 2];     // LN out, packed fp16
__device__ unsigned g_WqP [(DIM / 2) * INNER];
__device__ unsigned g_WkvP[(DIM / 2) * 2 * INNER];
__device__ unsigned g_WoP [(INNER / 2) * DIM];
__device__ float    g_qlin [TOKENS * INNER];
__device__ float    g_kvlin[TOKENS * 2 * INNER];
__device__ float    g_Q    [BATCH * HEADS * SEQ * DHEAD];
__device__ unsigned g_KtP  [64 * 32 * KTPITCH];   // [bh][dd][j]
__device__ unsigned g_VP   [64 * VROWS * 32];     // [bh][j][dw]
__device__ unsigned g_aoH  [TOKENS * INNER / 2];  // attention out, packed fp16

// ---------------- fp16 helpers --------------------------------------------------
__device__ __forceinline__ void mma_f16(float* c, const unsigned* a, const unsigned* b) {
    asm volatile(
        "mma.sync.aligned.m16n8k16.row.col.f32.f16.f16.f32 "
        "{%0,%1,%2,%3}, {%4,%5,%6,%7}, {%8,%9}, {%0,%1,%2,%3};"
        : "+f"(c[0]), "+f"(c[1]), "+f"(c[2]), "+f"(c[3])
        : "r"(a[0]), "r"(a[1]), "r"(a[2]), "r"(a[3]), "r"(b[0]), "r"(b[1]));
}
__device__ __forceinline__ void split2(float a, float b, unsigned& hi, unsigned& lo) {
    __half ha = __float2half_rn(a);
    __half hb = __float2half_rn(b);
    float la = a - __half2float(ha);
    float lb = b - __half2float(hb);
    __half2 h2 = __halves2half2(ha, hb);
    __half2 l2 = __floats2half2_rn(la, lb);
    hi = *(unsigned*)&h2;
    lo = *(unsigned*)&l2;
}
__device__ __forceinline__ unsigned pack2(float a, float b) {
    __half2 h2 = __floats2half2_rn(a, b);
    return *(unsigned*)&h2;
}
__device__ __forceinline__ unsigned prmt(unsigned a, unsigned b, unsigned sel) {
    unsigned d;
    asm("prmt.b32 %0, %1, %2, %3;" : "=r"(d) : "r"(a), "r"(b), "r"(sel));
    return d;
}

// ---------------- LayerNorm (writes packed fp16) --------------------------------
__global__ void __launch_bounds__(256) ln_kernel(const float* __restrict__ x,
                                                 const float* __restrict__ gamma,
                                                 const float* __restrict__ beta) {
    __shared__ float red[8][2];
    const int t = blockIdx.x;
    const int i = threadIdx.x;
    const float4 v = ((const float4*)(x + (size_t)t * DIM))[i];
    float s  = v.x + v.y + v.z + v.w;
    float ss = v.x*v.x + v.y*v.y + v.z*v.z + v.w*v.w;
    #pragma unroll
    for (int o = 16; o > 0; o >>= 1) {
        s  += __shfl_xor_sync(0xFFFFFFFFu, s,  o);
        ss += __shfl_xor_sync(0xFFFFFFFFu, ss, o);
    }
    const int w = i >> 5, l = i & 31;
    if (l == 0) { red[w][0] = s; red[w][1] = ss; }
    __syncthreads();
    if (w == 0) {
        s  = (l < 8) ? red[l][0] : 0.f;
        ss = (l < 8) ? red[l][1] : 0.f;
        #pragma unroll
        for (int o = 4; o > 0; o >>= 1) {
            s  += __shfl_xor_sync(0xFFFFFFFFu, s,  o);
            ss += __shfl_xor_sync(0xFFFFFFFFu, ss, o);
        }
        if (l == 0) { red[0][0] = s; red[0][1] = ss; }
    }
    __syncthreads();
    const float mu   = red[0][0] * (1.f / DIM);
    const float var  = red[0][1] * (1.f / DIM) - mu * mu;
    const float rstd = rsqrtf(var + LN_EPS);
    const float4 g  = ((const float4*)gamma)[i];
    const float4 be = ((const float4*)beta)[i];
    float4 o4;
    o4.x = (v.x - mu) * rstd * g.x + be.x;
    o4.y = (v.y - mu) * rstd * g.y + be.y;
    o4.z = (v.z - mu) * rstd * g.z + be.z;
    o4.w = (v.w - mu) * rstd * g.w + be.w;
    const size_t wi = (size_t)t * (DIM / 2) + 2 * i;
    *(uint2*)&g_xnH[wi] = make_uint2(pack2(o4.x, o4.y), pack2(o4.z, o4.w));
}

// ---------------- weight packing: W[K][N] fp32 -> WP[K/2][N] f16x2 -------------
__global__ void __launch_bounds__(256) pack_w(const float* __restrict__ W,
                                              unsigned* __restrict__ WP,
                                              int K, int N) {
    const int total = (K / 2) * N;
    for (int idx = blockIdx.x * 256 + threadIdx.x; idx < total; idx += gridDim.x * 256) {
        const int kp = idx / N;
        const int n  = idx - kp * N;
        WP[idx] = pack2(W[(size_t)(2 * kp) * N + n], W[(size_t)(2 * kp + 1) * N + n]);
    }
}

// ---------------- fp16 single-pass tensor-core GEMM ----------------------------
#define ASLD 20
#define BSLD 136
#define GSTAGE_W (128 * ASLD + 16 * BSLD)     /* 4736 words */
#define GEMM_SMEM (2 * GSTAGE_W * 4)          /* 37888 B */

template <int N, int K>
__device__ __forceinline__ void gemm_f16_body(const unsigned* __restrict__ AH,
                                              const unsigned* __restrict__ BP,
                                              float* __restrict__ C) {
    extern __shared__ unsigned gsm[];

    const int tid  = threadIdx.x;
    const int warp = tid >> 5;
    const int lane = tid & 31;
    const int r = lane >> 2;
    const int c = lane & 3;
    const int wm = (warp & 3) * 32;
    const int wn = (warp >> 2) * 64;
    const int rowBase = blockIdx.y * 128;
    const int colBase = blockIdx.x * 128;

    const int arow = tid >> 1;
    const int asel = (tid & 1) * 8;
    const int bkp  = tid >> 4;
    const int bn0  = (tid & 15) * 8;

    const unsigned* ApH = AH + (size_t)(rowBase + arow) * (K / 2) + asel;
    const unsigned* BpP = BP + colBase + bn0;

    float acc[2][8][4];
    #pragma unroll
    for (int mi = 0; mi < 2; mi++)
        #pragma unroll
        for (int ni = 0; ni < 8; ni++)
            #pragma unroll
            for (int j = 0; j < 4; j++) acc[mi][ni][j] = 0.f;

    const int NC = K / 32;

    auto fill = [&](int ck) {
        unsigned* st  = gsm + (ck & 1) * GSTAGE_W;
        unsigned* AsH = st;
        unsigned* Bs  = st + 128 * ASLD;
        const int kw = ck * 16;
        uint4 h0 = *(const uint4*)(ApH + kw);
        uint4 h1 = *(const uint4*)(ApH + kw + 4);
        unsigned* ad = &AsH[arow * ASLD + asel];
        *(uint4*)ad       = h0;
        *(uint4*)(ad + 4) = h1;
        const unsigned* bp = BpP + (size_t)(kw + bkp) * N;
        uint4 b0 = *(const uint4*)bp;
        uint4 b1 = *(const uint4*)(bp + 4);
        unsigned* bd = &Bs[bkp * BSLD + bn0];
        *(uint4*)bd       = b0;
        *(uint4*)(bd + 4) = b1;
    };

    fill(0);
    __syncthreads();

    #pragma unroll 1
    for (int ck = 0; ck < NC; ck++) {
        if (ck + 1 < NC) fill(ck + 1);

        const unsigned* st  = gsm + (ck & 1) * GSTAGE_W;
        const unsigned* AsH = st;
        const unsigned* Bs  = st + 128 * ASLD;

        #pragma unroll
        for (int s = 0; s < 2; s++) {
            unsigned ah[2][4];
            #pragma unroll
            for (int mi = 0; mi < 2; mi++) {
                const int row = wm + mi * 16;
                ah[mi][0] = AsH[(row + r) * ASLD + 8 * s + c];
                ah[mi][1] = AsH[(row + 8 + r) * ASLD + 8 * s + c];
                ah[mi][2] = AsH[(row + r) * ASLD + 8 * s + c + 4];
                ah[mi][3] = AsH[(row + 8 + r) * ASLD + 8 * s + c + 4];
            }
            #pragma unroll
            for (int ni = 0; ni < 8; ni++) {
                unsigned bf[2];
                bf[0] = Bs[(8 * s + c) * BSLD + wn + ni * 8 + r];
                bf[1] = Bs[(8 * s + c + 4) * BSLD + wn + ni * 8 + r];
                #pragma unroll
                for (int mi = 0; mi < 2; mi++)
                    mma_f16(acc[mi][ni], ah[mi], bf);
            }
        }
        __syncthreads();
    }

    #pragma unroll
    for (int mi = 0; mi < 2; mi++) {
        const int row = rowBase + wm + mi * 16 + r;
        #pragma unroll
        for (int ni = 0; ni < 8; ni++) {
            const int col = colBase + wn + ni * 8 + 2 * c;
            *(float2*)&C[(size_t)row * N + col]       = make_float2(acc[mi][ni][0], acc[mi][ni][1]);
            *(float2*)&C[(size_t)(row + 8) * N + col] = make_float2(acc[mi][ni][2], acc[mi][ni][3]);
        }
    }
}

__global__ void __launch_bounds__(256, 2) gemm_q_kernel() {
    gemm_f16_body<INNER, DIM>(g_xnH, g_WqP, g_qlin);
}
__global__ void __launch_bounds__(256, 2) gemm_kv_kernel() {
    gemm_f16_body<2 * INNER, DIM>(g_xnH, g_WkvP, g_kvlin);
}
__global__ void __launch_bounds__(256, 2) gemm_o_kernel(float* __restrict__ out) {
    gemm_f16_body<DIM, INNER>(g_aoH, g_WoP, out);
}

// ---------------- head split + l2norm + packed fp16 K/V ------------------------
__global__ void __launch_bounds__(256) qkv_prep(const float* __restrict__ q_scale,
                                                const float* __restrict__ k_scale) {
    const int gw   = (blockIdx.x * 256 + threadIdx.x) >> 5;
    const int lane = threadIdx.x & 31;
    if (gw >= TOKENS * HEADS) return;
    const int t = gw >> 4;
    const int h = gw & 15;
    const int bb = t >> 11;
    const int i = t & 2047;
    const int bh = bb * HEADS + h;
    const int src0 = (2 * lane) & 31;
    const int src1 = (2 * lane + 1) & 31;

    const float* qr = g_qlin + (size_t)t * INNER + h * DHEAD;
    float q0 = qr[lane], q1 = qr[lane + 32];
    float ss = q0 * q0 + q1 * q1;
    #pragma unroll
    for (int o = 16; o > 0; o >>= 1) ss += __shfl_xor_sync(0xFFFFFFFFu, ss, o);
    float inv = 1.f / fmaxf(sqrtf(ss), L2_EPS);
    float* qo = g_Q + ((size_t)bh * SEQ + i) * DHEAD;
    qo[lane]      = q0 * inv * q_scale[lane]      * SCALE_F;
    qo[lane + 32] = q1 * inv * q_scale[lane + 32] * SCALE_F;

    const float* kr = g_kvlin + (size_t)t * (2 * INNER) + h * DHEAD;
    float k0 = kr[lane], k1 = kr[lane + 32];
    ss = k0 * k0 + k1 * k1;
    #pragma unroll
    for (int o = 16; o > 0; o >>= 1) ss += __shfl_xor_sync(0xFFFFFFFFu, ss, o);
    inv = 1.f / fmaxf(sqrtf(ss), L2_EPS);
    const float kk0 = k0 * inv * k_scale[lane];
    const float kk1 = k1 * inv * k_scale[lane + 32];
    {
        float s0a = __shfl_sync(0xFFFFFFFFu, kk0, src0);
        float s0b = __shfl_sync(0xFFFFFFFFu, kk0, src1);
        float s1a = __shfl_sync(0xFFFFFFFFu, kk1, src0);
        float s1b = __shfl_sync(0xFFFFFFFFu, kk1, src1);
        const float a = (lane < 16) ? s0a : s1a;
        const float b = (lane < 16) ? s0b : s1b;
        g_KtP[((size_t)bh * 32 + lane) * KTPITCH + i + 1] = pack2(a, b);
    }

    const float* vr = g_kvlin + (size_t)t * (2 * INNER) + INNER + h * DHEAD;
    const float v0 = vr[lane], v1 = vr[lane + 32];
    {
        float s0a = __shfl_sync(0xFFFFFFFFu, v0, src0);
        float s0b = __shfl_sync(0xFFFFFFFFu, v0, src1);
        float s1a = __shfl_sync(0xFFFFFFFFu, v1, src0);
        float s1b = __shfl_sync(0xFFFFFFFFu, v1, src1);
        const float a = (lane < 16) ? s0a : s1a;
        const float b = (lane < 16) ? s0b : s1b;
        g_VP[((size_t)bh * VROWS + i + 1) * 32 + lane] = pack2(a, b);
    }
}

__global__ void null_prep(const float* __restrict__ null_kv,
                          const float* __restrict__ k_scale) {
    const int bh = blockIdx.x;
    const int h = bh & 15;
    const int lane = threadIdx.x;
    const int src0 = (2 * lane) & 31;
    const int src1 = (2 * lane + 1) & 31;
    const float* nk = null_kv + h * DHEAD;
    const float* nv = null_kv + HEADS * DHEAD + h * DHEAD;
    float k0 = nk[lane], k1 = nk[lane + 32];
    float ss = k0 * k0 + k1 * k1;
    #pragma unroll
    for (int o = 16; o > 0; o >>= 1) ss += __shfl_xor_sync(0xFFFFFFFFu, ss, o);
    const float inv = 1.f / fmaxf(sqrtf(ss), L2_EPS);
    const float kk0 = k0 * inv * k_scale[lane];
    const float kk1 = k1 * inv * k_scale[lane + 32];
    {
        float s0a = __shfl_sync(0xFFFFFFFFu, kk0, src0);
        float s0b = __shfl_sync(0xFFFFFFFFu, kk0, src1);
        float s1a = __shfl_sync(0xFFFFFFFFu, kk1, src0);
        float s1b = __shfl_sync(0xFFFFFFFFu, kk1, src1);
        const float a = (lane < 16) ? s0a : s1a;
        const float b = (lane < 16) ? s0b : s1b;
        g_KtP[((size_t)bh * 32 + lane) * KTPITCH] = pack2(a, b);
    }
    const float v0 = nv[lane], v1 = nv[lane + 32];
    {
        float s0a = __shfl_sync(0xFFFFFFFFu, v0, src0);
        float s0b = __shfl_sync(0xFFFFFFFFu, v0, src1);
        float s1a = __shfl_sync(0xFFFFFFFFu, v1, src0);
        float s1b = __shfl_sync(0xFFFFFFFFu, v1, src1);
        const float a = (lane < 16) ? s0a : s1a;
        const float b = (lane < 16) ? s0b : s1b;
        g_VP[(size_t)bh * VROWS * 32 + lane] = pack2(a, b);
    }
}

// ---------------- flash attention: S 2-pass, PV 1-pass, P in registers ---------
#define ABQ 128
#define ABK 64
#define ANT ((KVLEN + ABK - 1) / ABK)   /* 33 */
#define KTLD 72
#define VLD  72

#define ATT_SMEM ((32*KTLD + 32*VLD) * 4)   /* 18432 B */

__global__ void __launch_bounds__(256, 2) attn_mma_kernel() {
    extern __shared__ unsigned ash[];
    unsigned* KtH = ash;
    unsigned* VH  = KtH + 32 * KTLD;

    const int tid  = threadIdx.x;
    const int warp = tid >> 5;
    const int lane = tid & 31;
    const int r = lane >> 2;
    const int c = lane & 3;
    const int bh = blockIdx.y;
    const int qt = blockIdx.x;
    const int m0 = warp * 16;

    const float* Qg = g_Q + ((size_t)bh * SEQ + (size_t)qt * ABQ + m0) * DHEAD;
    unsigned qhi[4][4], qlo[4][4];
    #pragma unroll
    for (int s = 0; s < 4; s++) {
        float2 x0 = *(const float2*)(Qg + (size_t)r * DHEAD + s * 16 + 2 * c);
        float2 x1 = *(const float2*)(Qg + (size_t)(r + 8) * DHEAD + s * 16 + 2 * c);
        float2 x2 = *(const float2*)(Qg + (size_t)r * DHEAD + s * 16 + 2 * c + 8);
        float2 x3 = *(const float2*)(Qg + (size_t)(r + 8) * DHEAD + s * 16 + 2 * c + 8);
        split2(x0.x, x0.y, qhi[s][0], qlo[s][0]);
        split2(x1.x, x1.y, qhi[s][1], qlo[s][1]);
        split2(x2.x, x2.y, qhi[s][2], qlo[s][2]);
        split2(x3.x, x3.y, qhi[s][3], qlo[s][3]);
    }

    float oacc[8][4];
    #pragma unroll
    for (int nt = 0; nt < 8; nt++)
        #pragma unroll
        for (int j = 0; j < 4; j++) oacc[nt][j] = 0.f;
    float mrow0 = -1e30f, mrow1 = -1e30f, lrow0 = 0.f, lrow1 = 0.f;

    const unsigned* KtG = g_KtP + ((size_t)bh * 32 + (tid >> 3)) * KTPITCH + (tid & 7) * 8;
    const int vjj = tid >> 3;
    const int vdw = (tid & 7) * 4;
    const unsigned* VgBase = g_VP + (size_t)bh * VROWS * 32;

    for (int kt = 0; kt < ANT; kt++) {
        const int kvbase = kt * ABK;
        __syncthreads();

        // ---- Kt fill: straight copy ----
        {
            uint4 w0 = *(const uint4*)(KtG + kvbase);
            uint4 w1 = *(const uint4*)(KtG + kvbase + 4);
            unsigned* dst = &KtH[(tid >> 3) * KTLD + (tid & 7) * 8];
            *(uint4*)dst       = w0;
            *(uint4*)(dst + 4) = w1;
        }
        // ---- V fill: 2 loads + prmt interleave (j-pair packing) ----
        {
            const unsigned* va = VgBase + (size_t)(kvbase + 2 * vjj) * 32 + vdw;
            uint4 A4 = *(const uint4*)va;
            uint4 B4 = *(const uint4*)(va + 32);
            unsigned* dst = &VH[vjj * VLD + 2 * vdw];
            uint4 o0, o1;
            o0.x = prmt(A4.x, B4.x, 0x5410); o0.y = prmt(A4.x, B4.x, 0x7632);
            o0.z = prmt(A4.y, B4.y, 0x5410); o0.w = prmt(A4.y, B4.y, 0x7632);
            o1.x = prmt(A4.z, B4.z, 0x5410); o1.y = prmt(A4.z, B4.z, 0x7632);
            o1.z = prmt(A4.w, B4.w, 0x5410); o1.w = prmt(A4.w, B4.w, 0x7632);
            *(uint4*)dst       = o0;
            *(uint4*)(dst + 4) = o1;
        }
        __syncthreads();

        // ---- S = Q K^T (fp16 2-pass) ----
        float sa[8][4];
        #pragma unroll
        for (int nt = 0; nt < 8; nt++)
            #pragma unroll
            for (int j = 0; j < 4; j++) sa[nt][j] = 0.f;

        #pragma unroll
        for (int s = 0; s < 4; s++) {
            #pragma unroll
            for (int nt = 0; nt < 8; nt++) {
                unsigned bfh[2];
                bfh[0] = KtH[(8 * s + c) * KTLD + nt * 8 + r];
                bfh[1] = KtH[(8 * s + c + 4) * KTLD + nt * 8 + r];
                mma_f16(sa[nt], qhi[s], bfh);
                mma_f16(sa[nt], qlo[s], bfh);
            }
        }

        // ---- mask + online softmax -> P fragments in registers ----
        float tmax0 = -1e30f, tmax1 = -1e30f;
        #pragma unroll
        for (int nt = 0; nt < 8; nt++) {
            const int j0 = kvbase + nt * 8 + 2 * c;
            if (j0 >= KVLEN)     { sa[nt][0] = -1e30f; sa[nt][2] = -1e30f; }
            if (j0 + 1 >= KVLEN) { sa[nt][1] = -1e30f; sa[nt][3] = -1e30f; }
            tmax0 = fmaxf(tmax0, fmaxf(sa[nt][0], sa[nt][1]));
            tmax1 = fmaxf(tmax1, fmaxf(sa[nt][2], sa[nt][3]));
        }
        tmax0 = fmaxf(tmax0, __shfl_xor_sync(0xFFFFFFFFu, tmax0, 1));
        tmax0 = fmaxf(tmax0, __shfl_xor_sync(0xFFFFFFFFu, tmax0, 2));
        tmax1 = fmaxf(tmax1, __shfl_xor_sync(0xFFFFFFFFu, tmax1, 1));
        tmax1 = fmaxf(tmax1, __shfl_xor_sync(0xFFFFFFFFu, tmax1, 2));

        const float mnew0 = fmaxf(mrow0, tmax0);
        const float mnew1 = fmaxf(mrow1, tmax1);
        const float cf0 = __expf(mrow0 - mnew0);
        const float cf1 = __expf(mrow1 - mnew1);
        mrow0 = mnew0; mrow1 = mnew1;

        unsigned pfrag[8][2];
        float psum0 = 0.f, psum1 = 0.f;
        #pragma unroll
        for (int nt = 0; nt < 8; nt++) {
            const float p0 = __expf(sa[nt][0] - mnew0);
            const float p1 = __expf(sa[nt][1] - mnew0);
            const float p2 = __expf(sa[nt][2] - mnew1);
            const float p3 = __expf(sa[nt][3] - mnew1);
            psum0 += p0 + p1;
            psum1 += p2 + p3;
            pfrag[nt][0] = pack2(p0, p1);   // row r,   j-pair nt*4+c
            pfrag[nt][1] = pack2(p2, p3);   // row r+8, j-pair nt*4+c
        }
        psum0 += __shfl_xor_sync(0xFFFFFFFFu, psum0, 1);
        psum0 += __shfl_xor_sync(0xFFFFFFFFu, psum0, 2);
        psum1 += __shfl_xor_sync(0xFFFFFFFFu, psum1, 1);
        psum1 += __shfl_xor_sync(0xFFFFFFFFu, psum1, 2);
        lrow0 = lrow0 * cf0 + psum0;
        lrow1 = lrow1 * cf1 + psum1;

        #pragma unroll
        for (int nt = 0; nt < 8; nt++) {
            oacc[nt][0] *= cf0; oacc[nt][1] *= cf0;
            oacc[nt][2] *= cf1; oacc[nt][3] *= cf1;
        }

        // ---- O += P V (single pass; P a-frags straight from registers) ----
        #pragma unroll
        for (int s = 0; s < 4; s++) {
            unsigned pa[4];
            pa[0] = pfrag[2 * s][0];
            pa[1] = pfrag[2 * s][1];
            pa[2] = pfrag[2 * s + 1][0];
            pa[3] = pfrag[2 * s + 1][1];
            #pragma unroll
            for (int nt = 0; nt < 8; nt++) {
                unsigned vfh[2];
                vfh[0] = VH[(8 * s + c) * VLD + nt * 8 + r];
                vfh[1] = VH[(8 * s + c + 4) * VLD + nt * 8 + r];
                mma_f16(oacc[nt], pa, vfh);
            }
        }
    }

    // ---- epilogue: write packed fp16 for gemm_o ----
    const float li0 = 1.f / lrow0;
    const float li1 = 1.f / lrow1;
    const int bb = bh >> 4, h = bh & 15;
    const int row0 = qt * ABQ + m0 + r;
    #pragma unroll
    for (int nt = 0; nt < 8; nt++) {
        const size_t wi0 = (size_t)(bb * SEQ + row0) * (INNER / 2) + h * 32 + nt * 4 + c;
        const size_t wi1 = (size_t)(bb * SEQ + row0 + 8) * (INNER / 2) + h * 32 + nt * 4 + c;
        g_aoH[wi0] = pack2(oacc[nt][0] * li0, oacc[nt][1] * li0);
        g_aoH[wi1] = pack2(oacc[nt][2] * li1, oacc[nt][3] * li1);
    }
}

// ---------------- launch ------------------------------------------------------
extern "C" void kernel_launch(void* const* d_in, const int* in_sizes, int n_in,
                              void* d_out, int out_size) {
    const float* x       = (const float*)d_in[0];
    const float* gamma   = (const float*)d_in[1];
    const float* beta    = (const float*)d_in[2];
    const float* null_kv = (const float*)d_in[3];
    const float* Wq      = (const float*)d_in[4];
    const float* Wkv     = (const float*)d_in[5];
    const float* q_scale = (const float*)d_in[6];
    const float* k_scale = (const float*)d_in[7];
    const float* Wo      = (const float*)d_in[8];
    float* out = (float*)d_out;

    unsigned* wqp, *wkvp, *wop;
    cudaGetSymbolAddress((void**)&wqp,  g_WqP);
    cudaGetSymbolAddress((void**)&wkvp, g_WkvP);
    cudaGetSymbolAddress((void**)&wop,  g_WoP);

    cudaFuncSetAttribute(gemm_q_kernel,  cudaFuncAttributeMaxDynamicSharedMemorySize, GEMM_SMEM);
    cudaFuncSetAttribute(gemm_kv_kernel, cudaFuncAttributeMaxDynamicSharedMemorySize, GEMM_SMEM);
    cudaFuncSetAttribute(gemm_o_kernel,  cudaFuncAttributeMaxDynamicSharedMemorySize, GEMM_SMEM);
    cudaFuncSetAttribute(attn_mma_kernel, cudaFuncAttributeMaxDynamicSharedMemorySize, ATT_SMEM);

    pack_w<<<512, 256>>>(Wq,  wqp,  DIM,   INNER);
    pack_w<<<512, 256>>>(Wkv, wkvp, DIM,   2 * INNER);
    pack_w<<<512, 256>>>(Wo,  wop,  INNER, DIM);
    ln_kernel<<<TOKENS, 256>>>(x, gamma, beta);
    gemm_q_kernel <<<dim3(INNER / 128,     TOKENS / 128), 256, GEMM_SMEM>>>();
    gemm_kv_kernel<<<dim3(2 * INNER / 128, TOKENS / 128), 256, GEMM_SMEM>>>();
    qkv_prep<<<(TOKENS * HEADS) / 8, 256>>>(q_scale, k_scale);
    null_prep<<<BATCH * HEADS, 32>>>(null_kv, k_scale);
    attn_mma_kernel<<<dim3(SEQ / ABQ, BATCH * HEADS), 256, ATT_SMEM>>>();
    gemm_o_kernel<<<dim3(DIM / 128, TOKENS / 128), 256, GEMM_SMEM>>>(out);
}

// round 10
// speedup vs baseline: 9.4601x; 1.1082x over previous
#include <cuda_runtime.h>
#include <cuda_fp16.h>
#include <math.h>

#define HEADS   16
#define DHEAD   64
#define BATCH   4
#define SEQ     2048
#define DIM     1024
#define INNER   1024
#define TOKENS  (BATCH*SEQ)       /* 8192 */
#define KVLEN   (SEQ+1)           /* 2049 */
#define SCALE_F 8.0f
#define LN_EPS  1e-5f
#define L2_EPS  1e-12f

#define KTPITCH 2112   /* words per (bh,dd) row of packed-transposed K; zero-init pad */
#define VROWS   2112   /* padded j rows of packed V */

// ---------------- scratch (global device arrays; no allocations) -------------
__device__ unsigned g_xnH [TOKENS * DIM / 2];     // LN out, packed fp16
__device__ unsigned g_WqP [(DIM / 2) * INNER];
__device__ unsigned g_WkvP[(DIM / 2) * 2 * INNER];
__device__ unsigned g_WoP [(INNER / 2) * DIM];
__device__ float    g_kvlin[TOKENS * 2 * INNER];
__device__ unsigned g_QP   [64 * SEQ * 32];       // [bh][i][dw] packed fp16 d-pairs
__device__ unsigned g_KtP  [64 * 32 * KTPITCH];   // [bh][dd][j]
__device__ unsigned g_VP   [64 * VROWS * 32];     // [bh][j][dw]
__device__ unsigned g_aoH  [TOKENS * INNER / 2];  // attention out, packed fp16

// ---------------- fp16 helpers --------------------------------------------------
__device__ __forceinline__ void mma_f16(float* c, const unsigned* a, const unsigned* b) {
    asm volatile(
        "mma.sync.aligned.m16n8k16.row.col.f32.f16.f16.f32 "
        "{%0,%1,%2,%3}, {%4,%5,%6,%7}, {%8,%9}, {%0,%1,%2,%3};"
        : "+f"(c[0]), "+f"(c[1]), "+f"(c[2]), "+f"(c[3])
        : "r"(a[0]), "r"(a[1]), "r"(a[2]), "r"(a[3]), "r"(b[0]), "r"(b[1]));
}
__device__ __forceinline__ unsigned pack2(float a, float b) {
    __half2 h2 = __floats2half2_rn(a, b);
    return *(unsigned*)&h2;
}
__device__ __forceinline__ unsigned prmt(unsigned a, unsigned b, unsigned sel) {
    unsigned d;
    asm("prmt.b32 %0, %1, %2, %3;" : "=r"(d) : "r"(a), "r"(b), "r"(sel));
    return d;
}

// ---------------- LayerNorm (writes packed fp16) --------------------------------
__global__ void __launch_bounds__(256) ln_kernel(const float* __restrict__ x,
                                                 const float* __restrict__ gamma,
                                                 const float* __restrict__ beta) {
    __shared__ float red[8][2];
    const int t = blockIdx.x;
    const int i = threadIdx.x;
    const float4 v = ((const float4*)(x + (size_t)t * DIM))[i];
    float s  = v.x + v.y + v.z + v.w;
    float ss = v.x*v.x + v.y*v.y + v.z*v.z + v.w*v.w;
    #pragma unroll
    for (int o = 16; o > 0; o >>= 1) {
        s  += __shfl_xor_sync(0xFFFFFFFFu, s,  o);
        ss += __shfl_xor_sync(0xFFFFFFFFu, ss, o);
    }
    const int w = i >> 5, l = i & 31;
    if (l == 0) { red[w][0] = s; red[w][1] = ss; }
    __syncthreads();
    if (w == 0) {
        s  = (l < 8) ? red[l][0] : 0.f;
        ss = (l < 8) ? red[l][1] : 0.f;
        #pragma unroll
        for (int o = 4; o > 0; o >>= 1) {
            s  += __shfl_xor_sync(0xFFFFFFFFu, s,  o);
            ss += __shfl_xor_sync(0xFFFFFFFFu, ss, o);
        }
        if (l == 0) { red[0][0] = s; red[0][1] = ss; }
    }
    __syncthreads();
    const float mu   = red[0][0] * (1.f / DIM);
    const float var  = red[0][1] * (1.f / DIM) - mu * mu;
    const float rstd = rsqrtf(var + LN_EPS);
    const float4 g  = ((const float4*)gamma)[i];
    const float4 be = ((const float4*)beta)[i];
    float4 o4;
    o4.x = (v.x - mu) * rstd * g.x + be.x;
    o4.y = (v.y - mu) * rstd * g.y + be.y;
    o4.z = (v.z - mu) * rstd * g.z + be.z;
    o4.w = (v.w - mu) * rstd * g.w + be.w;
    const size_t wi = (size_t)t * (DIM / 2) + 2 * i;
    *(uint2*)&g_xnH[wi] = make_uint2(pack2(o4.x, o4.y), pack2(o4.z, o4.w));
}

// ---------------- weight packing: W[K][N] fp32 -> WP[K/2][N] f16x2 -------------
__global__ void __launch_bounds__(256) pack_w(const float* __restrict__ W,
                                              unsigned* __restrict__ WP,
                                              int K, int N) {
    const int total = (K / 2) * N;
    for (int idx = blockIdx.x * 256 + threadIdx.x; idx < total; idx += gridDim.x * 256) {
        const int kp = idx / N;
        const int n  = idx - kp * N;
        WP[idx] = pack2(W[(size_t)(2 * kp) * N + n], W[(size_t)(2 * kp + 1) * N + n]);
    }
}

// ---------------- fp16 single-pass GEMM mainloop (macro-shared) ----------------
#define ASLD 20
#define BSLD 136
#define GSTAGE_W (128 * ASLD + 16 * BSLD)     /* 4736 words */
#define GEMM_SMEM (2 * GSTAGE_W * 4)          /* 37888 B */

#define GEMM_MAINLOOP(AH, BP, N, K)                                               \
    extern __shared__ unsigned gsm[];                                             \
    const int tid  = threadIdx.x;                                                 \
    const int warp = tid >> 5;                                                    \
    const int lane = tid & 31;                                                    \
    const int r = lane >> 2;                                                      \
    const int c = lane & 3;                                                       \
    const int wm = (warp & 3) * 32;                                               \
    const int wn = (warp >> 2) * 64;                                              \
    const int rowBase = blockIdx.y * 128;                                         \
    const int colBase = blockIdx.x * 128;                                         \
    const int arow = tid >> 1;                                                    \
    const int asel = (tid & 1) * 8;                                               \
    const int bkp  = tid >> 4;                                                    \
    const int bn0  = (tid & 15) * 8;                                              \
    const unsigned* ApH = (AH) + (size_t)(rowBase + arow) * ((K) / 2) + asel;     \
    const unsigned* BpP = (BP) + colBase + bn0;                                   \
    float acc[2][8][4];                                                           \
    _Pragma("unroll")                                                             \
    for (int mi = 0; mi < 2; mi++)                                                \
        _Pragma("unroll")                                                         \
        for (int ni = 0; ni < 8; ni++)                                            \
            _Pragma("unroll")                                                     \
            for (int j = 0; j < 4; j++) acc[mi][ni][j] = 0.f;                     \
    const int NC = (K) / 32;                                                      \
    auto fill = [&](int ck) {                                                     \
        unsigned* st  = gsm + (ck & 1) * GSTAGE_W;                                \
        unsigned* AsH = st;                                                       \
        unsigned* Bs  = st + 128 * ASLD;                                          \
        const int kw = ck * 16;                                                   \
        uint4 h0 = *(const uint4*)(ApH + kw);                                     \
        uint4 h1 = *(const uint4*)(ApH + kw + 4);                                 \
        unsigned* ad = &AsH[arow * ASLD + asel];                                  \
        *(uint4*)ad       = h0;                                                   \
        *(uint4*)(ad + 4) = h1;                                                   \
        const unsigned* bp = BpP + (size_t)(kw + bkp) * (N);                      \
        uint4 b0 = *(const uint4*)bp;                                             \
        uint4 b1 = *(const uint4*)(bp + 4);                                       \
        unsigned* bd = &Bs[bkp * BSLD + bn0];                                     \
        *(uint4*)bd       = b0;                                                   \
        *(uint4*)(bd + 4) = b1;                                                   \
    };                                                                            \
    fill(0);                                                                      \
    __syncthreads();                                                              \
    _Pragma("unroll 1")                                                           \
    for (int ck = 0; ck < NC; ck++) {                                             \
        if (ck + 1 < NC) fill(ck + 1);                                            \
        const unsigned* st  = gsm + (ck & 1) * GSTAGE_W;                          \
        const unsigned* AsH = st;                                                 \
        const unsigned* Bs  = st + 128 * ASLD;                                    \
        _Pragma("unroll")                                                         \
        for (int s = 0; s < 2; s++) {                                             \
            unsigned ah[2][4];                                                    \
            _Pragma("unroll")                                                     \
            for (int mi = 0; mi < 2; mi++) {                                      \
                const int row = wm + mi * 16;                                     \
                ah[mi][0] = AsH[(row + r) * ASLD + 8 * s + c];                    \
                ah[mi][1] = AsH[(row + 8 + r) * ASLD + 8 * s + c];                \
                ah[mi][2] = AsH[(row + r) * ASLD + 8 * s + c + 4];                \
                ah[mi][3] = AsH[(row + 8 + r) * ASLD + 8 * s + c + 4];            \
            }                                                                     \
            _Pragma("unroll")                                                     \
            for (int ni = 0; ni < 8; ni++) {                                      \
                unsigned bf[2];                                                   \
                bf[0] = Bs[(8 * s + c) * BSLD + wn + ni * 8 + r];                 \
                bf[1] = Bs[(8 * s + c + 4) * BSLD + wn + ni * 8 + r];             \
                _Pragma("unroll")                                                 \
                for (int mi = 0; mi < 2; mi++)                                    \
                    mma_f16(acc[mi][ni], ah[mi], bf);                             \
            }                                                                     \
        }                                                                         \
        __syncthreads();                                                          \
    }

// ---- generic fp32 epilogue GEMM (kv, o) ----
template <int N, int K>
__device__ __forceinline__ void gemm_f16_body(const unsigned* __restrict__ AH,
                                              const unsigned* __restrict__ BP,
                                              float* __restrict__ C) {
    GEMM_MAINLOOP(AH, BP, N, K)
    #pragma unroll
    for (int mi = 0; mi < 2; mi++) {
        const int row = rowBase + wm + mi * 16 + r;
        #pragma unroll
        for (int ni = 0; ni < 8; ni++) {
            const int col = colBase + wn + ni * 8 + 2 * c;
            *(float2*)&C[(size_t)row * N + col]       = make_float2(acc[mi][ni][0], acc[mi][ni][1]);
            *(float2*)&C[(size_t)(row + 8) * N + col] = make_float2(acc[mi][ni][2], acc[mi][ni][3]);
        }
    }
}

// ---- gemm_q with fused l2norm + q_scale + SCALE -> packed fp16 g_QP -----------
__global__ void __launch_bounds__(256, 2) gemm_q_kernel(const float* __restrict__ q_scale) {
    GEMM_MAINLOOP(g_xnH, g_WqP, INNER, DIM)
    // warp N-tile = 64 cols = exactly one head
    const int h = (colBase + wn) >> 6;
    #pragma unroll
    for (int mi = 0; mi < 2; mi++) {
        const int row0 = rowBase + wm + mi * 16 + r;   // token of acc[..][0..1]
        // sum of squares across the head (per row-half)
        float ss0 = 0.f, ss1 = 0.f;
        #pragma unroll
        for (int ni = 0; ni < 8; ni++) {
            ss0 += acc[mi][ni][0] * acc[mi][ni][0] + acc[mi][ni][1] * acc[mi][ni][1];
            ss1 += acc[mi][ni][2] * acc[mi][ni][2] + acc[mi][ni][3] * acc[mi][ni][3];
        }
        ss0 += __shfl_xor_sync(0xFFFFFFFFu, ss0, 1);
        ss0 += __shfl_xor_sync(0xFFFFFFFFu, ss0, 2);
        ss1 += __shfl_xor_sync(0xFFFFFFFFu, ss1, 1);
        ss1 += __shfl_xor_sync(0xFFFFFFFFu, ss1, 2);
        const float f0 = SCALE_F / fmaxf(sqrtf(ss0), L2_EPS);
        const float f1 = SCALE_F / fmaxf(sqrtf(ss1), L2_EPS);
        #pragma unroll
        for (int ni = 0; ni < 8; ni++) {
            const int d = ni * 8 + 2 * c;
            const float2 qs = *(const float2*)&q_scale[d];
            const int bb0 = row0 >> 11, i0 = row0 & 2047;
            const int bb1 = (row0 + 8) >> 11, i1 = (row0 + 8) & 2047;
            g_QP[((size_t)(bb0 * HEADS + h) * SEQ + i0) * 32 + ni * 4 + c] =
                pack2(acc[mi][ni][0] * f0 * qs.x, acc[mi][ni][1] * f0 * qs.y);
            g_QP[((size_t)(bb1 * HEADS + h) * SEQ + i1) * 32 + ni * 4 + c] =
                pack2(acc[mi][ni][2] * f1 * qs.x, acc[mi][ni][3] * f1 * qs.y);
        }
    }
}

__global__ void __launch_bounds__(256, 2) gemm_kv_kernel() {
    gemm_f16_body<2 * INNER, DIM>(g_xnH, g_WkvP, g_kvlin);
}
__global__ void __launch_bounds__(256, 2) gemm_o_kernel(float* __restrict__ out) {
    gemm_f16_body<DIM, INNER>(g_aoH, g_WoP, out);
}

// ---------------- k/v split + l2norm + packed fp16 ------------------------------
__global__ void __launch_bounds__(256) kv_prep(const float* __restrict__ k_scale) {
    const int gw   = (blockIdx.x * 256 + threadIdx.x) >> 5;
    const int lane = threadIdx.x & 31;
    if (gw >= TOKENS * HEADS) return;
    const int t = gw >> 4;
    const int h = gw & 15;
    const int bb = t >> 11;
    const int i = t & 2047;
    const int bh = bb * HEADS + h;
    const int src0 = (2 * lane) & 31;
    const int src1 = (2 * lane + 1) & 31;

    const float* kr = g_kvlin + (size_t)t * (2 * INNER) + h * DHEAD;
    float k0 = kr[lane], k1 = kr[lane + 32];
    float ss = k0 * k0 + k1 * k1;
    #pragma unroll
    for (int o = 16; o > 0; o >>= 1) ss += __shfl_xor_sync(0xFFFFFFFFu, ss, o);
    const float inv = 1.f / fmaxf(sqrtf(ss), L2_EPS);
    const float kk0 = k0 * inv * k_scale[lane];
    const float kk1 = k1 * inv * k_scale[lane + 32];
    {
        float s0a = __shfl_sync(0xFFFFFFFFu, kk0, src0);
        float s0b = __shfl_sync(0xFFFFFFFFu, kk0, src1);
        float s1a = __shfl_sync(0xFFFFFFFFu, kk1, src0);
        float s1b = __shfl_sync(0xFFFFFFFFu, kk1, src1);
        const float a = (lane < 16) ? s0a : s1a;
        const float b = (lane < 16) ? s0b : s1b;
        g_KtP[((size_t)bh * 32 + lane) * KTPITCH + i + 1] = pack2(a, b);
    }

    const float* vr = g_kvlin + (size_t)t * (2 * INNER) + INNER + h * DHEAD;
    const float v0 = vr[lane], v1 = vr[lane + 32];
    {
        float s0a = __shfl_sync(0xFFFFFFFFu, v0, src0);
        float s0b = __shfl_sync(0xFFFFFFFFu, v0, src1);
        float s1a = __shfl_sync(0xFFFFFFFFu, v1, src0);
        float s1b = __shfl_sync(0xFFFFFFFFu, v1, src1);
        const float a = (lane < 16) ? s0a : s1a;
        const float b = (lane < 16) ? s0b : s1b;
        g_VP[((size_t)bh * VROWS + i + 1) * 32 + lane] = pack2(a, b);
    }
}

__global__ void null_prep(const float* __restrict__ null_kv,
                          const float* __restrict__ k_scale) {
    const int bh = blockIdx.x;
    const int h = bh & 15;
    const int lane = threadIdx.x;
    const int src0 = (2 * lane) & 31;
    const int src1 = (2 * lane + 1) & 31;
    const float* nk = null_kv + h * DHEAD;
    const float* nv = null_kv + HEADS * DHEAD + h * DHEAD;
    float k0 = nk[lane], k1 = nk[lane + 32];
    float ss = k0 * k0 + k1 * k1;
    #pragma unroll
    for (int o = 16; o > 0; o >>= 1) ss += __shfl_xor_sync(0xFFFFFFFFu, ss, o);
    const float inv = 1.f / fmaxf(sqrtf(ss), L2_EPS);
    const float kk0 = k0 * inv * k_scale[lane];
    const float kk1 = k1 * inv * k_scale[lane + 32];
    {
        float s0a = __shfl_sync(0xFFFFFFFFu, kk0, src0);
        float s0b = __shfl_sync(0xFFFFFFFFu, kk0, src1);
        float s1a = __shfl_sync(0xFFFFFFFFu, kk1, src0);
        float s1b = __shfl_sync(0xFFFFFFFFu, kk1, src1);
        const float a = (lane < 16) ? s0a : s1a;
        const float b = (lane < 16) ? s0b : s1b;
        g_KtP[((size_t)bh * 32 + lane) * KTPITCH] = pack2(a, b);
    }
    const float v0 = nv[lane], v1 = nv[lane + 32];
    {
        float s0a = __shfl_sync(0xFFFFFFFFu, v0, src0);
        float s0b = __shfl_sync(0xFFFFFFFFu, v0, src1);
        float s1a = __shfl_sync(0xFFFFFFFFu, v1, src0);
        float s1b = __shfl_sync(0xFFFFFFFFu, v1, src1);
        const float a = (lane < 16) ? s0a : s1a;
        const float b = (lane < 16) ? s0b : s1b;
        g_VP[(size_t)bh * VROWS * 32 + lane] = pack2(a, b);
    }
}

// ---------------- flash attention: all single-pass fp16, P in registers --------
#define ABQ 128
#define ABK 64
#define ANT ((KVLEN + ABK - 1) / ABK)   /* 33 */
#define KTLD 72
#define VLD  72

#define ATT_SMEM ((32*KTLD + 32*VLD) * 4)   /* 18432 B */

__global__ void __launch_bounds__(256, 2) attn_mma_kernel() {
    extern __shared__ unsigned ash[];
    unsigned* KtH = ash;
    unsigned* VH  = KtH + 32 * KTLD;

    const int tid  = threadIdx.x;
    const int warp = tid >> 5;
    const int lane = tid & 31;
    const int r = lane >> 2;
    const int c = lane & 3;
    const int bh = blockIdx.y;
    const int qt = blockIdx.x;
    const int m0 = warp * 16;

    // ---- Q fragments: direct packed fp16 loads ----
    const unsigned* QgP = g_QP + ((size_t)bh * SEQ + (size_t)qt * ABQ + m0) * 32;
    unsigned qh[4][4];
    #pragma unroll
    for (int s = 0; s < 4; s++) {
        qh[s][0] = QgP[(size_t)r * 32 + s * 8 + c];
        qh[s][1] = QgP[(size_t)(r + 8) * 32 + s * 8 + c];
        qh[s][2] = QgP[(size_t)r * 32 + s * 8 + c + 4];
        qh[s][3] = QgP[(size_t)(r + 8) * 32 + s * 8 + c + 4];
    }

    float oacc[8][4];
    #pragma unroll
    for (int nt = 0; nt < 8; nt++)
        #pragma unroll
        for (int j = 0; j < 4; j++) oacc[nt][j] = 0.f;
    float mrow0 = -1e30f, mrow1 = -1e30f, lrow0 = 0.f, lrow1 = 0.f;

    const unsigned* KtG = g_KtP + ((size_t)bh * 32 + (tid >> 3)) * KTPITCH + (tid & 7) * 8;
    const int vjj = tid >> 3;
    const int vdw = (tid & 7) * 4;
    const unsigned* VgBase = g_VP + (size_t)bh * VROWS * 32;

    for (int kt = 0; kt < ANT; kt++) {
        const int kvbase = kt * ABK;
        __syncthreads();

        {
            uint4 w0 = *(const uint4*)(KtG + kvbase);
            uint4 w1 = *(const uint4*)(KtG + kvbase + 4);
            unsigned* dst = &KtH[(tid >> 3) * KTLD + (tid & 7) * 8];
            *(uint4*)dst       = w0;
            *(uint4*)(dst + 4) = w1;
        }
        {
            const unsigned* va = VgBase + (size_t)(kvbase + 2 * vjj) * 32 + vdw;
            uint4 A4 = *(const uint4*)va;
            uint4 B4 = *(const uint4*)(va + 32);
            unsigned* dst = &VH[vjj * VLD + 2 * vdw];
            uint4 o0, o1;
            o0.x = prmt(A4.x, B4.x, 0x5410); o0.y = prmt(A4.x, B4.x, 0x7632);
            o0.z = prmt(A4.y, B4.y, 0x5410); o0.w = prmt(A4.y, B4.y, 0x7632);
            o1.x = prmt(A4.z, B4.z, 0x5410); o1.y = prmt(A4.z, B4.z, 0x7632);
            o1.z = prmt(A4.w, B4.w, 0x5410); o1.w = prmt(A4.w, B4.w, 0x7632);
            *(uint4*)dst       = o0;
            *(uint4*)(dst + 4) = o1;
        }
        __syncthreads();

        // ---- S = Q K^T (single-pass fp16) ----
        float sa[8][4];
        #pragma unroll
        for (int nt = 0; nt < 8; nt++)
            #pragma unroll
            for (int j = 0; j < 4; j++) sa[nt][j] = 0.f;

        #pragma unroll
        for (int s = 0; s < 4; s++) {
            #pragma unroll
            for (int nt = 0; nt < 8; nt++) {
                unsigned bfh[2];
                bfh[0] = KtH[(8 * s + c) * KTLD + nt * 8 + r];
                bfh[1] = KtH[(8 * s + c + 4) * KTLD + nt * 8 + r];
                mma_f16(sa[nt], qh[s], bfh);
            }
        }

        // ---- mask + online softmax -> P fragments in registers ----
        float tmax0 = -1e30f, tmax1 = -1e30f;
        #pragma unroll
        for (int nt = 0; nt < 8; nt++) {
            const int j0 = kvbase + nt * 8 + 2 * c;
            if (j0 >= KVLEN)     { sa[nt][0] = -1e30f; sa[nt][2] = -1e30f; }
            if (j0 + 1 >= KVLEN) { sa[nt][1] = -1e30f; sa[nt][3] = -1e30f; }
            tmax0 = fmaxf(tmax0, fmaxf(sa[nt][0], sa[nt][1]));
            tmax1 = fmaxf(tmax1, fmaxf(sa[nt][2], sa[nt][3]));
        }
        tmax0 = fmaxf(tmax0, __shfl_xor_sync(0xFFFFFFFFu, tmax0, 1));
        tmax0 = fmaxf(tmax0, __shfl_xor_sync(0xFFFFFFFFu, tmax0, 2));
        tmax1 = fmaxf(tmax1, __shfl_xor_sync(0xFFFFFFFFu, tmax1, 1));
        tmax1 = fmaxf(tmax1, __shfl_xor_sync(0xFFFFFFFFu, tmax1, 2));

        const float mnew0 = fmaxf(mrow0, tmax0);
        const float mnew1 = fmaxf(mrow1, tmax1);
        const float cf0 = __expf(mrow0 - mnew0);
        const float cf1 = __expf(mrow1 - mnew1);
        mrow0 = mnew0; mrow1 = mnew1;

        unsigned pfrag[8][2];
        float psum0 = 0.f, psum1 = 0.f;
        #pragma unroll
        for (int nt = 0; nt < 8; nt++) {
            const float p0 = __expf(sa[nt][0] - mnew0);
            const float p1 = __expf(sa[nt][1] - mnew0);
            const float p2 = __expf(sa[nt][2] - mnew1);
            const float p3 = __expf(sa[nt][3] - mnew1);
            psum0 += p0 + p1;
            psum1 += p2 + p3;
            pfrag[nt][0] = pack2(p0, p1);
            pfrag[nt][1] = pack2(p2, p3);
        }
        psum0 += __shfl_xor_sync(0xFFFFFFFFu, psum0, 1);
        psum0 += __shfl_xor_sync(0xFFFFFFFFu, psum0, 2);
        psum1 += __shfl_xor_sync(0xFFFFFFFFu, psum1, 1);
        psum1 += __shfl_xor_sync(0xFFFFFFFFu, psum1, 2);
        lrow0 = lrow0 * cf0 + psum0;
        lrow1 = lrow1 * cf1 + psum1;

        #pragma unroll
        for (int nt = 0; nt < 8; nt++) {
            oacc[nt][0] *= cf0; oacc[nt][1] *= cf0;
            oacc[nt][2] *= cf1; oacc[nt][3] *= cf1;
        }

        // ---- O += P V (single pass) ----
        #pragma unroll
        for (int s = 0; s < 4; s++) {
            unsigned pa[4];
            pa[0] = pfrag[2 * s][0];
            pa[1] = pfrag[2 * s][1];
            pa[2] = pfrag[2 * s + 1][0];
            pa[3] = pfrag[2 * s + 1][1];
            #pragma unroll
            for (int nt = 0; nt < 8; nt++) {
                unsigned vfh[2];
                vfh[0] = VH[(8 * s + c) * VLD + nt * 8 + r];
                vfh[1] = VH[(8 * s + c + 4) * VLD + nt * 8 + r];
                mma_f16(oacc[nt], pa, vfh);
            }
        }
    }

    // ---- epilogue: write packed fp16 for gemm_o ----
    const float li0 = 1.f / lrow0;
    const float li1 = 1.f / lrow1;
    const int bb = bh >> 4, h = bh & 15;
    const int row0 = qt * ABQ + m0 + r;
    #pragma unroll
    for (int nt = 0; nt < 8; nt++) {
        const size_t wi0 = (size_t)(bb * SEQ + row0) * (INNER / 2) + h * 32 + nt * 4 + c;
        const size_t wi1 = (size_t)(bb * SEQ + row0 + 8) * (INNER / 2) + h * 32 + nt * 4 + c;
        g_aoH[wi0] = pack2(oacc[nt][0] * li0, oacc[nt][1] * li0);
        g_aoH[wi1] = pack2(oacc[nt][2] * li1, oacc[nt][3] * li1);
    }
}

// ---------------- launch ------------------------------------------------------
extern "C" void kernel_launch(void* const* d_in, const int* in_sizes, int n_in,
                              void* d_out, int out_size) {
    const float* x       = (const float*)d_in[0];
    const float* gamma   = (const float*)d_in[1];
    const float* beta    = (const float*)d_in[2];
    const float* null_kv = (const float*)d_in[3];
    const float* Wq      = (const float*)d_in[4];
    const float* Wkv     = (const float*)d_in[5];
    const float* q_scale = (const float*)d_in[6];
    const float* k_scale = (const float*)d_in[7];
    const float* Wo      = (const float*)d_in[8];
    float* out = (float*)d_out;

    unsigned* wqp, *wkvp, *wop;
    cudaGetSymbolAddress((void**)&wqp,  g_WqP);
    cudaGetSymbolAddress((void**)&wkvp, g_WkvP);
    cudaGetSymbolAddress((void**)&wop,  g_WoP);

    cudaFuncSetAttribute(gemm_q_kernel,  cudaFuncAttributeMaxDynamicSharedMemorySize, GEMM_SMEM);
    cudaFuncSetAttribute(gemm_kv_kernel, cudaFuncAttributeMaxDynamicSharedMemorySize, GEMM_SMEM);
    cudaFuncSetAttribute(gemm_o_kernel,  cudaFuncAttributeMaxDynamicSharedMemorySize, GEMM_SMEM);
    cudaFuncSetAttribute(attn_mma_kernel, cudaFuncAttributeMaxDynamicSharedMemorySize, ATT_SMEM);

    pack_w<<<512, 256>>>(Wq,  wqp,  DIM,   INNER);
    pack_w<<<512, 256>>>(Wkv, wkvp, DIM,   2 * INNER);
    pack_w<<<512, 256>>>(Wo,  wop,  INNER, DIM);
    ln_kernel<<<TOKENS, 256>>>(x, gamma, beta);
    gemm_q_kernel <<<dim3(INNER / 128,     TOKENS / 128), 256, GEMM_SMEM>>>(q_scale);
    gemm_kv_kernel<<<dim3(2 * INNER / 128, TOKENS / 128), 256, GEMM_SMEM>>>();
    kv_prep<<<(TOKENS * HEADS) / 8, 256>>>(k_scale);
    null_prep<<<BATCH * HEADS, 32>>>(null_kv, k_scale);
    attn_mma_kernel<<<dim3(SEQ / ABQ, BATCH * HEADS), 256, ATT_SMEM>>>();
    gemm_o_kernel<<<dim3(DIM / 128, TOKENS / 128), 256, GEMM_SMEM>>>(out);
}

// round 11
// speedup vs baseline: 10.1563x; 1.0736x over previous
#include <cuda_runtime.h>
#include <cuda_fp16.h>
#include <math.h>

#define HEADS   16
#define DHEAD   64
#define BATCH   4
#define SEQ     2048
#define DIM     1024
#define INNER   1024
#define TOKENS  (BATCH*SEQ)       /* 8192 */
#define KVLEN   (SEQ+1)           /* 2049 */
#define SCALE_F 8.0f
#define LN_EPS  1e-5f
#define L2_EPS  1e-12f

#define NQKV    (3 * INNER)       /* 3072 fused projection width */
#define KTPITCH 2112
#define VROWS   2112

// ---------------- scratch (global device arrays; no allocations) -------------
__device__ unsigned g_xnH  [TOKENS * DIM / 2];     // LN out, packed fp16
__device__ unsigned g_WqkvP[(DIM / 2) * NQKV];     // fused packed weights [kp][q|k|v]
__device__ unsigned g_WoP  [(INNER / 2) * DIM];
__device__ unsigned g_QP   [64 * SEQ * 32];        // [bh][i][dw]
__device__ unsigned g_KtP  [64 * 32 * KTPITCH];    // [bh][dd][j]
__device__ unsigned g_VP   [64 * VROWS * 32];      // [bh][j][dw]
__device__ unsigned g_aoH  [TOKENS * INNER / 2];   // attention out, packed fp16

// ---------------- fp16 helpers --------------------------------------------------
__device__ __forceinline__ void mma_f16(float* c, const unsigned* a, const unsigned* b) {
    asm volatile(
        "mma.sync.aligned.m16n8k16.row.col.f32.f16.f16.f32 "
        "{%0,%1,%2,%3}, {%4,%5,%6,%7}, {%8,%9}, {%0,%1,%2,%3};"
        : "+f"(c[0]), "+f"(c[1]), "+f"(c[2]), "+f"(c[3])
        : "r"(a[0]), "r"(a[1]), "r"(a[2]), "r"(a[3]), "r"(b[0]), "r"(b[1]));
}
__device__ __forceinline__ unsigned pack2(float a, float b) {
    __half2 h2 = __floats2half2_rn(a, b);
    return *(unsigned*)&h2;
}
__device__ __forceinline__ unsigned prmt(unsigned a, unsigned b, unsigned sel) {
    unsigned d;
    asm("prmt.b32 %0, %1, %2, %3;" : "=r"(d) : "r"(a), "r"(b), "r"(sel));
    return d;
}

// ---------------- LayerNorm (writes packed fp16) --------------------------------
__global__ void __launch_bounds__(256) ln_kernel(const float* __restrict__ x,
                                                 const float* __restrict__ gamma,
                                                 const float* __restrict__ beta) {
    __shared__ float red[8][2];
    const int t = blockIdx.x;
    const int i = threadIdx.x;
    const float4 v = ((const float4*)(x + (size_t)t * DIM))[i];
    float s  = v.x + v.y + v.z + v.w;
    float ss = v.x*v.x + v.y*v.y + v.z*v.z + v.w*v.w;
    #pragma unroll
    for (int o = 16; o > 0; o >>= 1) {
        s  += __shfl_xor_sync(0xFFFFFFFFu, s,  o);
        ss += __shfl_xor_sync(0xFFFFFFFFu, ss, o);
    }
    const int w = i >> 5, l = i & 31;
    if (l == 0) { red[w][0] = s; red[w][1] = ss; }
    __syncthreads();
    if (w == 0) {
        s  = (l < 8) ? red[l][0] : 0.f;
        ss = (l < 8) ? red[l][1] : 0.f;
        #pragma unroll
        for (int o = 4; o > 0; o >>= 1) {
            s  += __shfl_xor_sync(0xFFFFFFFFu, s,  o);
            ss += __shfl_xor_sync(0xFFFFFFFFu, ss, o);
        }
        if (l == 0) { red[0][0] = s; red[0][1] = ss; }
    }
    __syncthreads();
    const float mu   = red[0][0] * (1.f / DIM);
    const float var  = red[0][1] * (1.f / DIM) - mu * mu;
    const float rstd = rsqrtf(var + LN_EPS);
    const float4 g  = ((const float4*)gamma)[i];
    const float4 be = ((const float4*)beta)[i];
    float4 o4;
    o4.x = (v.x - mu) * rstd * g.x + be.x;
    o4.y = (v.y - mu) * rstd * g.y + be.y;
    o4.z = (v.z - mu) * rstd * g.z + be.z;
    o4.w = (v.w - mu) * rstd * g.w + be.w;
    const size_t wi = (size_t)t * (DIM / 2) + 2 * i;
    *(uint2*)&g_xnH[wi] = make_uint2(pack2(o4.x, o4.y), pack2(o4.z, o4.w));
}

// ---------------- weight packing -------------------------------------------------
// fused: WqkvP[kp][0..1023]=Wq, [1024..2047]=Wkv K half, [2048..3071]=Wkv V half
__global__ void __launch_bounds__(256) pack_qkv(const float* __restrict__ Wq,
                                                const float* __restrict__ Wkv) {
    const int total = (DIM / 2) * NQKV;
    for (int idx = blockIdx.x * 256 + threadIdx.x; idx < total; idx += gridDim.x * 256) {
        const int kp = idx / NQKV;
        const int n  = idx - kp * NQKV;
        float a, b;
        if (n < INNER) {
            a = Wq[(size_t)(2 * kp) * INNER + n];
            b = Wq[(size_t)(2 * kp + 1) * INNER + n];
        } else {
            const int nk = (n < 2 * INNER) ? (n - INNER) : (n - 2 * INNER + INNER);
            a = Wkv[(size_t)(2 * kp) * (2 * INNER) + nk];
            b = Wkv[(size_t)(2 * kp + 1) * (2 * INNER) + nk];
        }
        g_WqkvP[idx] = pack2(a, b);
    }
}
__global__ void __launch_bounds__(256) pack_w(const float* __restrict__ W,
                                              unsigned* __restrict__ WP,
                                              int K, int N) {
    const int total = (K / 2) * N;
    for (int idx = blockIdx.x * 256 + threadIdx.x; idx < total; idx += gridDim.x * 256) {
        const int kp = idx / N;
        const int n  = idx - kp * N;
        WP[idx] = pack2(W[(size_t)(2 * kp) * N + n], W[(size_t)(2 * kp + 1) * N + n]);
    }
}

// ---------------- fp16 single-pass GEMM mainloop (macro-shared) ----------------
#define ASLD 20
#define BSLD 136
#define GSTAGE_W (128 * ASLD + 16 * BSLD)
#define GEMM_SMEM (2 * GSTAGE_W * 4)

#define GEMM_MAINLOOP(AH, BP, N, K)                                               \
    extern __shared__ unsigned gsm[];                                             \
    const int tid  = threadIdx.x;                                                 \
    const int warp = tid >> 5;                                                    \
    const int lane = tid & 31;                                                    \
    const int r = lane >> 2;                                                      \
    const int c = lane & 3;                                                       \
    const int wm = (warp & 3) * 32;                                               \
    const int wn = (warp >> 2) * 64;                                              \
    const int rowBase = blockIdx.y * 128;                                         \
    const int colBase = blockIdx.x * 128;                                         \
    const int arow = tid >> 1;                                                    \
    const int asel = (tid & 1) * 8;                                               \
    const int bkp  = tid >> 4;                                                    \
    const int bn0  = (tid & 15) * 8;                                              \
    const unsigned* ApH = (AH) + (size_t)(rowBase + arow) * ((K) / 2) + asel;     \
    const unsigned* BpP = (BP) + colBase + bn0;                                   \
    float acc[2][8][4];                                                           \
    _Pragma("unroll")                                                             \
    for (int mi = 0; mi < 2; mi++)                                                \
        _Pragma("unroll")                                                         \
        for (int ni = 0; ni < 8; ni++)                                            \
            _Pragma("unroll")                                                     \
            for (int j = 0; j < 4; j++) acc[mi][ni][j] = 0.f;                     \
    const int NC = (K) / 32;                                                      \
    auto fill = [&](int ck) {                                                     \
        unsigned* st  = gsm + (ck & 1) * GSTAGE_W;                                \
        unsigned* AsH = st;                                                       \
        unsigned* Bs  = st + 128 * ASLD;                                          \
        const int kw = ck * 16;                                                   \
        uint4 h0 = *(const uint4*)(ApH + kw);                                     \
        uint4 h1 = *(const uint4*)(ApH + kw + 4);                                 \
        unsigned* ad = &AsH[arow * ASLD + asel];                                  \
        *(uint4*)ad       = h0;                                                   \
        *(uint4*)(ad + 4) = h1;                                                   \
        const unsigned* bp = BpP + (size_t)(kw + bkp) * (N);                      \
        uint4 b0 = *(const uint4*)bp;                                             \
        uint4 b1 = *(const uint4*)(bp + 4);                                       \
        unsigned* bd = &Bs[bkp * BSLD + bn0];                                     \
        *(uint4*)bd       = b0;                                                   \
        *(uint4*)(bd + 4) = b1;                                                   \
    };                                                                            \
    fill(0);                                                                      \
    __syncthreads();                                                              \
    _Pragma("unroll 1")                                                           \
    for (int ck = 0; ck < NC; ck++) {                                             \
        if (ck + 1 < NC) fill(ck + 1);                                            \
        const unsigned* st  = gsm + (ck & 1) * GSTAGE_W;                          \
        const unsigned* AsH = st;                                                 \
        const unsigned* Bs  = st + 128 * ASLD;                                    \
        _Pragma("unroll")                                                         \
        for (int s = 0; s < 2; s++) {                                             \
            unsigned ah[2][4];                                                    \
            _Pragma("unroll")                                                     \
            for (int mi = 0; mi < 2; mi++) {                                      \
                const int row = wm + mi * 16;                                     \
                ah[mi][0] = AsH[(row + r) * ASLD + 8 * s + c];                    \
                ah[mi][1] = AsH[(row + 8 + r) * ASLD + 8 * s + c];                \
                ah[mi][2] = AsH[(row + r) * ASLD + 8 * s + c + 4];                \
                ah[mi][3] = AsH[(row + 8 + r) * ASLD + 8 * s + c + 4];            \
            }                                                                     \
            _Pragma("unroll")                                                     \
            for (int ni = 0; ni < 8; ni++) {                                      \
                unsigned bf[2];                                                   \
                bf[0] = Bs[(8 * s + c) * BSLD + wn + ni * 8 + r];                 \
                bf[1] = Bs[(8 * s + c + 4) * BSLD + wn + ni * 8 + r];             \
                _Pragma("unroll")                                                 \
                for (int mi = 0; mi < 2; mi++)                                    \
                    mma_f16(acc[mi][ni], ah[mi], bf);                             \
            }                                                                     \
        }                                                                         \
        __syncthreads();                                                          \
    }

// ---- fused q|k|v projection: epilogue dispatch by column range -----------------
__global__ void __launch_bounds__(256, 2) gemm_qkv_kernel(const float* __restrict__ q_scale,
                                                          const float* __restrict__ k_scale) {
    GEMM_MAINLOOP(g_xnH, g_WqkvP, NQKV, DIM)
    const int nbase = colBase + wn;          // 0..3071, head-aligned (64)
    if (nbase < INNER) {
        // ---- q path: l2norm + q_scale + SCALE -> g_QP ----
        const int h = nbase >> 6;
        #pragma unroll
        for (int mi = 0; mi < 2; mi++) {
            const int row0 = rowBase + wm + mi * 16 + r;
            float ss0 = 0.f, ss1 = 0.f;
            #pragma unroll
            for (int ni = 0; ni < 8; ni++) {
                ss0 += acc[mi][ni][0] * acc[mi][ni][0] + acc[mi][ni][1] * acc[mi][ni][1];
                ss1 += acc[mi][ni][2] * acc[mi][ni][2] + acc[mi][ni][3] * acc[mi][ni][3];
            }
            ss0 += __shfl_xor_sync(0xFFFFFFFFu, ss0, 1);
            ss0 += __shfl_xor_sync(0xFFFFFFFFu, ss0, 2);
            ss1 += __shfl_xor_sync(0xFFFFFFFFu, ss1, 1);
            ss1 += __shfl_xor_sync(0xFFFFFFFFu, ss1, 2);
            const float f0 = SCALE_F / fmaxf(sqrtf(ss0), L2_EPS);
            const float f1 = SCALE_F / fmaxf(sqrtf(ss1), L2_EPS);
            #pragma unroll
            for (int ni = 0; ni < 8; ni++) {
                const float2 qs = *(const float2*)&q_scale[ni * 8 + 2 * c];
                const int bb0 = row0 >> 11, i0 = row0 & 2047;
                const int bb1 = (row0 + 8) >> 11, i1 = (row0 + 8) & 2047;
                g_QP[((size_t)(bb0 * HEADS + h) * SEQ + i0) * 32 + ni * 4 + c] =
                    pack2(acc[mi][ni][0] * f0 * qs.x, acc[mi][ni][1] * f0 * qs.y);
                g_QP[((size_t)(bb1 * HEADS + h) * SEQ + i1) * 32 + ni * 4 + c] =
                    pack2(acc[mi][ni][2] * f1 * qs.x, acc[mi][ni][3] * f1 * qs.y);
            }
        }
    } else if (nbase < 2 * INNER) {
        // ---- k path: l2norm + k_scale -> transposed packed g_KtP ----
        const int h = (nbase - INNER) >> 6;
        #pragma unroll
        for (int mi = 0; mi < 2; mi++) {
            const int row0 = rowBase + wm + mi * 16 + r;
            float ss0 = 0.f, ss1 = 0.f;
            #pragma unroll
            for (int ni = 0; ni < 8; ni++) {
                ss0 += acc[mi][ni][0] * acc[mi][ni][0] + acc[mi][ni][1] * acc[mi][ni][1];
                ss1 += acc[mi][ni][2] * acc[mi][ni][2] + acc[mi][ni][3] * acc[mi][ni][3];
            }
            ss0 += __shfl_xor_sync(0xFFFFFFFFu, ss0, 1);
            ss0 += __shfl_xor_sync(0xFFFFFFFFu, ss0, 2);
            ss1 += __shfl_xor_sync(0xFFFFFFFFu, ss1, 1);
            ss1 += __shfl_xor_sync(0xFFFFFFFFu, ss1, 2);
            const float f0 = 1.f / fmaxf(sqrtf(ss0), L2_EPS);
            const float f1 = 1.f / fmaxf(sqrtf(ss1), L2_EPS);
            #pragma unroll
            for (int ni = 0; ni < 8; ni++) {
                const float2 ks = *(const float2*)&k_scale[ni * 8 + 2 * c];
                const int dd = ni * 4 + c;
                const int bb0 = row0 >> 11, i0 = row0 & 2047;
                const int bb1 = (row0 + 8) >> 11, i1 = (row0 + 8) & 2047;
                g_KtP[((size_t)(bb0 * HEADS + h) * 32 + dd) * KTPITCH + i0 + 1] =
                    pack2(acc[mi][ni][0] * f0 * ks.x, acc[mi][ni][1] * f0 * ks.y);
                g_KtP[((size_t)(bb1 * HEADS + h) * 32 + dd) * KTPITCH + i1 + 1] =
                    pack2(acc[mi][ni][2] * f1 * ks.x, acc[mi][ni][3] * f1 * ks.y);
            }
        }
    } else {
        // ---- v path: plain packed copy -> g_VP ----
        const int h = (nbase - 2 * INNER) >> 6;
        #pragma unroll
        for (int mi = 0; mi < 2; mi++) {
            const int row0 = rowBase + wm + mi * 16 + r;
            #pragma unroll
            for (int ni = 0; ni < 8; ni++) {
                const int bb0 = row0 >> 11, i0 = row0 & 2047;
                const int bb1 = (row0 + 8) >> 11, i1 = (row0 + 8) & 2047;
                g_VP[((size_t)(bb0 * HEADS + h) * VROWS + i0 + 1) * 32 + ni * 4 + c] =
                    pack2(acc[mi][ni][0], acc[mi][ni][1]);
                g_VP[((size_t)(bb1 * HEADS + h) * VROWS + i1 + 1) * 32 + ni * 4 + c] =
                    pack2(acc[mi][ni][2], acc[mi][ni][3]);
            }
        }
    }
}

// ---- output projection ----
__global__ void __launch_bounds__(256, 2) gemm_o_kernel(float* __restrict__ out) {
    GEMM_MAINLOOP(g_aoH, g_WoP, DIM, INNER)
    #pragma unroll
    for (int mi = 0; mi < 2; mi++) {
        const int row = rowBase + wm + mi * 16 + r;
        #pragma unroll
        for (int ni = 0; ni < 8; ni++) {
            const int col = colBase + wn + ni * 8 + 2 * c;
            *(float2*)&out[(size_t)row * DIM + col]       = make_float2(acc[mi][ni][0], acc[mi][ni][1]);
            *(float2*)&out[(size_t)(row + 8) * DIM + col] = make_float2(acc[mi][ni][2], acc[mi][ni][3]);
        }
    }
}

// ---------------- null slot -------------------------------------------------------
__global__ void null_prep(const float* __restrict__ null_kv,
                          const float* __restrict__ k_scale) {
    const int bh = blockIdx.x;
    const int h = bh & 15;
    const int lane = threadIdx.x;
    const int src0 = (2 * lane) & 31;
    const int src1 = (2 * lane + 1) & 31;
    const float* nk = null_kv + h * DHEAD;
    const float* nv = null_kv + HEADS * DHEAD + h * DHEAD;
    float k0 = nk[lane], k1 = nk[lane + 32];
    float ss = k0 * k0 + k1 * k1;
    #pragma unroll
    for (int o = 16; o > 0; o >>= 1) ss += __shfl_xor_sync(0xFFFFFFFFu, ss, o);
    const float inv = 1.f / fmaxf(sqrtf(ss), L2_EPS);
    const float kk0 = k0 * inv * k_scale[lane];
    const float kk1 = k1 * inv * k_scale[lane + 32];
    {
        float s0a = __shfl_sync(0xFFFFFFFFu, kk0, src0);
        float s0b = __shfl_sync(0xFFFFFFFFu, kk0, src1);
        float s1a = __shfl_sync(0xFFFFFFFFu, kk1, src0);
        float s1b = __shfl_sync(0xFFFFFFFFu, kk1, src1);
        const float a = (lane < 16) ? s0a : s1a;
        const float b = (lane < 16) ? s0b : s1b;
        g_KtP[((size_t)bh * 32 + lane) * KTPITCH] = pack2(a, b);
    }
    const float v0 = nv[lane], v1 = nv[lane + 32];
    {
        float s0a = __shfl_sync(0xFFFFFFFFu, v0, src0);
        float s0b = __shfl_sync(0xFFFFFFFFu, v0, src1);
        float s1a = __shfl_sync(0xFFFFFFFFu, v1, src0);
        float s1b = __shfl_sync(0xFFFFFFFFu, v1, src1);
        const float a = (lane < 16) ? s0a : s1a;
        const float b = (lane < 16) ? s0b : s1b;
        g_VP[(size_t)bh * VROWS * 32 + lane] = pack2(a, b);
    }
}

// ---------------- flash attention: all single-pass fp16, P in registers --------
#define ABQ 128
#define ABK 64
#define ANT ((KVLEN + ABK - 1) / ABK)   /* 33 */
#define KTLD 72
#define VLD  72

#define ATT_SMEM ((32*KTLD + 32*VLD) * 4)   /* 18432 B */

__global__ void __launch_bounds__(256, 2) attn_mma_kernel() {
    extern __shared__ unsigned ash[];
    unsigned* KtH = ash;
    unsigned* VH  = KtH + 32 * KTLD;

    const int tid  = threadIdx.x;
    const int warp = tid >> 5;
    const int lane = tid & 31;
    const int r = lane >> 2;
    const int c = lane & 3;
    const int bh = blockIdx.y;
    const int qt = blockIdx.x;
    const int m0 = warp * 16;

    const unsigned* QgP = g_QP + ((size_t)bh * SEQ + (size_t)qt * ABQ + m0) * 32;
    unsigned qh[4][4];
    #pragma unroll
    for (int s = 0; s < 4; s++) {
        qh[s][0] = QgP[(size_t)r * 32 + s * 8 + c];
        qh[s][1] = QgP[(size_t)(r + 8) * 32 + s * 8 + c];
        qh[s][2] = QgP[(size_t)r * 32 + s * 8 + c + 4];
        qh[s][3] = QgP[(size_t)(r + 8) * 32 + s * 8 + c + 4];
    }

    float oacc[8][4];
    #pragma unroll
    for (int nt = 0; nt < 8; nt++)
        #pragma unroll
        for (int j = 0; j < 4; j++) oacc[nt][j] = 0.f;
    float mrow0 = -1e30f, mrow1 = -1e30f, lrow0 = 0.f, lrow1 = 0.f;

    const unsigned* KtG = g_KtP + ((size_t)bh * 32 + (tid >> 3)) * KTPITCH + (tid & 7) * 8;
    const int vjj = tid >> 3;
    const int vdw = (tid & 7) * 4;
    const unsigned* VgBase = g_VP + (size_t)bh * VROWS * 32;

    for (int kt = 0; kt < ANT; kt++) {
        const int kvbase = kt * ABK;
        __syncthreads();

        {
            uint4 w0 = *(const uint4*)(KtG + kvbase);
            uint4 w1 = *(const uint4*)(KtG + kvbase + 4);
            unsigned* dst = &KtH[(tid >> 3) * KTLD + (tid & 7) * 8];
            *(uint4*)dst       = w0;
            *(uint4*)(dst + 4) = w1;
        }
        {
            const unsigned* va = VgBase + (size_t)(kvbase + 2 * vjj) * 32 + vdw;
            uint4 A4 = *(const uint4*)va;
            uint4 B4 = *(const uint4*)(va + 32);
            unsigned* dst = &VH[vjj * VLD + 2 * vdw];
            uint4 o0, o1;
            o0.x = prmt(A4.x, B4.x, 0x5410); o0.y = prmt(A4.x, B4.x, 0x7632);
            o0.z = prmt(A4.y, B4.y, 0x5410); o0.w = prmt(A4.y, B4.y, 0x7632);
            o1.x = prmt(A4.z, B4.z, 0x5410); o1.y = prmt(A4.z, B4.z, 0x7632);
            o1.z = prmt(A4.w, B4.w, 0x5410); o1.w = prmt(A4.w, B4.w, 0x7632);
            *(uint4*)dst       = o0;
            *(uint4*)(dst + 4) = o1;
        }
        __syncthreads();

        float sa[8][4];
        #pragma unroll
        for (int nt = 0; nt < 8; nt++)
            #pragma unroll
            for (int j = 0; j < 4; j++) sa[nt][j] = 0.f;

        #pragma unroll
        for (int s = 0; s < 4; s++) {
            #pragma unroll
            for (int nt = 0; nt < 8; nt++) {
                unsigned bfh[2];
                bfh[0] = KtH[(8 * s + c) * KTLD + nt * 8 + r];
                bfh[1] = KtH[(8 * s + c + 4) * KTLD + nt * 8 + r];
                mma_f16(sa[nt], qh[s], bfh);
            }
        }

        float tmax0 = -1e30f, tmax1 = -1e30f;
        #pragma unroll
        for (int nt = 0; nt < 8; nt++) {
            const int j0 = kvbase + nt * 8 + 2 * c;
            if (j0 >= KVLEN)     { sa[nt][0] = -1e30f; sa[nt][2] = -1e30f; }
            if (j0 + 1 >= KVLEN) { sa[nt][1] = -1e30f; sa[nt][3] = -1e30f; }
            tmax0 = fmaxf(tmax0, fmaxf(sa[nt][0], sa[nt][1]));
            tmax1 = fmaxf(tmax1, fmaxf(sa[nt][2], sa[nt][3]));
        }
        tmax0 = fmaxf(tmax0, __shfl_xor_sync(0xFFFFFFFFu, tmax0, 1));
        tmax0 = fmaxf(tmax0, __shfl_xor_sync(0xFFFFFFFFu, tmax0, 2));
        tmax1 = fmaxf(tmax1, __shfl_xor_sync(0xFFFFFFFFu, tmax1, 1));
        tmax1 = fmaxf(tmax1, __shfl_xor_sync(0xFFFFFFFFu, tmax1, 2));

        const float mnew0 = fmaxf(mrow0, tmax0);
        const float mnew1 = fmaxf(mrow1, tmax1);
        const float cf0 = __expf(mrow0 - mnew0);
        const float cf1 = __expf(mrow1 - mnew1);
        mrow0 = mnew0; mrow1 = mnew1;

        unsigned pfrag[8][2];
        float psum0 = 0.f, psum1 = 0.f;
        #pragma unroll
        for (int nt = 0; nt < 8; nt++) {
            const float p0 = __expf(sa[nt][0] - mnew0);
            const float p1 = __expf(sa[nt][1] - mnew0);
            const float p2 = __expf(sa[nt][2] - mnew1);
            const float p3 = __expf(sa[nt][3] - mnew1);
            psum0 += p0 + p1;
            psum1 += p2 + p3;
            pfrag[nt][0] = pack2(p0, p1);
            pfrag[nt][1] = pack2(p2, p3);
        }
        psum0 += __shfl_xor_sync(0xFFFFFFFFu, psum0, 1);
        psum0 += __shfl_xor_sync(0xFFFFFFFFu, psum0, 2);
        psum1 += __shfl_xor_sync(0xFFFFFFFFu, psum1, 1);
        psum1 += __shfl_xor_sync(0xFFFFFFFFu, psum1, 2);
        lrow0 = lrow0 * cf0 + psum0;
        lrow1 = lrow1 * cf1 + psum1;

        #pragma unroll
        for (int nt = 0; nt < 8; nt++) {
            oacc[nt][0] *= cf0; oacc[nt][1] *= cf0;
            oacc[nt][2] *= cf1; oacc[nt][3] *= cf1;
        }

        #pragma unroll
        for (int s = 0; s < 4; s++) {
            unsigned pa[4];
            pa[0] = pfrag[2 * s][0];
            pa[1] = pfrag[2 * s][1];
            pa[2] = pfrag[2 * s + 1][0];
            pa[3] = pfrag[2 * s + 1][1];
            #pragma unroll
            for (int nt = 0; nt < 8; nt++) {
                unsigned vfh[2];
                vfh[0] = VH[(8 * s + c) * VLD + nt * 8 + r];
                vfh[1] = VH[(8 * s + c + 4) * VLD + nt * 8 + r];
                mma_f16(oacc[nt], pa, vfh);
            }
        }
    }

    const float li0 = 1.f / lrow0;
    const float li1 = 1.f / lrow1;
    const int bb = bh >> 4, h = bh & 15;
    const int row0 = qt * ABQ + m0 + r;
    #pragma unroll
    for (int nt = 0; nt < 8; nt++) {
        const size_t wi0 = (size_t)(bb * SEQ + row0) * (INNER / 2) + h * 32 + nt * 4 + c;
        const size_t wi1 = (size_t)(bb * SEQ + row0 + 8) * (INNER / 2) + h * 32 + nt * 4 + c;
        g_aoH[wi0] = pack2(oacc[nt][0] * li0, oacc[nt][1] * li0);
        g_aoH[wi1] = pack2(oacc[nt][2] * li1, oacc[nt][3] * li1);
    }
}

// ---------------- launch ------------------------------------------------------
extern "C" void kernel_launch(void* const* d_in, const int* in_sizes, int n_in,
                              void* d_out, int out_size) {
    const float* x       = (const float*)d_in[0];
    const float* gamma   = (const float*)d_in[1];
    const float* beta    = (const float*)d_in[2];
    const float* null_kv = (const float*)d_in[3];
    const float* Wq      = (const float*)d_in[4];
    const float* Wkv     = (const float*)d_in[5];
    const float* q_scale = (const float*)d_in[6];
    const float* k_scale = (const float*)d_in[7];
    const float* Wo      = (const float*)d_in[8];
    float* out = (float*)d_out;

    unsigned* wop;
    cudaGetSymbolAddress((void**)&wop, g_WoP);

    cudaFuncSetAttribute(gemm_qkv_kernel, cudaFuncAttributeMaxDynamicSharedMemorySize, GEMM_SMEM);
    cudaFuncSetAttribute(gemm_o_kernel,   cudaFuncAttributeMaxDynamicSharedMemorySize, GEMM_SMEM);
    cudaFuncSetAttribute(attn_mma_kernel, cudaFuncAttributeMaxDynamicSharedMemorySize, ATT_SMEM);

    pack_qkv<<<768, 256>>>(Wq, Wkv);
    pack_w<<<512, 256>>>(Wo, wop, INNER, DIM);
    ln_kernel<<<TOKENS, 256>>>(x, gamma, beta);
    null_prep<<<BATCH * HEADS, 32>>>(null_kv, k_scale);
    gemm_qkv_kernel<<<dim3(NQKV / 128, TOKENS / 128), 256, GEMM_SMEM>>>(q_scale, k_scale);
    attn_mma_kernel<<<dim3(SEQ / ABQ, BATCH * HEADS), 256, ATT_SMEM>>>();
    gemm_o_kernel<<<dim3(DIM / 128, TOKENS / 128), 256, GEMM_SMEM>>>(out);
}

// round 12
// speedup vs baseline: 10.9059x; 1.0738x over previous
#include <cuda_runtime.h>
#include <cuda_fp16.h>
#include <math.h>

#define HEADS   16
#define DHEAD   64
#define BATCH   4
#define SEQ     2048
#define DIM     1024
#define INNER   1024
#define TOKENS  (BATCH*SEQ)       /* 8192 */
#define KVLEN   (SEQ+1)           /* 2049 */
#define SCALE_F 8.0f
#define LN_EPS  1e-5f
#define L2_EPS  1e-12f

#define NQKV    (3 * INNER)       /* 3072 fused projection width */
#define KTPITCH 2112
#define VROWS   2112

// ---------------- scratch (global device arrays; no allocations) -------------
__device__ unsigned g_xnH  [TOKENS * DIM / 2];     // LN out, packed fp16
__device__ unsigned g_WqkvP[(DIM / 2) * NQKV];     // fused packed weights [kp][q|k|v]
__device__ unsigned g_WoP  [(INNER / 2) * DIM];
__device__ unsigned g_QP   [64 * SEQ * 32];        // [bh][i][dw]
__device__ unsigned g_KtP  [64 * 32 * KTPITCH];    // [bh][dd][j]
__device__ unsigned g_VP   [64 * VROWS * 32];      // [bh][j][dw]
__device__ unsigned g_aoH  [TOKENS * INNER / 2];   // attention out, packed fp16

// ---------------- fp16 / async helpers ------------------------------------------
__device__ __forceinline__ void mma_f16(float* c, const unsigned* a, const unsigned* b) {
    asm volatile(
        "mma.sync.aligned.m16n8k16.row.col.f32.f16.f16.f32 "
        "{%0,%1,%2,%3}, {%4,%5,%6,%7}, {%8,%9}, {%0,%1,%2,%3};"
        : "+f"(c[0]), "+f"(c[1]), "+f"(c[2]), "+f"(c[3])
        : "r"(a[0]), "r"(a[1]), "r"(a[2]), "r"(a[3]), "r"(b[0]), "r"(b[1]));
}
__device__ __forceinline__ unsigned pack2(float a, float b) {
    __half2 h2 = __floats2half2_rn(a, b);
    return *(unsigned*)&h2;
}
__device__ __forceinline__ unsigned prmt(unsigned a, unsigned b, unsigned sel) {
    unsigned d;
    asm("prmt.b32 %0, %1, %2, %3;" : "=r"(d) : "r"(a), "r"(b), "r"(sel));
    return d;
}
__device__ __forceinline__ void cp_async16(unsigned smem_addr, const void* gptr) {
    asm volatile("cp.async.cg.shared.global [%0], [%1], 16;"
                 :: "r"(smem_addr), "l"(gptr) : "memory");
}
__device__ __forceinline__ void cp_commit() {
    asm volatile("cp.async.commit_group;" ::: "memory");
}
__device__ __forceinline__ void cp_wait0() {
    asm volatile("cp.async.wait_group 0;" ::: "memory");
}

// ---------------- LayerNorm (writes packed fp16) --------------------------------
__global__ void __launch_bounds__(256) ln_kernel(const float* __restrict__ x,
                                                 const float* __restrict__ gamma,
                                                 const float* __restrict__ beta) {
    __shared__ float red[8][2];
    const int t = blockIdx.x;
    const int i = threadIdx.x;
    const float4 v = ((const float4*)(x + (size_t)t * DIM))[i];
    float s  = v.x + v.y + v.z + v.w;
    float ss = v.x*v.x + v.y*v.y + v.z*v.z + v.w*v.w;
    #pragma unroll
    for (int o = 16; o > 0; o >>= 1) {
        s  += __shfl_xor_sync(0xFFFFFFFFu, s,  o);
        ss += __shfl_xor_sync(0xFFFFFFFFu, ss, o);
    }
    const int w = i >> 5, l = i & 31;
    if (l == 0) { red[w][0] = s; red[w][1] = ss; }
    __syncthreads();
    if (w == 0) {
        s  = (l < 8) ? red[l][0] : 0.f;
        ss = (l < 8) ? red[l][1] : 0.f;
        #pragma unroll
        for (int o = 4; o > 0; o >>= 1) {
            s  += __shfl_xor_sync(0xFFFFFFFFu, s,  o);
            ss += __shfl_xor_sync(0xFFFFFFFFu, ss, o);
        }
        if (l == 0) { red[0][0] = s; red[0][1] = ss; }
    }
    __syncthreads();
    const float mu   = red[0][0] * (1.f / DIM);
    const float var  = red[0][1] * (1.f / DIM) - mu * mu;
    const float rstd = rsqrtf(var + LN_EPS);
    const float4 g  = ((const float4*)gamma)[i];
    const float4 be = ((const float4*)beta)[i];
    float4 o4;
    o4.x = (v.x - mu) * rstd * g.x + be.x;
    o4.y = (v.y - mu) * rstd * g.y + be.y;
    o4.z = (v.z - mu) * rstd * g.z + be.z;
    o4.w = (v.w - mu) * rstd * g.w + be.w;
    const size_t wi = (size_t)t * (DIM / 2) + 2 * i;
    *(uint2*)&g_xnH[wi] = make_uint2(pack2(o4.x, o4.y), pack2(o4.z, o4.w));
}

// ---------------- weight packing -------------------------------------------------
__global__ void __launch_bounds__(256) pack_qkv(const float* __restrict__ Wq,
                                                const float* __restrict__ Wkv) {
    const int total = (DIM / 2) * NQKV;
    for (int idx = blockIdx.x * 256 + threadIdx.x; idx < total; idx += gridDim.x * 256) {
        const int kp = idx / NQKV;
        const int n  = idx - kp * NQKV;
        float a, b;
        if (n < INNER) {
            a = Wq[(size_t)(2 * kp) * INNER + n];
            b = Wq[(size_t)(2 * kp + 1) * INNER + n];
        } else {
            const int nk = (n < 2 * INNER) ? (n - INNER) : (n - 2 * INNER + INNER);
            a = Wkv[(size_t)(2 * kp) * (2 * INNER) + nk];
            b = Wkv[(size_t)(2 * kp + 1) * (2 * INNER) + nk];
        }
        g_WqkvP[idx] = pack2(a, b);
    }
}
__global__ void __launch_bounds__(256) pack_w(const float* __restrict__ W,
                                              unsigned* __restrict__ WP,
                                              int K, int N) {
    const int total = (K / 2) * N;
    for (int idx = blockIdx.x * 256 + threadIdx.x; idx < total; idx += gridDim.x * 256) {
        const int kp = idx / N;
        const int n  = idx - kp * N;
        WP[idx] = pack2(W[(size_t)(2 * kp) * N + n], W[(size_t)(2 * kp + 1) * N + n]);
    }
}

// ---------------- fp16 single-pass GEMM mainloop (cp.async pipelined) ----------
#define ASLD 20
#define BSLD 136
#define GSTAGE_W (128 * ASLD + 16 * BSLD)
#define GEMM_SMEM (2 * GSTAGE_W * 4)

#define GEMM_MAINLOOP(AH, BP, N, K)                                               \
    extern __shared__ unsigned gsm[];                                             \
    const unsigned gsb = (unsigned)__cvta_generic_to_shared(gsm);                 \
    const int tid  = threadIdx.x;                                                 \
    const int warp = tid >> 5;                                                    \
    const int lane = tid & 31;                                                    \
    const int r = lane >> 2;                                                      \
    const int c = lane & 3;                                                       \
    const int wm = (warp & 3) * 32;                                               \
    const int wn = (warp >> 2) * 64;                                              \
    const int rowBase = blockIdx.y * 128;                                         \
    const int colBase = blockIdx.x * 128;                                         \
    const int arow = tid >> 1;                                                    \
    const int asel = (tid & 1) * 8;                                               \
    const int bkp  = tid >> 4;                                                    \
    const int bn0  = (tid & 15) * 8;                                              \
    const unsigned* ApH = (AH) + (size_t)(rowBase + arow) * ((K) / 2) + asel;     \
    const unsigned* BpP = (BP) + colBase + bn0;                                   \
    float acc[2][8][4];                                                           \
    _Pragma("unroll")                                                             \
    for (int mi = 0; mi < 2; mi++)                                                \
        _Pragma("unroll")                                                         \
        for (int ni = 0; ni < 8; ni++)                                            \
            _Pragma("unroll")                                                     \
            for (int j = 0; j < 4; j++) acc[mi][ni][j] = 0.f;                     \
    const int NC = (K) / 32;                                                      \
    const unsigned aoff0 = (arow * ASLD + asel) * 4;                              \
    const unsigned boff0 = (128 * ASLD + bkp * BSLD + bn0) * 4;                   \
    auto fill_async = [&](int ck) {                                               \
        const unsigned st = gsb + ((ck & 1) * GSTAGE_W) * 4;                      \
        const int kw = ck * 16;                                                   \
        cp_async16(st + aoff0,      ApH + kw);                                    \
        cp_async16(st + aoff0 + 16, ApH + kw + 4);                                \
        const unsigned* bp = BpP + (size_t)(kw + bkp) * (N);                      \
        cp_async16(st + boff0,      bp);                                          \
        cp_async16(st + boff0 + 16, bp + 4);                                      \
    };                                                                            \
    fill_async(0);                                                                \
    cp_commit();                                                                  \
    _Pragma("unroll 1")                                                           \
    for (int ck = 0; ck < NC; ck++) {                                             \
        cp_wait0();                                                               \
        __syncthreads();                                                          \
        if (ck + 1 < NC) { fill_async(ck + 1); cp_commit(); }                     \
        const unsigned* st  = gsm + (ck & 1) * GSTAGE_W;                          \
        const unsigned* AsH = st;                                                 \
        const unsigned* Bs  = st + 128 * ASLD;                                    \
        _Pragma("unroll")                                                         \
        for (int s = 0; s < 2; s++) {                                             \
            unsigned ah[2][4];                                                    \
            _Pragma("unroll")                                                     \
            for (int mi = 0; mi < 2; mi++) {                                      \
                const int row = wm + mi * 16;                                     \
                ah[mi][0] = AsH[(row + r) * ASLD + 8 * s + c];                    \
                ah[mi][1] = AsH[(row + 8 + r) * ASLD + 8 * s + c];                \
                ah[mi][2] = AsH[(row + r) * ASLD + 8 * s + c + 4];                \
                ah[mi][3] = AsH[(row + 8 + r) * ASLD + 8 * s + c + 4];            \
            }                                                                     \
            _Pragma("unroll")                                                     \
            for (int ni = 0; ni < 8; ni++) {                                      \
                unsigned bf[2];                                                   \
                bf[0] = Bs[(8 * s + c) * BSLD + wn + ni * 8 + r];                 \
                bf[1] = Bs[(8 * s + c + 4) * BSLD + wn + ni * 8 + r];             \
                _Pragma("unroll")                                                 \
                for (int mi = 0; mi < 2; mi++)                                    \
                    mma_f16(acc[mi][ni], ah[mi], bf);                             \
            }                                                                     \
        }                                                                         \
    }

// ---- fused q|k|v projection: epilogue dispatch by column range -----------------
__global__ void __launch_bounds__(256, 2) gemm_qkv_kernel(const float* __restrict__ q_scale,
                                                          const float* __restrict__ k_scale) {
    GEMM_MAINLOOP(g_xnH, g_WqkvP, NQKV, DIM)
    const int nbase = colBase + wn;          // 0..3071, head-aligned (64)
    if (nbase < INNER) {
        const int h = nbase >> 6;
        #pragma unroll
        for (int mi = 0; mi < 2; mi++) {
            const int row0 = rowBase + wm + mi * 16 + r;
            float ss0 = 0.f, ss1 = 0.f;
            #pragma unroll
            for (int ni = 0; ni < 8; ni++) {
                ss0 += acc[mi][ni][0] * acc[mi][ni][0] + acc[mi][ni][1] * acc[mi][ni][1];
                ss1 += acc[mi][ni][2] * acc[mi][ni][2] + acc[mi][ni][3] * acc[mi][ni][3];
            }
            ss0 += __shfl_xor_sync(0xFFFFFFFFu, ss0, 1);
            ss0 += __shfl_xor_sync(0xFFFFFFFFu, ss0, 2);
            ss1 += __shfl_xor_sync(0xFFFFFFFFu, ss1, 1);
            ss1 += __shfl_xor_sync(0xFFFFFFFFu, ss1, 2);
            const float f0 = SCALE_F / fmaxf(sqrtf(ss0), L2_EPS);
            const float f1 = SCALE_F / fmaxf(sqrtf(ss1), L2_EPS);
            #pragma unroll
            for (int ni = 0; ni < 8; ni++) {
                const float2 qs = *(const float2*)&q_scale[ni * 8 + 2 * c];
                const int bb0 = row0 >> 11, i0 = row0 & 2047;
                const int bb1 = (row0 + 8) >> 11, i1 = (row0 + 8) & 2047;
                g_QP[((size_t)(bb0 * HEADS + h) * SEQ + i0) * 32 + ni * 4 + c] =
                    pack2(acc[mi][ni][0] * f0 * qs.x, acc[mi][ni][1] * f0 * qs.y);
                g_QP[((size_t)(bb1 * HEADS + h) * SEQ + i1) * 32 + ni * 4 + c] =
                    pack2(acc[mi][ni][2] * f1 * qs.x, acc[mi][ni][3] * f1 * qs.y);
            }
        }
    } else if (nbase < 2 * INNER) {
        const int h = (nbase - INNER) >> 6;
        #pragma unroll
        for (int mi = 0; mi < 2; mi++) {
            const int row0 = rowBase + wm + mi * 16 + r;
            float ss0 = 0.f, ss1 = 0.f;
            #pragma unroll
            for (int ni = 0; ni < 8; ni++) {
                ss0 += acc[mi][ni][0] * acc[mi][ni][0] + acc[mi][ni][1] * acc[mi][ni][1];
                ss1 += acc[mi][ni][2] * acc[mi][ni][2] + acc[mi][ni][3] * acc[mi][ni][3];
            }
            ss0 += __shfl_xor_sync(0xFFFFFFFFu, ss0, 1);
            ss0 += __shfl_xor_sync(0xFFFFFFFFu, ss0, 2);
            ss1 += __shfl_xor_sync(0xFFFFFFFFu, ss1, 1);
            ss1 += __shfl_xor_sync(0xFFFFFFFFu, ss1, 2);
            const float f0 = 1.f / fmaxf(sqrtf(ss0), L2_EPS);
            const float f1 = 1.f / fmaxf(sqrtf(ss1), L2_EPS);
            #pragma unroll
            for (int ni = 0; ni < 8; ni++) {
                const float2 ks = *(const float2*)&k_scale[ni * 8 + 2 * c];
                const int dd = ni * 4 + c;
                const int bb0 = row0 >> 11, i0 = row0 & 2047;
                const int bb1 = (row0 + 8) >> 11, i1 = (row0 + 8) & 2047;
                g_KtP[((size_t)(bb0 * HEADS + h) * 32 + dd) * KTPITCH + i0 + 1] =
                    pack2(acc[mi][ni][0] * f0 * ks.x, acc[mi][ni][1] * f0 * ks.y);
                g_KtP[((size_t)(bb1 * HEADS + h) * 32 + dd) * KTPITCH + i1 + 1] =
                    pack2(acc[mi][ni][2] * f1 * ks.x, acc[mi][ni][3] * f1 * ks.y);
            }
        }
    } else {
        const int h = (nbase - 2 * INNER) >> 6;
        #pragma unroll
        for (int mi = 0; mi < 2; mi++) {
            const int row0 = rowBase + wm + mi * 16 + r;
            #pragma unroll
            for (int ni = 0; ni < 8; ni++) {
                const int bb0 = row0 >> 11, i0 = row0 & 2047;
                const int bb1 = (row0 + 8) >> 11, i1 = (row0 + 8) & 2047;
                g_VP[((size_t)(bb0 * HEADS + h) * VROWS + i0 + 1) * 32 + ni * 4 + c] =
                    pack2(acc[mi][ni][0], acc[mi][ni][1]);
                g_VP[((size_t)(bb1 * HEADS + h) * VROWS + i1 + 1) * 32 + ni * 4 + c] =
                    pack2(acc[mi][ni][2], acc[mi][ni][3]);
            }
        }
    }
}

// ---- output projection ----
__global__ void __launch_bounds__(256, 2) gemm_o_kernel(float* __restrict__ out) {
    GEMM_MAINLOOP(g_aoH, g_WoP, DIM, INNER)
    #pragma unroll
    for (int mi = 0; mi < 2; mi++) {
        const int row = rowBase + wm + mi * 16 + r;
        #pragma unroll
        for (int ni = 0; ni < 8; ni++) {
            const int col = colBase + wn + ni * 8 + 2 * c;
            *(float2*)&out[(size_t)row * DIM + col]       = make_float2(acc[mi][ni][0], acc[mi][ni][1]);
            *(float2*)&out[(size_t)(row + 8) * DIM + col] = make_float2(acc[mi][ni][2], acc[mi][ni][3]);
        }
    }
}

// ---------------- null slot -------------------------------------------------------
__global__ void null_prep(const float* __restrict__ null_kv,
                          const float* __restrict__ k_scale) {
    const int bh = blockIdx.x;
    const int h = bh & 15;
    const int lane = threadIdx.x;
    const int src0 = (2 * lane) & 31;
    const int src1 = (2 * lane + 1) & 31;
    const float* nk = null_kv + h * DHEAD;
    const float* nv = null_kv + HEADS * DHEAD + h * DHEAD;
    float k0 = nk[lane], k1 = nk[lane + 32];
    float ss = k0 * k0 + k1 * k1;
    #pragma unroll
    for (int o = 16; o > 0; o >>= 1) ss += __shfl_xor_sync(0xFFFFFFFFu, ss, o);
    const float inv = 1.f / fmaxf(sqrtf(ss), L2_EPS);
    const float kk0 = k0 * inv * k_scale[lane];
    const float kk1 = k1 * inv * k_scale[lane + 32];
    {
        float s0a = __shfl_sync(0xFFFFFFFFu, kk0, src0);
        float s0b = __shfl_sync(0xFFFFFFFFu, kk0, src1);
        float s1a = __shfl_sync(0xFFFFFFFFu, kk1, src0);
        float s1b = __shfl_sync(0xFFFFFFFFu, kk1, src1);
        const float a = (lane < 16) ? s0a : s1a;
        const float b = (lane < 16) ? s0b : s1b;
        g_KtP[((size_t)bh * 32 + lane) * KTPITCH] = pack2(a, b);
    }
    const float v0 = nv[lane], v1 = nv[lane + 32];
    {
        float s0a = __shfl_sync(0xFFFFFFFFu, v0, src0);
        float s0b = __shfl_sync(0xFFFFFFFFu, v0, src1);
        float s1a = __shfl_sync(0xFFFFFFFFu, v1, src0);
        float s1b = __shfl_sync(0xFFFFFFFFu, v1, src1);
        const float a = (lane < 16) ? s0a : s1a;
        const float b = (lane < 16) ? s0b : s1b;
        g_VP[(size_t)bh * VROWS * 32 + lane] = pack2(a, b);
    }
}

// ---------------- flash attention: all single-pass fp16, P in registers --------
#define ABQ 128
#define ABK 64
#define ANT ((KVLEN + ABK - 1) / ABK)   /* 33 */
#define KTLD 72
#define VLD  72

#define ATT_SMEM ((32*KTLD + 32*VLD) * 4)   /* 18432 B */

__global__ void __launch_bounds__(256, 2) attn_mma_kernel() {
    extern __shared__ unsigned ash[];
    unsigned* KtH = ash;
    unsigned* VH  = KtH + 32 * KTLD;

    const int tid  = threadIdx.x;
    const int warp = tid >> 5;
    const int lane = tid & 31;
    const int r = lane >> 2;
    const int c = lane & 3;
    const int bh = blockIdx.y;
    const int qt = blockIdx.x;
    const int m0 = warp * 16;

    const unsigned* QgP = g_QP + ((size_t)bh * SEQ + (size_t)qt * ABQ + m0) * 32;
    unsigned qh[4][4];
    #pragma unroll
    for (int s = 0; s < 4; s++) {
        qh[s][0] = QgP[(size_t)r * 32 + s * 8 + c];
        qh[s][1] = QgP[(size_t)(r + 8) * 32 + s * 8 + c];
        qh[s][2] = QgP[(size_t)r * 32 + s * 8 + c + 4];
        qh[s][3] = QgP[(size_t)(r + 8) * 32 + s * 8 + c + 4];
    }

    float oacc[8][4];
    #pragma unroll
    for (int nt = 0; nt < 8; nt++)
        #pragma unroll
        for (int j = 0; j < 4; j++) oacc[nt][j] = 0.f;
    float mrow0 = -1e30f, mrow1 = -1e30f, lrow0 = 0.f, lrow1 = 0.f;

    const unsigned* KtG = g_KtP + ((size_t)bh * 32 + (tid >> 3)) * KTPITCH + (tid & 7) * 8;
    const int vjj = tid >> 3;
    const int vdw = (tid & 7) * 4;
    const unsigned* VgBase = g_VP + (size_t)bh * VROWS * 32;

    for (int kt = 0; kt < ANT; kt++) {
        const int kvbase = kt * ABK;
        __syncthreads();

        {
            uint4 w0 = *(const uint4*)(KtG + kvbase);
            uint4 w1 = *(const uint4*)(KtG + kvbase + 4);
            unsigned* dst = &KtH[(tid >> 3) * KTLD + (tid & 7) * 8];
            *(uint4*)dst       = w0;
            *(uint4*)(dst + 4) = w1;
        }
        {
            const unsigned* va = VgBase + (size_t)(kvbase + 2 * vjj) * 32 + vdw;
            uint4 A4 = *(const uint4*)va;
            uint4 B4 = *(const uint4*)(va + 32);
            unsigned* dst = &VH[vjj * VLD + 2 * vdw];
            uint4 o0, o1;
            o0.x = prmt(A4.x, B4.x, 0x5410); o0.y = prmt(A4.x, B4.x, 0x7632);
            o0.z = prmt(A4.y, B4.y, 0x5410); o0.w = prmt(A4.y, B4.y, 0x7632);
            o1.x = prmt(A4.z, B4.z, 0x5410); o1.y = prmt(A4.z, B4.z, 0x7632);
            o1.z = prmt(A4.w, B4.w, 0x5410); o1.w = prmt(A4.w, B4.w, 0x7632);
            *(uint4*)dst       = o0;
            *(uint4*)(dst + 4) = o1;
        }
        __syncthreads();

        float sa[8][4];
        #pragma unroll
        for (int nt = 0; nt < 8; nt++)
            #pragma unroll
            for (int j = 0; j < 4; j++) sa[nt][j] = 0.f;

        #pragma unroll
        for (int s = 0; s < 4; s++) {
            #pragma unroll
            for (int nt = 0; nt < 8; nt++) {
                unsigned bfh[2];
                bfh[0] = KtH[(8 * s + c) * KTLD + nt * 8 + r];
                bfh[1] = KtH[(8 * s + c + 4) * KTLD + nt * 8 + r];
                mma_f16(sa[nt], qh[s], bfh);
            }
        }

        float tmax0 = -1e30f, tmax1 = -1e30f;
        #pragma unroll
        for (int nt = 0; nt < 8; nt++) {
            const int j0 = kvbase + nt * 8 + 2 * c;
            if (j0 >= KVLEN)     { sa[nt][0] = -1e30f; sa[nt][2] = -1e30f; }
            if (j0 + 1 >= KVLEN) { sa[nt][1] = -1e30f; sa[nt][3] = -1e30f; }
            tmax0 = fmaxf(tmax0, fmaxf(sa[nt][0], sa[nt][1]));
            tmax1 = fmaxf(tmax1, fmaxf(sa[nt][2], sa[nt][3]));
        }
        tmax0 = fmaxf(tmax0, __shfl_xor_sync(0xFFFFFFFFu, tmax0, 1));
        tmax0 = fmaxf(tmax0, __shfl_xor_sync(0xFFFFFFFFu, tmax0, 2));
        tmax1 = fmaxf(tmax1, __shfl_xor_sync(0xFFFFFFFFu, tmax1, 1));
        tmax1 = fmaxf(tmax1, __shfl_xor_sync(0xFFFFFFFFu, tmax1, 2));

        const float mnew0 = fmaxf(mrow0, tmax0);
        const float mnew1 = fmaxf(mrow1, tmax1);
        const float cf0 = __expf(mrow0 - mnew0);
        const float cf1 = __expf(mrow1 - mnew1);
        mrow0 = mnew0; mrow1 = mnew1;

        unsigned pfrag[8][2];
        float psum0 = 0.f, psum1 = 0.f;
        #pragma unroll
        for (int nt = 0; nt < 8; nt++) {
            const float p0 = __expf(sa[nt][0] - mnew0);
            const float p1 = __expf(sa[nt][1] - mnew0);
            const float p2 = __expf(sa[nt][2] - mnew1);
            const float p3 = __expf(sa[nt][3] - mnew1);
            psum0 += p0 + p1;
            psum1 += p2 + p3;
            pfrag[nt][0] = pack2(p0, p1);
            pfrag[nt][1] = pack2(p2, p3);
        }
        psum0 += __shfl_xor_sync(0xFFFFFFFFu, psum0, 1);
        psum0 += __shfl_xor_sync(0xFFFFFFFFu, psum0, 2);
        psum1 += __shfl_xor_sync(0xFFFFFFFFu, psum1, 1);
        psum1 += __shfl_xor_sync(0xFFFFFFFFu, psum1, 2);
        lrow0 = lrow0 * cf0 + psum0;
        lrow1 = lrow1 * cf1 + psum1;

        #pragma unroll
        for (int nt = 0; nt < 8; nt++) {
            oacc[nt][0] *= cf0; oacc[nt][1] *= cf0;
            oacc[nt][2] *= cf1; oacc[nt][3] *= cf1;
        }

        #pragma unroll
        for (int s = 0; s < 4; s++) {
            unsigned pa[4];
            pa[0] = pfrag[2 * s][0];
            pa[1] = pfrag[2 * s][1];
            pa[2] = pfrag[2 * s + 1][0];
            pa[3] = pfrag[2 * s + 1][1];
            #pragma unroll
            for (int nt = 0; nt < 8; nt++) {
                unsigned vfh[2];
                vfh[0] = VH[(8 * s + c) * VLD + nt * 8 + r];
                vfh[1] = VH[(8 * s + c + 4) * VLD + nt * 8 + r];
                mma_f16(oacc[nt], pa, vfh);
            }
        }
    }

    const float li0 = 1.f / lrow0;
    const float li1 = 1.f / lrow1;
    const int bb = bh >> 4, h = bh & 15;
    const int row0 = qt * ABQ + m0 + r;
    #pragma unroll
    for (int nt = 0; nt < 8; nt++) {
        const size_t wi0 = (size_t)(bb * SEQ + row0) * (INNER / 2) + h * 32 + nt * 4 + c;
        const size_t wi1 = (size_t)(bb * SEQ + row0 + 8) * (INNER / 2) + h * 32 + nt * 4 + c;
        g_aoH[wi0] = pack2(oacc[nt][0] * li0, oacc[nt][1] * li0);
        g_aoH[wi1] = pack2(oacc[nt][2] * li1, oacc[nt][3] * li1);
    }
}

// ---------------- launch ------------------------------------------------------
extern "C" void kernel_launch(void* const* d_in, const int* in_sizes, int n_in,
                              void* d_out, int out_size) {
    const float* x       = (const float*)d_in[0];
    const float* gamma   = (const float*)d_in[1];
    const float* beta    = (const float*)d_in[2];
    const float* null_kv = (const float*)d_in[3];
    const float* Wq      = (const float*)d_in[4];
    const float* Wkv     = (const float*)d_in[5];
    const float* q_scale = (const float*)d_in[6];
    const float* k_scale = (const float*)d_in[7];
    const float* Wo      = (const float*)d_in[8];
    float* out = (float*)d_out;

    unsigned* wop;
    cudaGetSymbolAddress((void**)&wop, g_WoP);

    cudaFuncSetAttribute(gemm_qkv_kernel, cudaFuncAttributeMaxDynamicSharedMemorySize, GEMM_SMEM);
    cudaFuncSetAttribute(gemm_o_kernel,   cudaFuncAttributeMaxDynamicSharedMemorySize, GEMM_SMEM);
    cudaFuncSetAttribute(attn_mma_kernel, cudaFuncAttributeMaxDynamicSharedMemorySize, ATT_SMEM);

    pack_qkv<<<768, 256>>>(Wq, Wkv);
    pack_w<<<512, 256>>>(Wo, wop, INNER, DIM);
    ln_kernel<<<TOKENS, 256>>>(x, gamma, beta);
    null_prep<<<BATCH * HEADS, 32>>>(null_kv, k_scale);
    gemm_qkv_kernel<<<dim3(NQKV / 128, TOKENS / 128), 256, GEMM_SMEM>>>(q_scale, k_scale);
    attn_mma_kernel<<<dim3(SEQ / ABQ, BATCH * HEADS), 256, ATT_SMEM>>>();
    gemm_o_kernel<<<dim3(DIM / 128, TOKENS / 128), 256, GEMM_SMEM>>>(out);
}

// round 13
// speedup vs baseline: 11.3396x; 1.0398x over previous
#include <cuda_runtime.h>
#include <cuda_fp16.h>
#include <math.h>

#define HEADS   16
#define DHEAD   64
#define BATCH   4
#define SEQ     2048
#define DIM     1024
#define INNER   1024
#define TOKENS  (BATCH*SEQ)       /* 8192 */
#define KVLEN   (SEQ+1)           /* 2049; null slot now at j=2048 */
#define SCALE_F 8.0f
#define LN_EPS  1e-5f
#define L2_EPS  1e-12f

#define NQKV    (3 * INNER)
#define KTPITCH 2112              /* K columns pad (>= 2048+64) */
#define VROWSP  1056              /* V j-pair rows pad (>= 1025, tile-multiple) */

// ---------------- scratch (global device arrays; no allocations) -------------
__device__ unsigned g_xnH  [TOKENS * DIM / 2];     // LN out, packed fp16
__device__ unsigned g_WqkvP[(DIM / 2) * NQKV];     // fused packed weights
__device__ unsigned g_WoP  [(INNER / 2) * DIM];
__device__ unsigned g_QP   [64 * SEQ * 32];        // [bh][i][dw]
__device__ unsigned g_KtP  [64 * 32 * KTPITCH];    // [bh][dd][j]  (d-pair words)
__device__ unsigned g_VtP  [64 * VROWSP * 64];     // [bh][jj][d]  (j-pair words)
__device__ unsigned g_aoH  [TOKENS * INNER / 2];   // attention out, packed fp16

// ---------------- fp16 / async helpers ------------------------------------------
__device__ __forceinline__ void mma_f16(float* c, const unsigned* a, const unsigned* b) {
    asm volatile(
        "mma.sync.aligned.m16n8k16.row.col.f32.f16.f16.f32 "
        "{%0,%1,%2,%3}, {%4,%5,%6,%7}, {%8,%9}, {%0,%1,%2,%3};"
        : "+f"(c[0]), "+f"(c[1]), "+f"(c[2]), "+f"(c[3])
        : "r"(a[0]), "r"(a[1]), "r"(a[2]), "r"(a[3]), "r"(b[0]), "r"(b[1]));
}
__device__ __forceinline__ unsigned pack2(float a, float b) {
    __half2 h2 = __floats2half2_rn(a, b);
    return *(unsigned*)&h2;
}
__device__ __forceinline__ void cp_async16(unsigned smem_addr, const void* gptr) {
    asm volatile("cp.async.cg.shared.global [%0], [%1], 16;"
                 :: "r"(smem_addr), "l"(gptr) : "memory");
}
__device__ __forceinline__ void cp_commit() {
    asm volatile("cp.async.commit_group;" ::: "memory");
}
__device__ __forceinline__ void cp_wait0() {
    asm volatile("cp.async.wait_group 0;" ::: "memory");
}

// ---------------- LayerNorm (writes packed fp16) --------------------------------
__global__ void __launch_bounds__(256) ln_kernel(const float* __restrict__ x,
                                                 const float* __restrict__ gamma,
                                                 const float* __restrict__ beta) {
    __shared__ float red[8][2];
    const int t = blockIdx.x;
    const int i = threadIdx.x;
    const float4 v = ((const float4*)(x + (size_t)t * DIM))[i];
    float s  = v.x + v.y + v.z + v.w;
    float ss = v.x*v.x + v.y*v.y + v.z*v.z + v.w*v.w;
    #pragma unroll
    for (int o = 16; o > 0; o >>= 1) {
        s  += __shfl_xor_sync(0xFFFFFFFFu, s,  o);
        ss += __shfl_xor_sync(0xFFFFFFFFu, ss, o);
    }
    const int w = i >> 5, l = i & 31;
    if (l == 0) { red[w][0] = s; red[w][1] = ss; }
    __syncthreads();
    if (w == 0) {
        s  = (l < 8) ? red[l][0] : 0.f;
        ss = (l < 8) ? red[l][1] : 0.f;
        #pragma unroll
        for (int o = 4; o > 0; o >>= 1) {
            s  += __shfl_xor_sync(0xFFFFFFFFu, s,  o);
            ss += __shfl_xor_sync(0xFFFFFFFFu, ss, o);
        }
        if (l == 0) { red[0][0] = s; red[0][1] = ss; }
    }
    __syncthreads();
    const float mu   = red[0][0] * (1.f / DIM);
    const float var  = red[0][1] * (1.f / DIM) - mu * mu;
    const float rstd = rsqrtf(var + LN_EPS);
    const float4 g  = ((const float4*)gamma)[i];
    const float4 be = ((const float4*)beta)[i];
    float4 o4;
    o4.x = (v.x - mu) * rstd * g.x + be.x;
    o4.y = (v.y - mu) * rstd * g.y + be.y;
    o4.z = (v.z - mu) * rstd * g.z + be.z;
    o4.w = (v.w - mu) * rstd * g.w + be.w;
    const size_t wi = (size_t)t * (DIM / 2) + 2 * i;
    *(uint2*)&g_xnH[wi] = make_uint2(pack2(o4.x, o4.y), pack2(o4.z, o4.w));
}

// ---------------- weight packing -------------------------------------------------
__global__ void __launch_bounds__(256) pack_qkv(const float* __restrict__ Wq,
                                                const float* __restrict__ Wkv) {
    const int total = (DIM / 2) * NQKV;
    for (int idx = blockIdx.x * 256 + threadIdx.x; idx < total; idx += gridDim.x * 256) {
        const int kp = idx / NQKV;
        const int n  = idx - kp * NQKV;
        float a, b;
        if (n < INNER) {
            a = Wq[(size_t)(2 * kp) * INNER + n];
            b = Wq[(size_t)(2 * kp + 1) * INNER + n];
        } else {
            const int nk = (n < 2 * INNER) ? (n - INNER) : (n - 2 * INNER + INNER);
            a = Wkv[(size_t)(2 * kp) * (2 * INNER) + nk];
            b = Wkv[(size_t)(2 * kp + 1) * (2 * INNER) + nk];
        }
        g_WqkvP[idx] = pack2(a, b);
    }
}
__global__ void __launch_bounds__(256) pack_w(const float* __restrict__ W,
                                              unsigned* __restrict__ WP,
                                              int K, int N) {
    const int total = (K / 2) * N;
    for (int idx = blockIdx.x * 256 + threadIdx.x; idx < total; idx += gridDim.x * 256) {
        const int kp = idx / N;
        const int n  = idx - kp * N;
        WP[idx] = pack2(W[(size_t)(2 * kp) * N + n], W[(size_t)(2 * kp + 1) * N + n]);
    }
}

// ---------------- fp16 single-pass GEMM mainloop (cp.async pipelined) ----------
#define ASLD 20
#define BSLD 136
#define GSTAGE_W (128 * ASLD + 16 * BSLD)
#define GEMM_SMEM (2 * GSTAGE_W * 4)

#define GEMM_MAINLOOP(AH, BP, N, K)                                               \
    extern __shared__ unsigned gsm[];                                             \
    const unsigned gsb = (unsigned)__cvta_generic_to_shared(gsm);                 \
    const int tid  = threadIdx.x;                                                 \
    const int warp = tid >> 5;                                                    \
    const int lane = tid & 31;                                                    \
    const int r = lane >> 2;                                                      \
    const int c = lane & 3;                                                       \
    const int wm = (warp & 3) * 32;                                               \
    const int wn = (warp >> 2) * 64;                                              \
    const int rowBase = blockIdx.y * 128;                                         \
    const int colBase = blockIdx.x * 128;                                         \
    const int arow = tid >> 1;                                                    \
    const int asel = (tid & 1) * 8;                                               \
    const int bkp  = tid >> 4;                                                    \
    const int bn0  = (tid & 15) * 8;                                              \
    const unsigned* ApH = (AH) + (size_t)(rowBase + arow) * ((K) / 2) + asel;     \
    const unsigned* BpP = (BP) + colBase + bn0;                                   \
    float acc[2][8][4];                                                           \
    _Pragma("unroll")                                                             \
    for (int mi = 0; mi < 2; mi++)                                                \
        _Pragma("unroll")                                                         \
        for (int ni = 0; ni < 8; ni++)                                            \
            _Pragma("unroll")                                                     \
            for (int j = 0; j < 4; j++) acc[mi][ni][j] = 0.f;                     \
    const int NC = (K) / 32;                                                      \
    const unsigned aoff0 = (arow * ASLD + asel) * 4;                              \
    const unsigned boff0 = (128 * ASLD + bkp * BSLD + bn0) * 4;                   \
    auto fill_async = [&](int ck) {                                               \
        const unsigned st = gsb + ((ck & 1) * GSTAGE_W) * 4;                      \
        const int kw = ck * 16;                                                   \
        cp_async16(st + aoff0,      ApH + kw);                                    \
        cp_async16(st + aoff0 + 16, ApH + kw + 4);                                \
        const unsigned* bp = BpP + (size_t)(kw + bkp) * (N);                      \
        cp_async16(st + boff0,      bp);                                          \
        cp_async16(st + boff0 + 16, bp + 4);                                      \
    };                                                                            \
    fill_async(0);                                                                \
    cp_commit();                                                                  \
    _Pragma("unroll 1")                                                           \
    for (int ck = 0; ck < NC; ck++) {                                             \
        cp_wait0();                                                               \
        __syncthreads();                                                          \
        if (ck + 1 < NC) { fill_async(ck + 1); cp_commit(); }                     \
        const unsigned* st  = gsm + (ck & 1) * GSTAGE_W;                          \
        const unsigned* AsH = st;                                                 \
        const unsigned* Bs  = st + 128 * ASLD;                                    \
        _Pragma("unroll")                                                         \
        for (int s = 0; s < 2; s++) {                                             \
            unsigned ah[2][4];                                                    \
            _Pragma("unroll")                                                     \
            for (int mi = 0; mi < 2; mi++) {                                      \
                const int row = wm + mi * 16;                                     \
                ah[mi][0] = AsH[(row + r) * ASLD + 8 * s + c];                    \
                ah[mi][1] = AsH[(row + 8 + r) * ASLD + 8 * s + c];                \
                ah[mi][2] = AsH[(row + r) * ASLD + 8 * s + c + 4];                \
                ah[mi][3] = AsH[(row + 8 + r) * ASLD + 8 * s + c + 4];            \
            }                                                                     \
            _Pragma("unroll")                                                     \
            for (int ni = 0; ni < 8; ni++) {                                      \
                unsigned bf[2];                                                   \
                bf[0] = Bs[(8 * s + c) * BSLD + wn + ni * 8 + r];                 \
                bf[1] = Bs[(8 * s + c + 4) * BSLD + wn + ni * 8 + r];             \
                _Pragma("unroll")                                                 \
                for (int mi = 0; mi < 2; mi++)                                    \
                    mma_f16(acc[mi][ni], ah[mi], bf);                             \
            }                                                                     \
        }                                                                         \
    }

// ---- fused q|k|v projection: epilogue dispatch by column range -----------------
__global__ void __launch_bounds__(256, 2) gemm_qkv_kernel(const float* __restrict__ q_scale,
                                                          const float* __restrict__ k_scale) {
    GEMM_MAINLOOP(g_xnH, g_WqkvP, NQKV, DIM)
    const int nbase = colBase + wn;          // 0..3071, head-aligned (64)
    if (nbase < INNER) {
        // ---- q path: l2norm + q_scale + SCALE -> g_QP ----
        const int h = nbase >> 6;
        #pragma unroll
        for (int mi = 0; mi < 2; mi++) {
            const int row0 = rowBase + wm + mi * 16 + r;
            float ss0 = 0.f, ss1 = 0.f;
            #pragma unroll
            for (int ni = 0; ni < 8; ni++) {
                ss0 += acc[mi][ni][0] * acc[mi][ni][0] + acc[mi][ni][1] * acc[mi][ni][1];
                ss1 += acc[mi][ni][2] * acc[mi][ni][2] + acc[mi][ni][3] * acc[mi][ni][3];
            }
            ss0 += __shfl_xor_sync(0xFFFFFFFFu, ss0, 1);
            ss0 += __shfl_xor_sync(0xFFFFFFFFu, ss0, 2);
            ss1 += __shfl_xor_sync(0xFFFFFFFFu, ss1, 1);
            ss1 += __shfl_xor_sync(0xFFFFFFFFu, ss1, 2);
            const float f0 = SCALE_F / fmaxf(sqrtf(ss0), L2_EPS);
            const float f1 = SCALE_F / fmaxf(sqrtf(ss1), L2_EPS);
            #pragma unroll
            for (int ni = 0; ni < 8; ni++) {
                const float2 qs = *(const float2*)&q_scale[ni * 8 + 2 * c];
                const int bb0 = row0 >> 11, i0 = row0 & 2047;
                const int bb1 = (row0 + 8) >> 11, i1 = (row0 + 8) & 2047;
                g_QP[((size_t)(bb0 * HEADS + h) * SEQ + i0) * 32 + ni * 4 + c] =
                    pack2(acc[mi][ni][0] * f0 * qs.x, acc[mi][ni][1] * f0 * qs.y);
                g_QP[((size_t)(bb1 * HEADS + h) * SEQ + i1) * 32 + ni * 4 + c] =
                    pack2(acc[mi][ni][2] * f1 * qs.x, acc[mi][ni][3] * f1 * qs.y);
            }
        }
    } else if (nbase < 2 * INNER) {
        // ---- k path: l2norm + k_scale -> transposed packed g_KtP (token i at j=i) ----
        const int h = (nbase - INNER) >> 6;
        #pragma unroll
        for (int mi = 0; mi < 2; mi++) {
            const int row0 = rowBase + wm + mi * 16 + r;
            float ss0 = 0.f, ss1 = 0.f;
            #pragma unroll
            for (int ni = 0; ni < 8; ni++) {
                ss0 += acc[mi][ni][0] * acc[mi][ni][0] + acc[mi][ni][1] * acc[mi][ni][1];
                ss1 += acc[mi][ni][2] * acc[mi][ni][2] + acc[mi][ni][3] * acc[mi][ni][3];
            }
            ss0 += __shfl_xor_sync(0xFFFFFFFFu, ss0, 1);
            ss0 += __shfl_xor_sync(0xFFFFFFFFu, ss0, 2);
            ss1 += __shfl_xor_sync(0xFFFFFFFFu, ss1, 1);
            ss1 += __shfl_xor_sync(0xFFFFFFFFu, ss1, 2);
            const float f0 = 1.f / fmaxf(sqrtf(ss0), L2_EPS);
            const float f1 = 1.f / fmaxf(sqrtf(ss1), L2_EPS);
            #pragma unroll
            for (int ni = 0; ni < 8; ni++) {
                const float2 ks = *(const float2*)&k_scale[ni * 8 + 2 * c];
                const int dd = ni * 4 + c;
                const int bb0 = row0 >> 11, i0 = row0 & 2047;
                const int bb1 = (row0 + 8) >> 11, i1 = (row0 + 8) & 2047;
                g_KtP[((size_t)(bb0 * HEADS + h) * 32 + dd) * KTPITCH + i0] =
                    pack2(acc[mi][ni][0] * f0 * ks.x, acc[mi][ni][1] * f0 * ks.y);
                g_KtP[((size_t)(bb1 * HEADS + h) * 32 + dd) * KTPITCH + i1] =
                    pack2(acc[mi][ni][2] * f1 * ks.x, acc[mi][ni][3] * f1 * ks.y);
            }
        }
    } else {
        // ---- v path: j-pair transpose via lane-xor-4 shuffle -> g_VtP[bh][jj][d] ----
        const int h = (nbase - 2 * INNER) >> 6;
        const bool evenr = ((lane >> 2) & 1) == 0;
        #pragma unroll
        for (int mi = 0; mi < 2; mi++) {
            const int row0 = rowBase + wm + mi * 16 + r;   // even when r even
            #pragma unroll
            for (int ni = 0; ni < 8; ni++) {
                const float p0 = __shfl_xor_sync(0xFFFFFFFFu, acc[mi][ni][0], 4);
                const float p1 = __shfl_xor_sync(0xFFFFFFFFu, acc[mi][ni][1], 4);
                const float p2 = __shfl_xor_sync(0xFFFFFFFFu, acc[mi][ni][2], 4);
                const float p3 = __shfl_xor_sync(0xFFFFFFFFu, acc[mi][ni][3], 4);
                if (evenr) {
                    const int bb = row0 >> 11;
                    const int i0 = row0 & 2047;
                    const int jj = i0 >> 1;
                    const int d0 = ni * 8 + 2 * c;
                    unsigned* base = g_VtP + (size_t)(bb * HEADS + h) * VROWSP * 64;
                    *(uint2*)&base[(size_t)jj * 64 + d0] =
                        make_uint2(pack2(acc[mi][ni][0], p0), pack2(acc[mi][ni][1], p1));
                    *(uint2*)&base[(size_t)(jj + 4) * 64 + d0] =
                        make_uint2(pack2(acc[mi][ni][2], p2), pack2(acc[mi][ni][3], p3));
                }
            }
        }
    }
}

// ---- output projection ----
__global__ void __launch_bounds__(256, 2) gemm_o_kernel(float* __restrict__ out) {
    GEMM_MAINLOOP(g_aoH, g_WoP, DIM, INNER)
    #pragma unroll
    for (int mi = 0; mi < 2; mi++) {
        const int row = rowBase + wm + mi * 16 + r;
        #pragma unroll
        for (int ni = 0; ni < 8; ni++) {
            const int col = colBase + wn + ni * 8 + 2 * c;
            *(float2*)&out[(size_t)row * DIM + col]       = make_float2(acc[mi][ni][0], acc[mi][ni][1]);
            *(float2*)&out[(size_t)(row + 8) * DIM + col] = make_float2(acc[mi][ni][2], acc[mi][ni][3]);
        }
    }
}

// ---------------- null slot at j=2048 -------------------------------------------
__global__ void null_prep(const float* __restrict__ null_kv,
                          const float* __restrict__ k_scale) {
    const int bh = blockIdx.x;
    const int h = bh & 15;
    const int lane = threadIdx.x;
    const int src0 = (2 * lane) & 31;
    const int src1 = (2 * lane + 1) & 31;
    const float* nk = null_kv + h * DHEAD;
    const float* nv = null_kv + HEADS * DHEAD + h * DHEAD;
    float k0 = nk[lane], k1 = nk[lane + 32];
    float ss = k0 * k0 + k1 * k1;
    #pragma unroll
    for (int o = 16; o > 0; o >>= 1) ss += __shfl_xor_sync(0xFFFFFFFFu, ss, o);
    const float inv = 1.f / fmaxf(sqrtf(ss), L2_EPS);
    const float kk0 = k0 * inv * k_scale[lane];
    const float kk1 = k1 * inv * k_scale[lane + 32];
    {
        float s0a = __shfl_sync(0xFFFFFFFFu, kk0, src0);
        float s0b = __shfl_sync(0xFFFFFFFFu, kk0, src1);
        float s1a = __shfl_sync(0xFFFFFFFFu, kk1, src0);
        float s1b = __shfl_sync(0xFFFFFFFFu, kk1, src1);
        const float a = (lane < 16) ? s0a : s1a;
        const float b = (lane < 16) ? s0b : s1b;
        g_KtP[((size_t)bh * 32 + lane) * KTPITCH + 2048] = pack2(a, b);
    }
    // V null: j-pair (2048, 2049-pad) -> word (null_v, 0) at jj=1024
    const float v0 = nv[lane], v1 = nv[lane + 32];
    unsigned* base = g_VtP + ((size_t)bh * VROWSP + 1024) * 64;
    base[lane]      = pack2(v0, 0.f);
    base[lane + 32] = pack2(v1, 0.f);
}

// ---------------- flash attention: cp.async double-buffered fills ---------------
#define ABQ 128
#define ABK 64
#define ANT ((KVLEN + ABK - 1) / ABK)   /* 33 */
#define KTLD 72
#define VLD  72
#define AST_W (32 * KTLD + 32 * VLD)    /* 4608 words per stage */

#define ATT_SMEM (2 * AST_W * 4)        /* 36864 B */

__global__ void __launch_bounds__(256, 2) attn_mma_kernel() {
    extern __shared__ unsigned ash[];
    const unsigned asb = (unsigned)__cvta_generic_to_shared(ash);

    const int tid  = threadIdx.x;
    const int warp = tid >> 5;
    const int lane = tid & 31;
    const int r = lane >> 2;
    const int c = lane & 3;
    const int bh = blockIdx.y;
    const int qt = blockIdx.x;
    const int m0 = warp * 16;

    // ---- Q fragments: direct packed fp16 loads ----
    const unsigned* QgP = g_QP + ((size_t)bh * SEQ + (size_t)qt * ABQ + m0) * 32;
    unsigned qh[4][4];
    #pragma unroll
    for (int s = 0; s < 4; s++) {
        qh[s][0] = QgP[(size_t)r * 32 + s * 8 + c];
        qh[s][1] = QgP[(size_t)(r + 8) * 32 + s * 8 + c];
        qh[s][2] = QgP[(size_t)r * 32 + s * 8 + c + 4];
        qh[s][3] = QgP[(size_t)(r + 8) * 32 + s * 8 + c + 4];
    }

    float oacc[8][4];
    #pragma unroll
    for (int nt = 0; nt < 8; nt++)
        #pragma unroll
        for (int j = 0; j < 4; j++) oacc[nt][j] = 0.f;
    float mrow0 = -1e30f, mrow1 = -1e30f, lrow0 = 0.f, lrow1 = 0.f;

    // fill addressing (pads are zero-initialized -> unchecked copies safe)
    const unsigned* KtG = g_KtP + ((size_t)bh * 32 + (tid >> 3)) * KTPITCH + (tid & 7) * 8;
    const unsigned* VtG = g_VtP + ((size_t)bh * VROWSP + (tid >> 3)) * 64 + (tid & 7) * 8;
    const unsigned koff = ((tid >> 3) * KTLD + (tid & 7) * 8) * 4;
    const unsigned voff = (32 * KTLD + (tid >> 3) * VLD + (tid & 7) * 8) * 4;

    auto fill_async = [&](int kt) {
        const unsigned st = asb + ((kt & 1) * AST_W) * 4;
        const int kvbase = kt * ABK;
        cp_async16(st + koff,      KtG + kvbase);
        cp_async16(st + koff + 16, KtG + kvbase + 4);
        const unsigned* vp = VtG + (size_t)(kt * 32) * 64;
        cp_async16(st + voff,      vp);
        cp_async16(st + voff + 16, vp + 4);
    };

    fill_async(0);
    cp_commit();

    for (int kt = 0; kt < ANT; kt++) {
        const int kvbase = kt * ABK;
        cp_wait0();
        __syncthreads();
        if (kt + 1 < ANT) { fill_async(kt + 1); cp_commit(); }

        const unsigned* KtH = ash + (kt & 1) * AST_W;
        const unsigned* VH  = KtH + 32 * KTLD;

        // ---- S = Q K^T (single-pass fp16) ----
        float sa[8][4];
        #pragma unroll
        for (int nt = 0; nt < 8; nt++)
            #pragma unroll
            for (int j = 0; j < 4; j++) sa[nt][j] = 0.f;

        #pragma unroll
        for (int s = 0; s < 4; s++) {
            #pragma unroll
            for (int nt = 0; nt < 8; nt++) {
                unsigned bfh[2];
                bfh[0] = KtH[(8 * s + c) * KTLD + nt * 8 + r];
                bfh[1] = KtH[(8 * s + c + 4) * KTLD + nt * 8 + r];
                mma_f16(sa[nt], qh[s], bfh);
            }
        }

        // ---- mask + online softmax -> P fragments in registers ----
        float tmax0 = -1e30f, tmax1 = -1e30f;
        #pragma unroll
        for (int nt = 0; nt < 8; nt++) {
            const int j0 = kvbase + nt * 8 + 2 * c;
            if (j0 >= KVLEN)     { sa[nt][0] = -1e30f; sa[nt][2] = -1e30f; }
            if (j0 + 1 >= KVLEN) { sa[nt][1] = -1e30f; sa[nt][3] = -1e30f; }
            tmax0 = fmaxf(tmax0, fmaxf(sa[nt][0], sa[nt][1]));
            tmax1 = fmaxf(tmax1, fmaxf(sa[nt][2], sa[nt][3]));
        }
        tmax0 = fmaxf(tmax0, __shfl_xor_sync(0xFFFFFFFFu, tmax0, 1));
        tmax0 = fmaxf(tmax0, __shfl_xor_sync(0xFFFFFFFFu, tmax0, 2));
        tmax1 = fmaxf(tmax1, __shfl_xor_sync(0xFFFFFFFFu, tmax1, 1));
        tmax1 = fmaxf(tmax1, __shfl_xor_sync(0xFFFFFFFFu, tmax1, 2));

        const float mnew0 = fmaxf(mrow0, tmax0);
        const float mnew1 = fmaxf(mrow1, tmax1);
        const float cf0 = __expf(mrow0 - mnew0);
        const float cf1 = __expf(mrow1 - mnew1);
        mrow0 = mnew0; mrow1 = mnew1;

        unsigned pfrag[8][2];
        float psum0 = 0.f, psum1 = 0.f;
        #pragma unroll
        for (int nt = 0; nt < 8; nt++) {
            const float p0 = __expf(sa[nt][0] - mnew0);
            const float p1 = __expf(sa[nt][1] - mnew0);
            const float p2 = __expf(sa[nt][2] - mnew1);
            const float p3 = __expf(sa[nt][3] - mnew1);
            psum0 += p0 + p1;
            psum1 += p2 + p3;
            pfrag[nt][0] = pack2(p0, p1);
            pfrag[nt][1] = pack2(p2, p3);
        }
        psum0 += __shfl_xor_sync(0xFFFFFFFFu, psum0, 1);
        psum0 += __shfl_xor_sync(0xFFFFFFFFu, psum0, 2);
        psum1 += __shfl_xor_sync(0xFFFFFFFFu, psum1, 1);
        psum1 += __shfl_xor_sync(0xFFFFFFFFu, psum1, 2);
        lrow0 = lrow0 * cf0 + psum0;
        lrow1 = lrow1 * cf1 + psum1;

        #pragma unroll
        for (int nt = 0; nt < 8; nt++) {
            oacc[nt][0] *= cf0; oacc[nt][1] *= cf0;
            oacc[nt][2] *= cf1; oacc[nt][3] *= cf1;
        }

        // ---- O += P V (single pass; V already j-pair packed) ----
        #pragma unroll
        for (int s = 0; s < 4; s++) {
            unsigned pa[4];
            pa[0] = pfrag[2 * s][0];
            pa[1] = pfrag[2 * s][1];
            pa[2] = pfrag[2 * s + 1][0];
            pa[3] = pfrag[2 * s + 1][1];
            #pragma unroll
            for (int nt = 0; nt < 8; nt++) {
                unsigned vfh[2];
                vfh[0] = VH[(8 * s + c) * VLD + nt * 8 + r];
                vfh[1] = VH[(8 * s + c + 4) * VLD + nt * 8 + r];
                mma_f16(oacc[nt], pa, vfh);
            }
        }
    }

    // ---- epilogue: write packed fp16 for gemm_o ----
    const float li0 = 1.f / lrow0;
    const float li1 = 1.f / lrow1;
    const int bb = bh >> 4, h = bh & 15;
    const int row0 = qt * ABQ + m0 + r;
    #pragma unroll
    for (int nt = 0; nt < 8; nt++) {
        const size_t wi0 = (size_t)(bb * SEQ + row0) * (INNER / 2) + h * 32 + nt * 4 + c;
        const size_t wi1 = (size_t)(bb * SEQ + row0 + 8) * (INNER / 2) + h * 32 + nt * 4 + c;
        g_aoH[wi0] = pack2(oacc[nt][0] * li0, oacc[nt][1] * li0);
        g_aoH[wi1] = pack2(oacc[nt][2] * li1, oacc[nt][3] * li1);
    }
}

// ---------------- launch ------------------------------------------------------
extern "C" void kernel_launch(void* const* d_in, const int* in_sizes, int n_in,
                              void* d_out, int out_size) {
    const float* x       = (const float*)d_in[0];
    const float* gamma   = (const float*)d_in[1];
    const float* beta    = (const float*)d_in[2];
    const float* null_kv = (const float*)d_in[3];
    const float* Wq      = (const float*)d_in[4];
    const float* Wkv     = (const float*)d_in[5];
    const float* q_scale = (const float*)d_in[6];
    const float* k_scale = (const float*)d_in[7];
    const float* Wo      = (const float*)d_in[8];
    float* out = (float*)d_out;

    unsigned* wop;
    cudaGetSymbolAddress((void**)&wop, g_WoP);

    cudaFuncSetAttribute(gemm_qkv_kernel, cudaFuncAttributeMaxDynamicSharedMemorySize, GEMM_SMEM);
    cudaFuncSetAttribute(gemm_o_kernel,   cudaFuncAttributeMaxDynamicSharedMemorySize, GEMM_SMEM);
    cudaFuncSetAttribute(attn_mma_kernel, cudaFuncAttributeMaxDynamicSharedMemorySize, ATT_SMEM);

    pack_qkv<<<768, 256>>>(Wq, Wkv);
    pack_w<<<512, 256>>>(Wo, wop, INNER, DIM);
    ln_kernel<<<TOKENS, 256>>>(x, gamma, beta);
    null_prep<<<BATCH * HEADS, 32>>>(null_kv, k_scale);
    gemm_qkv_kernel<<<dim3(NQKV / 128, TOKENS / 128), 256, GEMM_SMEM>>>(q_scale, k_scale);
    attn_mma_kernel<<<dim3(SEQ / ABQ, BATCH * HEADS), 256, ATT_SMEM>>>();
    gemm_o_kernel<<<dim3(DIM / 128, TOKENS / 128), 256, GEMM_SMEM>>>(out);
}

// round 14
// speedup vs baseline: 11.4806x; 1.0124x over previous
#include <cuda_runtime.h>
#include <cuda_fp16.h>
#include <math.h>

#define HEADS   16
#define DHEAD   64
#define BATCH   4
#define SEQ     2048
#define DIM     1024
#define INNER   1024
#define TOKENS  (BATCH*SEQ)       /* 8192 */
#define KVLEN   (SEQ+1)           /* 2049; null slot at j=2048 */
#define SCALE_F 8.0f
#define LN_EPS  1e-5f
#define L2_EPS  1e-12f

#define NQKV    (3 * INNER)
#define KTPITCH 2112
#define VROWSP  1056

// ---------------- scratch (global device arrays; no allocations) -------------
__device__ unsigned g_xnH  [TOKENS * DIM / 2];
__device__ unsigned g_WqkvP[(DIM / 2) * NQKV];
__device__ unsigned g_WoP  [(INNER / 2) * DIM];
__device__ unsigned g_QP   [64 * SEQ * 32];
__device__ unsigned g_KtP  [64 * 32 * KTPITCH];
__device__ unsigned g_VtP  [64 * VROWSP * 64];
__device__ unsigned g_aoH  [TOKENS * INNER / 2];

// ---------------- fp16 / async helpers ------------------------------------------
__device__ __forceinline__ void mma_f16(float* c, const unsigned* a, const unsigned* b) {
    asm volatile(
        "mma.sync.aligned.m16n8k16.row.col.f32.f16.f16.f32 "
        "{%0,%1,%2,%3}, {%4,%5,%6,%7}, {%8,%9}, {%0,%1,%2,%3};"
        : "+f"(c[0]), "+f"(c[1]), "+f"(c[2]), "+f"(c[3])
        : "r"(a[0]), "r"(a[1]), "r"(a[2]), "r"(a[3]), "r"(b[0]), "r"(b[1]));
}
__device__ __forceinline__ unsigned pack2(float a, float b) {
    __half2 h2 = __floats2half2_rn(a, b);
    return *(unsigned*)&h2;
}
__device__ __forceinline__ void cp_async16(unsigned smem_addr, const void* gptr) {
    asm volatile("cp.async.cg.shared.global [%0], [%1], 16;"
                 :: "r"(smem_addr), "l"(gptr) : "memory");
}
__device__ __forceinline__ void cp_commit() {
    asm volatile("cp.async.commit_group;" ::: "memory");
}
__device__ __forceinline__ void cp_wait0() {
    asm volatile("cp.async.wait_group 0;" ::: "memory");
}
__device__ __forceinline__ void cp_wait1() {
    asm volatile("cp.async.wait_group 1;" ::: "memory");
}

// ---------------- LayerNorm (writes packed fp16) --------------------------------
__global__ void __launch_bounds__(256) ln_kernel(const float* __restrict__ x,
                                                 const float* __restrict__ gamma,
                                                 const float* __restrict__ beta) {
    __shared__ float red[8][2];
    const int t = blockIdx.x;
    const int i = threadIdx.x;
    const float4 v = ((const float4*)(x + (size_t)t * DIM))[i];
    float s  = v.x + v.y + v.z + v.w;
    float ss = v.x*v.x + v.y*v.y + v.z*v.z + v.w*v.w;
    #pragma unroll
    for (int o = 16; o > 0; o >>= 1) {
        s  += __shfl_xor_sync(0xFFFFFFFFu, s,  o);
        ss += __shfl_xor_sync(0xFFFFFFFFu, ss, o);
    }
    const int w = i >> 5, l = i & 31;
    if (l == 0) { red[w][0] = s; red[w][1] = ss; }
    __syncthreads();
    if (w == 0) {
        s  = (l < 8) ? red[l][0] : 0.f;
        ss = (l < 8) ? red[l][1] : 0.f;
        #pragma unroll
        for (int o = 4; o > 0; o >>= 1) {
            s  += __shfl_xor_sync(0xFFFFFFFFu, s,  o);
            ss += __shfl_xor_sync(0xFFFFFFFFu, ss, o);
        }
        if (l == 0) { red[0][0] = s; red[0][1] = ss; }
    }
    __syncthreads();
    const float mu   = red[0][0] * (1.f / DIM);
    const float var  = red[0][1] * (1.f / DIM) - mu * mu;
    const float rstd = rsqrtf(var + LN_EPS);
    const float4 g  = ((const float4*)gamma)[i];
    const float4 be = ((const float4*)beta)[i];
    float4 o4;
    o4.x = (v.x - mu) * rstd * g.x + be.x;
    o4.y = (v.y - mu) * rstd * g.y + be.y;
    o4.z = (v.z - mu) * rstd * g.z + be.z;
    o4.w = (v.w - mu) * rstd * g.w + be.w;
    const size_t wi = (size_t)t * (DIM / 2) + 2 * i;
    *(uint2*)&g_xnH[wi] = make_uint2(pack2(o4.x, o4.y), pack2(o4.z, o4.w));
}

// ---------------- weight packing -------------------------------------------------
__global__ void __launch_bounds__(256) pack_qkv(const float* __restrict__ Wq,
                                                const float* __restrict__ Wkv) {
    const int total = (DIM / 2) * NQKV;
    for (int idx = blockIdx.x * 256 + threadIdx.x; idx < total; idx += gridDim.x * 256) {
        const int kp = idx / NQKV;
        const int n  = idx - kp * NQKV;
        float a, b;
        if (n < INNER) {
            a = Wq[(size_t)(2 * kp) * INNER + n];
            b = Wq[(size_t)(2 * kp + 1) * INNER + n];
        } else {
            const int nk = (n < 2 * INNER) ? (n - INNER) : (n - 2 * INNER + INNER);
            a = Wkv[(size_t)(2 * kp) * (2 * INNER) + nk];
            b = Wkv[(size_t)(2 * kp + 1) * (2 * INNER) + nk];
        }
        g_WqkvP[idx] = pack2(a, b);
    }
}
__global__ void __launch_bounds__(256) pack_w(const float* __restrict__ W,
                                              unsigned* __restrict__ WP,
                                              int K, int N) {
    const int total = (K / 2) * N;
    for (int idx = blockIdx.x * 256 + threadIdx.x; idx < total; idx += gridDim.x * 256) {
        const int kp = idx / N;
        const int n  = idx - kp * N;
        WP[idx] = pack2(W[(size_t)(2 * kp) * N + n], W[(size_t)(2 * kp + 1) * N + n]);
    }
}

// ---------------- fp16 single-pass GEMM mainloop (3-stage cp.async) ------------
#define ASLD 20
#define BSLD 136
#define GSTAGE_W (128 * ASLD + 16 * BSLD)
#define GEMM_SMEM (3 * GSTAGE_W * 4)

#define GEMM_MAINLOOP(AH, BP, N, K)                                               \
    extern __shared__ unsigned gsm[];                                             \
    const unsigned gsb = (unsigned)__cvta_generic_to_shared(gsm);                 \
    const int tid  = threadIdx.x;                                                 \
    const int warp = tid >> 5;                                                    \
    const int lane = tid & 31;                                                    \
    const int r = lane >> 2;                                                      \
    const int c = lane & 3;                                                       \
    const int wm = (warp & 3) * 32;                                               \
    const int wn = (warp >> 2) * 64;                                              \
    const int rowBase = blockIdx.y * 128;                                         \
    const int colBase = blockIdx.x * 128;                                         \
    const int arow = tid >> 1;                                                    \
    const int asel = (tid & 1) * 8;                                               \
    const int bkp  = tid >> 4;                                                    \
    const int bn0  = (tid & 15) * 8;                                              \
    const unsigned* ApH = (AH) + (size_t)(rowBase + arow) * ((K) / 2) + asel;     \
    const unsigned* BpP = (BP) + colBase + bn0;                                   \
    float acc[2][8][4];                                                           \
    _Pragma("unroll")                                                             \
    for (int mi = 0; mi < 2; mi++)                                                \
        _Pragma("unroll")                                                         \
        for (int ni = 0; ni < 8; ni++)                                            \
            _Pragma("unroll")                                                     \
            for (int j = 0; j < 4; j++) acc[mi][ni][j] = 0.f;                     \
    const int NC = (K) / 32;                                                      \
    const unsigned aoff0 = (arow * ASLD + asel) * 4;                              \
    const unsigned boff0 = (128 * ASLD + bkp * BSLD + bn0) * 4;                   \
    auto fill_async = [&](int ck) {                                               \
        const unsigned st = gsb + ((ck % 3) * GSTAGE_W) * 4;                      \
        const int kw = ck * 16;                                                   \
        cp_async16(st + aoff0,      ApH + kw);                                    \
        cp_async16(st + aoff0 + 16, ApH + kw + 4);                                \
        const unsigned* bp = BpP + (size_t)(kw + bkp) * (N);                      \
        cp_async16(st + boff0,      bp);                                          \
        cp_async16(st + boff0 + 16, bp + 4);                                      \
    };                                                                            \
    fill_async(0);                                                                \
    cp_commit();                                                                  \
    fill_async(1);                                                                \
    cp_commit();                                                                  \
    _Pragma("unroll 1")                                                           \
    for (int ck = 0; ck < NC; ck++) {                                             \
        if (ck + 1 < NC) cp_wait1(); else cp_wait0();                             \
        __syncthreads();                                                          \
        if (ck + 2 < NC) { fill_async(ck + 2); cp_commit(); }                     \
        const unsigned* st  = gsm + (ck % 3) * GSTAGE_W;                          \
        const unsigned* AsH = st;                                                 \
        const unsigned* Bs  = st + 128 * ASLD;                                    \
        _Pragma("unroll")                                                         \
        for (int s = 0; s < 2; s++) {                                             \
            unsigned ah[2][4];                                                    \
            _Pragma("unroll")                                                     \
            for (int mi = 0; mi < 2; mi++) {                                      \
                const int row = wm + mi * 16;                                     \
                ah[mi][0] = AsH[(row + r) * ASLD + 8 * s + c];                    \
                ah[mi][1] = AsH[(row + 8 + r) * ASLD + 8 * s + c];                \
                ah[mi][2] = AsH[(row + r) * ASLD + 8 * s + c + 4];                \
                ah[mi][3] = AsH[(row + 8 + r) * ASLD + 8 * s + c + 4];            \
            }                                                                     \
            _Pragma("unroll")                                                     \
            for (int ni = 0; ni < 8; ni++) {                                      \
                unsigned bf[2];                                                   \
                bf[0] = Bs[(8 * s + c) * BSLD + wn + ni * 8 + r];                 \
                bf[1] = Bs[(8 * s + c + 4) * BSLD + wn + ni * 8 + r];             \
                _Pragma("unroll")                                                 \
                for (int mi = 0; mi < 2; mi++)                                    \
                    mma_f16(acc[mi][ni], ah[mi], bf);                             \
            }                                                                     \
        }                                                                         \
    }

// ---- fused q|k|v projection: epilogue dispatch by column range -----------------
__global__ void __launch_bounds__(256, 2) gemm_qkv_kernel(const float* __restrict__ q_scale,
                                                          const float* __restrict__ k_scale) {
    GEMM_MAINLOOP(g_xnH, g_WqkvP, NQKV, DIM)
    const int nbase = colBase + wn;
    if (nbase < INNER) {
        const int h = nbase >> 6;
        #pragma unroll
        for (int mi = 0; mi < 2; mi++) {
            const int row0 = rowBase + wm + mi * 16 + r;
            float ss0 = 0.f, ss1 = 0.f;
            #pragma unroll
            for (int ni = 0; ni < 8; ni++) {
                ss0 += acc[mi][ni][0] * acc[mi][ni][0] + acc[mi][ni][1] * acc[mi][ni][1];
                ss1 += acc[mi][ni][2] * acc[mi][ni][2] + acc[mi][ni][3] * acc[mi][ni][3];
            }
            ss0 += __shfl_xor_sync(0xFFFFFFFFu, ss0, 1);
            ss0 += __shfl_xor_sync(0xFFFFFFFFu, ss0, 2);
            ss1 += __shfl_xor_sync(0xFFFFFFFFu, ss1, 1);
            ss1 += __shfl_xor_sync(0xFFFFFFFFu, ss1, 2);
            const float f0 = SCALE_F / fmaxf(sqrtf(ss0), L2_EPS);
            const float f1 = SCALE_F / fmaxf(sqrtf(ss1), L2_EPS);
            #pragma unroll
            for (int ni = 0; ni < 8; ni++) {
                const float2 qs = *(const float2*)&q_scale[ni * 8 + 2 * c];
                const int bb0 = row0 >> 11, i0 = row0 & 2047;
                const int bb1 = (row0 + 8) >> 11, i1 = (row0 + 8) & 2047;
                g_QP[((size_t)(bb0 * HEADS + h) * SEQ + i0) * 32 + ni * 4 + c] =
                    pack2(acc[mi][ni][0] * f0 * qs.x, acc[mi][ni][1] * f0 * qs.y);
                g_QP[((size_t)(bb1 * HEADS + h) * SEQ + i1) * 32 + ni * 4 + c] =
                    pack2(acc[mi][ni][2] * f1 * qs.x, acc[mi][ni][3] * f1 * qs.y);
            }
        }
    } else if (nbase < 2 * INNER) {
        const int h = (nbase - INNER) >> 6;
        #pragma unroll
        for (int mi = 0; mi < 2; mi++) {
            const int row0 = rowBase + wm + mi * 16 + r;
            float ss0 = 0.f, ss1 = 0.f;
            #pragma unroll
            for (int ni = 0; ni < 8; ni++) {
                ss0 += acc[mi][ni][0] * acc[mi][ni][0] + acc[mi][ni][1] * acc[mi][ni][1];
                ss1 += acc[mi][ni][2] * acc[mi][ni][2] + acc[mi][ni][3] * acc[mi][ni][3];
            }
            ss0 += __shfl_xor_sync(0xFFFFFFFFu, ss0, 1);
            ss0 += __shfl_xor_sync(0xFFFFFFFFu, ss0, 2);
            ss1 += __shfl_xor_sync(0xFFFFFFFFu, ss1, 1);
            ss1 += __shfl_xor_sync(0xFFFFFFFFu, ss1, 2);
            const float f0 = 1.f / fmaxf(sqrtf(ss0), L2_EPS);
            const float f1 = 1.f / fmaxf(sqrtf(ss1), L2_EPS);
            #pragma unroll
            for (int ni = 0; ni < 8; ni++) {
                const float2 ks = *(const float2*)&k_scale[ni * 8 + 2 * c];
                const int dd = ni * 4 + c;
                const int bb0 = row0 >> 11, i0 = row0 & 2047;
                const int bb1 = (row0 + 8) >> 11, i1 = (row0 + 8) & 2047;
                g_KtP[((size_t)(bb0 * HEADS + h) * 32 + dd) * KTPITCH + i0] =
                    pack2(acc[mi][ni][0] * f0 * ks.x, acc[mi][ni][1] * f0 * ks.y);
                g_KtP[((size_t)(bb1 * HEADS + h) * 32 + dd) * KTPITCH + i1] =
                    pack2(acc[mi][ni][2] * f1 * ks.x, acc[mi][ni][3] * f1 * ks.y);
            }
        }
    } else {
        const int h = (nbase - 2 * INNER) >> 6;
        const bool evenr = ((lane >> 2) & 1) == 0;
        #pragma unroll
        for (int mi = 0; mi < 2; mi++) {
            const int row0 = rowBase + wm + mi * 16 + r;
            #pragma unroll
            for (int ni = 0; ni < 8; ni++) {
                const float p0 = __shfl_xor_sync(0xFFFFFFFFu, acc[mi][ni][0], 4);
                const float p1 = __shfl_xor_sync(0xFFFFFFFFu, acc[mi][ni][1], 4);
                const float p2 = __shfl_xor_sync(0xFFFFFFFFu, acc[mi][ni][2], 4);
                const float p3 = __shfl_xor_sync(0xFFFFFFFFu, acc[mi][ni][3], 4);
                if (evenr) {
                    const int bb = row0 >> 11;
                    const int i0 = row0 & 2047;
                    const int jj = i0 >> 1;
                    const int d0 = ni * 8 + 2 * c;
                    unsigned* base = g_VtP + (size_t)(bb * HEADS + h) * VROWSP * 64;
                    *(uint2*)&base[(size_t)jj * 64 + d0] =
                        make_uint2(pack2(acc[mi][ni][0], p0), pack2(acc[mi][ni][1], p1));
                    *(uint2*)&base[(size_t)(jj + 4) * 64 + d0] =
                        make_uint2(pack2(acc[mi][ni][2], p2), pack2(acc[mi][ni][3], p3));
                }
            }
        }
    }
}

// ---- output projection ----
__global__ void __launch_bounds__(256, 2) gemm_o_kernel(float* __restrict__ out) {
    GEMM_MAINLOOP(g_aoH, g_WoP, DIM, INNER)
    #pragma unroll
    for (int mi = 0; mi < 2; mi++) {
        const int row = rowBase + wm + mi * 16 + r;
        #pragma unroll
        for (int ni = 0; ni < 8; ni++) {
            const int col = colBase + wn + ni * 8 + 2 * c;
            *(float2*)&out[(size_t)row * DIM + col]       = make_float2(acc[mi][ni][0], acc[mi][ni][1]);
            *(float2*)&out[(size_t)(row + 8) * DIM + col] = make_float2(acc[mi][ni][2], acc[mi][ni][3]);
        }
    }
}

// ---------------- null slot at j=2048 -------------------------------------------
__global__ void null_prep(const float* __restrict__ null_kv,
                          const float* __restrict__ k_scale) {
    const int bh = blockIdx.x;
    const int h = bh & 15;
    const int lane = threadIdx.x;
    const int src0 = (2 * lane) & 31;
    const int src1 = (2 * lane + 1) & 31;
    const float* nk = null_kv + h * DHEAD;
    const float* nv = null_kv + HEADS * DHEAD + h * DHEAD;
    float k0 = nk[lane], k1 = nk[lane + 32];
    float ss = k0 * k0 + k1 * k1;
    #pragma unroll
    for (int o = 16; o > 0; o >>= 1) ss += __shfl_xor_sync(0xFFFFFFFFu, ss, o);
    const float inv = 1.f / fmaxf(sqrtf(ss), L2_EPS);
    const float kk0 = k0 * inv * k_scale[lane];
    const float kk1 = k1 * inv * k_scale[lane + 32];
    {
        float s0a = __shfl_sync(0xFFFFFFFFu, kk0, src0);
        float s0b = __shfl_sync(0xFFFFFFFFu, kk0, src1);
        float s1a = __shfl_sync(0xFFFFFFFFu, kk1, src0);
        float s1b = __shfl_sync(0xFFFFFFFFu, kk1, src1);
        const float a = (lane < 16) ? s0a : s1a;
        const float b = (lane < 16) ? s0b : s1b;
        g_KtP[((size_t)bh * 32 + lane) * KTPITCH + 2048] = pack2(a, b);
    }
    const float v0 = nv[lane], v1 = nv[lane + 32];
    unsigned* base = g_VtP + ((size_t)bh * VROWSP + 1024) * 64;
    base[lane]      = pack2(v0, 0.f);
    base[lane + 32] = pack2(v1, 0.f);
}

// ---------------- flash attention: 3-stage cp.async fills -----------------------
#define ABQ 128
#define ABK 64
#define ANT ((KVLEN + ABK - 1) / ABK)   /* 33 */
#define KTLD 72
#define VLD  72
#define AST_W (32 * KTLD + 32 * VLD)    /* 4608 words per stage */

#define ATT_SMEM (3 * AST_W * 4)        /* 55296 B */

__global__ void __launch_bounds__(256, 2) attn_mma_kernel() {
    extern __shared__ unsigned ash[];
    const unsigned asb = (unsigned)__cvta_generic_to_shared(ash);

    const int tid  = threadIdx.x;
    const int warp = tid >> 5;
    const int lane = tid & 31;
    const int r = lane >> 2;
    const int c = lane & 3;
    const int bh = blockIdx.y;
    const int qt = blockIdx.x;
    const int m0 = warp * 16;

    const unsigned* QgP = g_QP + ((size_t)bh * SEQ + (size_t)qt * ABQ + m0) * 32;
    unsigned qh[4][4];
    #pragma unroll
    for (int s = 0; s < 4; s++) {
        qh[s][0] = QgP[(size_t)r * 32 + s * 8 + c];
        qh[s][1] = QgP[(size_t)(r + 8) * 32 + s * 8 + c];
        qh[s][2] = QgP[(size_t)r * 32 + s * 8 + c + 4];
        qh[s][3] = QgP[(size_t)(r + 8) * 32 + s * 8 + c + 4];
    }

    float oacc[8][4];
    #pragma unroll
    for (int nt = 0; nt < 8; nt++)
        #pragma unroll
        for (int j = 0; j < 4; j++) oacc[nt][j] = 0.f;
    float mrow0 = -1e30f, mrow1 = -1e30f, lrow0 = 0.f, lrow1 = 0.f;

    const unsigned* KtG = g_KtP + ((size_t)bh * 32 + (tid >> 3)) * KTPITCH + (tid & 7) * 8;
    const unsigned* VtG = g_VtP + ((size_t)bh * VROWSP + (tid >> 3)) * 64 + (tid & 7) * 8;
    const unsigned koff = ((tid >> 3) * KTLD + (tid & 7) * 8) * 4;
    const unsigned voff = (32 * KTLD + (tid >> 3) * VLD + (tid & 7) * 8) * 4;

    auto fill_async = [&](int kt) {
        const unsigned st = asb + ((kt % 3) * AST_W) * 4;
        const int kvbase = kt * ABK;
        cp_async16(st + koff,      KtG + kvbase);
        cp_async16(st + koff + 16, KtG + kvbase + 4);
        const unsigned* vp = VtG + (size_t)(kt * 32) * 64;
        cp_async16(st + voff,      vp);
        cp_async16(st + voff + 16, vp + 4);
    };

    fill_async(0);
    cp_commit();
    fill_async(1);
    cp_commit();

    for (int kt = 0; kt < ANT; kt++) {
        const int kvbase = kt * ABK;
        if (kt + 1 < ANT) cp_wait1(); else cp_wait0();
        __syncthreads();
        if (kt + 2 < ANT) { fill_async(kt + 2); cp_commit(); }

        const unsigned* KtH = ash + (kt % 3) * AST_W;
        const unsigned* VH  = KtH + 32 * KTLD;

        float sa[8][4];
        #pragma unroll
        for (int nt = 0; nt < 8; nt++)
            #pragma unroll
            for (int j = 0; j < 4; j++) sa[nt][j] = 0.f;

        #pragma unroll
        for (int s = 0; s < 4; s++) {
            #pragma unroll
            for (int nt = 0; nt < 8; nt++) {
                unsigned bfh[2];
                bfh[0] = KtH[(8 * s + c) * KTLD + nt * 8 + r];
                bfh[1] = KtH[(8 * s + c + 4) * KTLD + nt * 8 + r];
                mma_f16(sa[nt], qh[s], bfh);
            }
        }

        float tmax0 = -1e30f, tmax1 = -1e30f;
        #pragma unroll
        for (int nt = 0; nt < 8; nt++) {
            const int j0 = kvbase + nt * 8 + 2 * c;
            if (j0 >= KVLEN)     { sa[nt][0] = -1e30f; sa[nt][2] = -1e30f; }
            if (j0 + 1 >= KVLEN) { sa[nt][1] = -1e30f; sa[nt][3] = -1e30f; }
            tmax0 = fmaxf(tmax0, fmaxf(sa[nt][0], sa[nt][1]));
            tmax1 = fmaxf(tmax1, fmaxf(sa[nt][2], sa[nt][3]));
        }
        tmax0 = fmaxf(tmax0, __shfl_xor_sync(0xFFFFFFFFu, tmax0, 1));
        tmax0 = fmaxf(tmax0, __shfl_xor_sync(0xFFFFFFFFu, tmax0, 2));
        tmax1 = fmaxf(tmax1, __shfl_xor_sync(0xFFFFFFFFu, tmax1, 1));
        tmax1 = fmaxf(tmax1, __shfl_xor_sync(0xFFFFFFFFu, tmax1, 2));

        const float mnew0 = fmaxf(mrow0, tmax0);
        const float mnew1 = fmaxf(mrow1, tmax1);
        const float cf0 = __expf(mrow0 - mnew0);
        const float cf1 = __expf(mrow1 - mnew1);
        mrow0 = mnew0; mrow1 = mnew1;

        unsigned pfrag[8][2];
        float psum0 = 0.f, psum1 = 0.f;
        #pragma unroll
        for (int nt = 0; nt < 8; nt++) {
            const float p0 = __expf(sa[nt][0] - mnew0);
            const float p1 = __expf(sa[nt][1] - mnew0);
            const float p2 = __expf(sa[nt][2] - mnew1);
            const float p3 = __expf(sa[nt][3] - mnew1);
            psum0 += p0 + p1;
            psum1 += p2 + p3;
            pfrag[nt][0] = pack2(p0, p1);
            pfrag[nt][1] = pack2(p2, p3);
        }
        psum0 += __shfl_xor_sync(0xFFFFFFFFu, psum0, 1);
        psum0 += __shfl_xor_sync(0xFFFFFFFFu, psum0, 2);
        psum1 += __shfl_xor_sync(0xFFFFFFFFu, psum1, 1);
        psum1 += __shfl_xor_sync(0xFFFFFFFFu, psum1, 2);
        lrow0 = lrow0 * cf0 + psum0;
        lrow1 = lrow1 * cf1 + psum1;

        #pragma unroll
        for (int nt = 0; nt < 8; nt++) {
            oacc[nt][0] *= cf0; oacc[nt][1] *= cf0;
            oacc[nt][2] *= cf1; oacc[nt][3] *= cf1;
        }

        #pragma unroll
        for (int s = 0; s < 4; s++) {
            unsigned pa[4];
            pa[0] = pfrag[2 * s][0];
            pa[1] = pfrag[2 * s][1];
            pa[2] = pfrag[2 * s + 1][0];
            pa[3] = pfrag[2 * s + 1][1];
            #pragma unroll
            for (int nt = 0; nt < 8; nt++) {
                unsigned vfh[2];
                vfh[0] = VH[(8 * s + c) * VLD + nt * 8 + r];
                vfh[1] = VH[(8 * s + c + 4) * VLD + nt * 8 + r];
                mma_f16(oacc[nt], pa, vfh);
            }
        }
    }

    const float li0 = 1.f / lrow0;
    const float li1 = 1.f / lrow1;
    const int bb = bh >> 4, h = bh & 15;
    const int row0 = qt * ABQ + m0 + r;
    #pragma unroll
    for (int nt = 0; nt < 8; nt++) {
        const size_t wi0 = (size_t)(bb * SEQ + row0) * (INNER / 2) + h * 32 + nt * 4 + c;
        const size_t wi1 = (size_t)(bb * SEQ + row0 + 8) * (INNER / 2) + h * 32 + nt * 4 + c;
        g_aoH[wi0] = pack2(oacc[nt][0] * li0, oacc[nt][1] * li0);
        g_aoH[wi1] = pack2(oacc[nt][2] * li1, oacc[nt][3] * li1);
    }
}

// ---------------- launch ------------------------------------------------------
extern "C" void kernel_launch(void* const* d_in, const int* in_sizes, int n_in,
                              void* d_out, int out_size) {
    const float* x       = (const float*)d_in[0];
    const float* gamma   = (const float*)d_in[1];
    const float* beta    = (const float*)d_in[2];
    const float* null_kv = (const float*)d_in[3];
    const float* Wq      = (const float*)d_in[4];
    const float* Wkv     = (const float*)d_in[5];
    const float* q_scale = (const float*)d_in[6];
    const float* k_scale = (const float*)d_in[7];
    const float* Wo      = (const float*)d_in[8];
    float* out = (float*)d_out;

    unsigned* wop;
    cudaGetSymbolAddress((void**)&wop, g_WoP);

    cudaFuncSetAttribute(gemm_qkv_kernel, cudaFuncAttributeMaxDynamicSharedMemorySize, GEMM_SMEM);
    cudaFuncSetAttribute(gemm_o_kernel,   cudaFuncAttributeMaxDynamicSharedMemorySize, GEMM_SMEM);
    cudaFuncSetAttribute(attn_mma_kernel, cudaFuncAttributeMaxDynamicSharedMemorySize, ATT_SMEM);

    pack_qkv<<<768, 256>>>(Wq, Wkv);
    pack_w<<<512, 256>>>(Wo, wop, INNER, DIM);
    ln_kernel<<<TOKENS, 256>>>(x, gamma, beta);
    null_prep<<<BATCH * HEADS, 32>>>(null_kv, k_scale);
    gemm_qkv_kernel<<<dim3(NQKV / 128, TOKENS / 128), 256, GEMM_SMEM>>>(q_scale, k_scale);
    attn_mma_kernel<<<dim3(SEQ / ABQ, BATCH * HEADS), 256, ATT_SMEM>>>();
    gemm_o_kernel<<<dim3(DIM / 128, TOKENS / 128), 256, GEMM_SMEM>>>(out);
}